// round 4
// baseline (speedup 1.0000x reference)
#include <cuda_runtime.h>
#include <cuda_bf16.h>
#include <math.h>
#include <stdint.h>

// ---------------- problem constants ----------------
#define Bc   4
#define Lc   2048
#define Dc   1024
#define Hc   4
#define HDc  256
#define NLc  2
#define FFc  4096
#define Mc   (Bc*Lc)     // 8192 tokens
#define D3c  (3*Dc)      // 3072

typedef __nv_bfloat16 bf16;

// ---------------- device scratch (static; no allocations) ----------------
__device__ float g_h  [(size_t)Mc*Dc];            // residual fp32
__device__ float g_sc [(size_t)Bc*Hc*Lc*Lc];      // scores fp32
// split bf16 planes
__device__ __align__(16) bf16 g_xh [(size_t)Mc*D3c],  g_xl [(size_t)Mc*D3c];
__device__ __align__(16) bf16 g_w3h[(size_t)Dc*D3c],  g_w3l[(size_t)Dc*D3c];
__device__ __align__(16) bf16 g_hnh[(size_t)Mc*Dc],   g_hnl[(size_t)Mc*Dc];
__device__ __align__(16) bf16 g_wqh[(size_t)D3c*Dc],  g_wql[(size_t)D3c*Dc];
__device__ __align__(16) bf16 g_wph[(size_t)Dc*Dc],   g_wpl[(size_t)Dc*Dc];
__device__ __align__(16) bf16 g_w1h[(size_t)FFc*Dc],  g_w1l[(size_t)FFc*Dc];
__device__ __align__(16) bf16 g_w2h[(size_t)Dc*FFc],  g_w2l[(size_t)Dc*FFc];
__device__ __align__(16) bf16 g_qvh[(size_t)Mc*D3c],  g_qvl[(size_t)Mc*D3c];
__device__ __align__(16) bf16 g_vth[(size_t)Bc*Hc*HDc*Lc], g_vtl[(size_t)Bc*Hc*HDc*Lc];
__device__ __align__(16) bf16 g_ph [(size_t)Bc*Hc*Lc*Lc],  g_pl [(size_t)Bc*Hc*Lc*Lc];
__device__ __align__(16) bf16 g_oh [(size_t)Mc*Dc],   g_ol [(size_t)Mc*Dc];
__device__ __align__(16) bf16 g_fh [(size_t)Mc*FFc],  g_fl [(size_t)Mc*FFc];

// ---------------- helpers ----------------
__device__ __forceinline__ uint32_t smem_u32(const void* p) {
    uint32_t a;
    asm("{ .reg .u64 t; cvta.to.shared.u64 t, %1; cvt.u32.u64 %0, t; }" : "=r"(a) : "l"(p));
    return a;
}
__device__ __forceinline__ void ldsm4(uint32_t* r, uint32_t addr) {
    asm volatile("ldmatrix.sync.aligned.m8n8.x4.shared.b16 {%0,%1,%2,%3}, [%4];"
        : "=r"(r[0]), "=r"(r[1]), "=r"(r[2]), "=r"(r[3]) : "r"(addr));
}
__device__ __forceinline__ void mma16816(float* d, const uint32_t* a, const uint32_t* b) {
    asm volatile(
        "mma.sync.aligned.m16n8k16.row.col.f32.bf16.bf16.f32 "
        "{%0,%1,%2,%3}, {%4,%5,%6,%7}, {%8,%9}, {%0,%1,%2,%3};"
        : "+f"(d[0]), "+f"(d[1]), "+f"(d[2]), "+f"(d[3])
        : "r"(a[0]), "r"(a[1]), "r"(a[2]), "r"(a[3]), "r"(b[0]), "r"(b[1]));
}
__device__ __forceinline__ void cpa16(uint32_t dst, const void* src) {
    asm volatile("cp.async.cg.shared.global [%0], [%1], 16;" :: "r"(dst), "l"(src));
}
#define CP_COMMIT() asm volatile("cp.async.commit_group;" ::: "memory")
#define CP_WAIT1()  asm volatile("cp.async.wait_group 1;"  ::: "memory")

__device__ __forceinline__ float gelu_exact(float x) {
    return 0.5f * x * (1.0f + erff(x * 0.70710678118654752440f));
}
// split fp32x4 -> hi/lo bf16x4 packed as uint2
__device__ __forceinline__ void split4(float4 v, uint2& Hh, uint2& Ll) {
    bf16 hx = __float2bfloat16_rn(v.x);
    bf16 hy = __float2bfloat16_rn(v.y);
    bf16 hz = __float2bfloat16_rn(v.z);
    bf16 hw = __float2bfloat16_rn(v.w);
    union { __nv_bfloat162 b2[2]; uint2 u; } H, L;
    H.b2[0] = __halves2bfloat162(hx, hy);
    H.b2[1] = __halves2bfloat162(hz, hw);
    L.b2[0] = __halves2bfloat162(__float2bfloat16_rn(v.x - __bfloat162float(hx)),
                                 __float2bfloat16_rn(v.y - __bfloat162float(hy)));
    L.b2[1] = __halves2bfloat162(__float2bfloat16_rn(v.z - __bfloat162float(hz)),
                                 __float2bfloat16_rn(v.w - __bfloat162float(hw)));
    Hh = H.u; Ll = L.u;
}

// ---------------- pipelined bf16 split GEMM ----------------
// C[M,N] = act(scale * (Ah+Al)(Bh+Bl)^T + bias + resid), 3-term MMA.
// A planes [M,K] lda, B planes [N,K] ldb (K-major). Tile 128x128, KC=32, 3 stages.
#define KC     32
#define SKB    40                 // smem row stride in bf16 elems (80B, conflict-free)
#define TILE_B (128*SKB*2)        // 10240 B
#define STAGE_B (4*TILE_B)        // 40960 B
#define SMEM_DYN (3*STAGE_B)      // 122880 B

__device__ __forceinline__ void stage_load(uint32_t sdst,
    const bf16* Ah, const bf16* Al, int lda,
    const bf16* Bh, const bf16* Bl, int ldb, int tid)
{
    #pragma unroll
    for (int j = 0; j < 2; j++) {
        int idx = tid * 2 + j;
        int r = idx >> 2, c = idx & 3;
        uint32_t doff = (uint32_t)(r * SKB + c * 8) * 2;
        size_t ao = (size_t)r * lda + c * 8;
        size_t bo = (size_t)r * ldb + c * 8;
        cpa16(sdst + 0*TILE_B + doff, Ah + ao);
        cpa16(sdst + 1*TILE_B + doff, Al + ao);
        cpa16(sdst + 2*TILE_B + doff, Bh + bo);
        cpa16(sdst + 3*TILE_B + doff, Bl + bo);
    }
}

template<bool HB, bool HR, int ACT, int OUT>   // OUT: 0 = fp32 C, 1 = split (Ch,Cl)
__global__ __launch_bounds__(256, 1) void tc_gemm(
    const bf16* __restrict__ Ah, const bf16* __restrict__ Al, int lda,
    const bf16* __restrict__ Bh, const bf16* __restrict__ Bl, int ldb,
    const float* __restrict__ bias,
    const float* __restrict__ resid,
    float* __restrict__ C, bf16* __restrict__ Ch, bf16* __restrict__ Cl, int ldc,
    int K, float scale,
    long aso, long asi, long bso, long bsi, long cso, long csi, int zinner)
{
    const int z  = blockIdx.z;
    const int zo = z / zinner;
    const int zi = z - zo * zinner;
    const size_t aofs = (size_t)zo * aso + (size_t)zi * asi;
    const size_t bofs = (size_t)zo * bso + (size_t)zi * bsi;
    const size_t cofs = (size_t)zo * cso + (size_t)zi * csi;
    Ah += aofs; Al += aofs;
    Bh += bofs; Bl += bofs;
    if (OUT == 0) C += cofs; else { Ch += cofs; Cl += cofs; }

    extern __shared__ char dsm[];
    const uint32_t sb32 = smem_u32(dsm);

    const int tid  = threadIdx.x;
    const int wid  = tid >> 5;
    const int lane = tid & 31;
    const int wr   = wid & 3;
    const int wc   = wid >> 2;
    const int row0 = blockIdx.y * 128;
    const int col0 = blockIdx.x * 128;

    const bf16* A0h = Ah + (size_t)row0 * lda;
    const bf16* A0l = Al + (size_t)row0 * lda;
    const bf16* B0h = Bh + (size_t)col0 * ldb;
    const bf16* B0l = Bl + (size_t)col0 * ldb;

    float acc[2][8][4];
    #pragma unroll
    for (int mt = 0; mt < 2; mt++)
        #pragma unroll
        for (int nt = 0; nt < 8; nt++)
            #pragma unroll
            for (int j = 0; j < 4; j++) acc[mt][nt][j] = 0.0f;

    const int nc = K / KC;

    // prologue: stages 0 and 1
    stage_load(sb32,           A0h,      A0l,      lda, B0h,      B0l,      ldb, tid);
    CP_COMMIT();
    stage_load(sb32 + STAGE_B, A0h + KC, A0l + KC, lda, B0h + KC, B0l + KC, ldb, tid);
    CP_COMMIT();

    const int ro = lane & 15;
    const int co = (lane >> 4) << 3;

    for (int c = 0; c < nc; c++) {
        CP_WAIT1();
        __syncthreads();

        if (c + 2 < nc) {
            int s2 = (c + 2) % 3;
            int k2 = (c + 2) * KC;
            stage_load(sb32 + s2 * STAGE_B, A0h + k2, A0l + k2, lda,
                       B0h + k2, B0l + k2, ldb, tid);
        }
        CP_COMMIT();

        const uint32_t sOff = sb32 + (uint32_t)(c % 3) * STAGE_B;
        #pragma unroll
        for (int ks = 0; ks < 2; ks++) {
            const int k0 = ks * 16;
            uint32_t ah[2][4], al[2][4];
            #pragma unroll
            for (int mt = 0; mt < 2; mt++) {
                uint32_t off = (uint32_t)((32*wr + 16*mt + ro) * SKB + k0 + co) * 2;
                ldsm4(ah[mt], sOff + 0*TILE_B + off);
                ldsm4(al[mt], sOff + 1*TILE_B + off);
            }
            uint32_t bh[8][2], bl[8][2];
            #pragma unroll
            for (int p = 0; p < 4; p++) {
                uint32_t off = (uint32_t)((64*wc + 16*p + ro) * SKB + k0 + co) * 2;
                uint32_t r[4];
                ldsm4(r, sOff + 2*TILE_B + off);
                bh[2*p][0] = r[0];   bh[2*p][1] = r[2];
                bh[2*p+1][0] = r[1]; bh[2*p+1][1] = r[3];
                ldsm4(r, sOff + 3*TILE_B + off);
                bl[2*p][0] = r[0];   bl[2*p][1] = r[2];
                bl[2*p+1][0] = r[1]; bl[2*p+1][1] = r[3];
            }
            #pragma unroll
            for (int mt = 0; mt < 2; mt++)
                #pragma unroll
                for (int nt = 0; nt < 8; nt++) {
                    mma16816(acc[mt][nt], ah[mt], bh[nt]);
                    mma16816(acc[mt][nt], al[mt], bh[nt]);
                    mma16816(acc[mt][nt], ah[mt], bl[nt]);
                }
        }
    }

    // ---- epilogue ----
    #pragma unroll
    for (int mt = 0; mt < 2; mt++) {
        #pragma unroll
        for (int nt = 0; nt < 8; nt++) {
            const int r0 = row0 + 32*wr + 16*mt + (lane >> 2);
            const int cc = col0 + 64*wc + 8*nt + 2*(lane & 3);
            float2 bv = make_float2(0.f, 0.f);
            if (HB) bv = *(const float2*)&bias[cc];
            #pragma unroll
            for (int hh = 0; hh < 2; hh++) {
                const int r = r0 + hh * 8;
                float v0 = acc[mt][nt][2*hh]     * scale;
                float v1 = acc[mt][nt][2*hh + 1] * scale;
                if (HB) { v0 += bv.x; v1 += bv.y; }
                if (HR) {
                    float2 rv = *(const float2*)&resid[(size_t)r * ldc + cc];
                    v0 += rv.x; v1 += rv.y;
                }
                if (ACT == 1) { v0 = gelu_exact(v0); v1 = gelu_exact(v1); }
                if (OUT == 0) {
                    *(float2*)&C[(size_t)r * ldc + cc] = make_float2(v0, v1);
                } else {
                    bf16 h0 = __float2bfloat16_rn(v0);
                    bf16 h1 = __float2bfloat16_rn(v1);
                    *(__nv_bfloat162*)&Ch[(size_t)r * ldc + cc] = __halves2bfloat162(h0, h1);
                    *(__nv_bfloat162*)&Cl[(size_t)r * ldc + cc] =
                        __halves2bfloat162(__float2bfloat16_rn(v0 - __bfloat162float(h0)),
                                           __float2bfloat16_rn(v1 - __bfloat162float(h1)));
                }
            }
        }
    }
}

// ---------------- split: fp32 -> (hi, lo) bf16 planes ----------------
__global__ __launch_bounds__(256) void split_kernel(const float4* __restrict__ src,
                                                    uint2* __restrict__ h,
                                                    uint2* __restrict__ l, int n4)
{
    int i = blockIdx.x * 256 + threadIdx.x;
    if (i < n4) {
        uint2 H, L;
        split4(src[i], H, L);
        h[i] = H; l[i] = L;
    }
}

// ---------------- V transpose on split planes ----------------
__global__ __launch_bounds__(256) void transpose_v(const bf16* __restrict__ qh,
                                                   const bf16* __restrict__ ql,
                                                   bf16* __restrict__ vth,
                                                   bf16* __restrict__ vtl)
{
    __shared__ bf16 th[32][34], tl[32][34];
    const int bh = blockIdx.z, b = bh / Hc, h = bh % Hc;
    const int q0 = blockIdx.x * 32, d0 = blockIdx.y * 32;
    const int tx = threadIdx.x & 31, ty = threadIdx.x >> 5;
    const size_t so = (size_t)b * Lc * D3c + 2 * Dc + h * HDc;
    #pragma unroll
    for (int i = ty; i < 32; i += 8) {
        th[i][tx] = qh[so + (size_t)(q0 + i) * D3c + d0 + tx];
        tl[i][tx] = ql[so + (size_t)(q0 + i) * D3c + d0 + tx];
    }
    __syncthreads();
    const size_t dofs = (size_t)bh * HDc * Lc;
    #pragma unroll
    for (int i = ty; i < 32; i += 8) {
        vth[dofs + (size_t)(d0 + i) * Lc + q0 + tx] = th[tx][i];
        vtl[dofs + (size_t)(d0 + i) * Lc + q0 + tx] = tl[tx][i];
    }
}

// ---------------- layernorm (fp32 in, split bf16 out) ----------------
template<bool SPLIT>
__global__ __launch_bounds__(256)
void layernorm_kernel(const float* __restrict__ x, const float* __restrict__ g,
                      const float* __restrict__ b,
                      float* __restrict__ outF, bf16* __restrict__ outH, bf16* __restrict__ outL)
{
    const int row = blockIdx.x;
    const int t   = threadIdx.x;
    const float4 v = ((const float4*)(x + (size_t)row * Dc))[t];

    float s1 = v.x + v.y + v.z + v.w;
    float s2 = v.x*v.x + v.y*v.y + v.z*v.z + v.w*v.w;

    __shared__ float sh1[8], sh2[8];
    #pragma unroll
    for (int o = 16; o > 0; o >>= 1) {
        s1 += __shfl_down_sync(0xffffffffu, s1, o);
        s2 += __shfl_down_sync(0xffffffffu, s2, o);
    }
    if ((t & 31) == 0) { sh1[t >> 5] = s1; sh2[t >> 5] = s2; }
    __syncthreads();
    if (t < 8) {
        s1 = sh1[t]; s2 = sh2[t];
        #pragma unroll
        for (int o = 4; o > 0; o >>= 1) {
            s1 += __shfl_down_sync(0xffu, s1, o);
            s2 += __shfl_down_sync(0xffu, s2, o);
        }
        if (t == 0) { sh1[0] = s1; sh2[0] = s2; }
    }
    __syncthreads();

    const float mean = sh1[0] * (1.0f / Dc);
    const float var  = sh2[0] * (1.0f / Dc) - mean * mean;
    const float rstd = rsqrtf(var + 1e-5f);

    const float4 gv = ((const float4*)g)[t];
    const float4 bv = ((const float4*)b)[t];
    float4 r;
    r.x = (v.x - mean) * rstd * gv.x + bv.x;
    r.y = (v.y - mean) * rstd * gv.y + bv.y;
    r.z = (v.z - mean) * rstd * gv.z + bv.z;
    r.w = (v.w - mean) * rstd * gv.w + bv.w;
    if (SPLIT) {
        uint2 H, L;
        split4(r, H, L);
        ((uint2*)(outH + (size_t)row * Dc))[t] = H;
        ((uint2*)(outL + (size_t)row * Dc))[t] = L;
    } else {
        ((float4*)(outF + (size_t)row * Dc))[t] = r;
    }
}

// ---------------- softmax (fp32 in, split bf16 out) ----------------
__global__ __launch_bounds__(256)
void softmax_kernel(const float* __restrict__ s, bf16* __restrict__ ph, bf16* __restrict__ pl)
{
    const size_t row = blockIdx.x;
    const float4* p = (const float4*)(s + row * (size_t)Lc);
    const int t = threadIdx.x;

    float4 a = p[t];
    float4 c = p[t + 256];

    float mx = fmaxf(fmaxf(fmaxf(a.x, a.y), fmaxf(a.z, a.w)),
                     fmaxf(fmaxf(c.x, c.y), fmaxf(c.z, c.w)));

    __shared__ float sh[8];
    #pragma unroll
    for (int o = 16; o > 0; o >>= 1) mx = fmaxf(mx, __shfl_down_sync(0xffffffffu, mx, o));
    if ((t & 31) == 0) sh[t >> 5] = mx;
    __syncthreads();
    if (t < 8) {
        mx = sh[t];
        #pragma unroll
        for (int o = 4; o > 0; o >>= 1) mx = fmaxf(mx, __shfl_down_sync(0xffu, mx, o));
        if (t == 0) sh[0] = mx;
    }
    __syncthreads();
    mx = sh[0];
    __syncthreads();

    a.x = expf(a.x - mx); a.y = expf(a.y - mx); a.z = expf(a.z - mx); a.w = expf(a.w - mx);
    c.x = expf(c.x - mx); c.y = expf(c.y - mx); c.z = expf(c.z - mx); c.w = expf(c.w - mx);

    float sm = a.x + a.y + a.z + a.w + c.x + c.y + c.z + c.w;
    #pragma unroll
    for (int o = 16; o > 0; o >>= 1) sm += __shfl_down_sync(0xffffffffu, sm, o);
    if ((t & 31) == 0) sh[t >> 5] = sm;
    __syncthreads();
    if (t < 8) {
        sm = sh[t];
        #pragma unroll
        for (int o = 4; o > 0; o >>= 1) sm += __shfl_down_sync(0xffu, sm, o);
        if (t == 0) sh[0] = sm;
    }
    __syncthreads();
    const float inv = 1.0f / sh[0];

    a.x *= inv; a.y *= inv; a.z *= inv; a.w *= inv;
    c.x *= inv; c.y *= inv; c.z *= inv; c.w *= inv;

    uint2 H, L;
    split4(a, H, L);
    ((uint2*)(ph + row * (size_t)Lc))[t] = H;
    ((uint2*)(pl + row * (size_t)Lc))[t] = L;
    split4(c, H, L);
    ((uint2*)(ph + row * (size_t)Lc))[t + 256] = H;
    ((uint2*)(pl + row * (size_t)Lc))[t + 256] = L;
}

// ---------------- host side ----------------
static void do_split(const float* src, bf16* h, bf16* l, size_t n) {
    int n4 = (int)(n / 4);
    split_kernel<<<(n4 + 255) / 256, 256>>>((const float4*)src, (uint2*)h, (uint2*)l, n4);
}

extern "C" void kernel_launch(void* const* d_in, const int* in_sizes, int n_in,
                              void* d_out, int out_size)
{
    const float* x    = (const float*)d_in[0];
    const float* w3d  = (const float*)d_in[1];
    const float* b3d  = (const float*)d_in[2];
    const float* ln1g = (const float*)d_in[3];
    const float* ln1b = (const float*)d_in[4];
    const float* wqkv = (const float*)d_in[5];
    const float* bqkv = (const float*)d_in[6];
    const float* wprj = (const float*)d_in[7];
    const float* bprj = (const float*)d_in[8];
    const float* ln2g = (const float*)d_in[9];
    const float* ln2b = (const float*)d_in[10];
    const float* w1   = (const float*)d_in[11];
    const float* b1   = (const float*)d_in[12];
    const float* w2   = (const float*)d_in[13];
    const float* b2   = (const float*)d_in[14];
    const float* lnfg = (const float*)d_in[15];
    const float* lnfb = (const float*)d_in[16];
    float* out = (float*)d_out;

    float *h, *sc;
    bf16 *xh,*xl,*w3h,*w3l,*hnh,*hnl,*wqh,*wql,*wph,*wpl,*w1h,*w1l,*w2h,*w2l;
    bf16 *qvh,*qvl,*vth,*vtl,*ph,*pl,*oh,*ol,*fh,*fl;
    cudaGetSymbolAddress((void**)&h,   g_h);
    cudaGetSymbolAddress((void**)&sc,  g_sc);
    cudaGetSymbolAddress((void**)&xh,  g_xh);  cudaGetSymbolAddress((void**)&xl,  g_xl);
    cudaGetSymbolAddress((void**)&w3h, g_w3h); cudaGetSymbolAddress((void**)&w3l, g_w3l);
    cudaGetSymbolAddress((void**)&hnh, g_hnh); cudaGetSymbolAddress((void**)&hnl, g_hnl);
    cudaGetSymbolAddress((void**)&wqh, g_wqh); cudaGetSymbolAddress((void**)&wql, g_wql);
    cudaGetSymbolAddress((void**)&wph, g_wph); cudaGetSymbolAddress((void**)&wpl, g_wpl);
    cudaGetSymbolAddress((void**)&w1h, g_w1h); cudaGetSymbolAddress((void**)&w1l, g_w1l);
    cudaGetSymbolAddress((void**)&w2h, g_w2h); cudaGetSymbolAddress((void**)&w2l, g_w2l);
    cudaGetSymbolAddress((void**)&qvh, g_qvh); cudaGetSymbolAddress((void**)&qvl, g_qvl);
    cudaGetSymbolAddress((void**)&vth, g_vth); cudaGetSymbolAddress((void**)&vtl, g_vtl);
    cudaGetSymbolAddress((void**)&ph,  g_ph);  cudaGetSymbolAddress((void**)&pl,  g_pl);
    cudaGetSymbolAddress((void**)&oh,  g_oh);  cudaGetSymbolAddress((void**)&ol,  g_ol);
    cudaGetSymbolAddress((void**)&fh,  g_fh);  cudaGetSymbolAddress((void**)&fl,  g_fl);

    cudaFuncSetAttribute(tc_gemm<true,false,0,0>,  cudaFuncAttributeMaxDynamicSharedMemorySize, SMEM_DYN);
    cudaFuncSetAttribute(tc_gemm<true,false,0,1>,  cudaFuncAttributeMaxDynamicSharedMemorySize, SMEM_DYN);
    cudaFuncSetAttribute(tc_gemm<false,false,0,0>, cudaFuncAttributeMaxDynamicSharedMemorySize, SMEM_DYN);
    cudaFuncSetAttribute(tc_gemm<false,false,0,1>, cudaFuncAttributeMaxDynamicSharedMemorySize, SMEM_DYN);
    cudaFuncSetAttribute(tc_gemm<true,true,0,0>,   cudaFuncAttributeMaxDynamicSharedMemorySize, SMEM_DYN);
    cudaFuncSetAttribute(tc_gemm<true,false,1,1>,  cudaFuncAttributeMaxDynamicSharedMemorySize, SMEM_DYN);

    const dim3 blk(256);

    // one-time splits
    do_split(x,   xh,  xl,  (size_t)Mc * D3c);
    do_split(w3d, w3h, w3l, (size_t)Dc * D3c);

    // ---- embed: h = x @ w3d^T + b3d ----
    tc_gemm<true,false,0,0><<<dim3(Dc/128, Mc/128, 1), blk, SMEM_DYN>>>(
        xh, xl, D3c, w3h, w3l, D3c, b3d, nullptr,
        h, nullptr, nullptr, Dc, D3c, 1.0f, 0,0,0,0,0,0, 1);

    for (int i = 0; i < NLc; i++) {
        do_split(wqkv + (size_t)i*D3c*Dc, wqh, wql, (size_t)D3c*Dc);
        do_split(wprj + (size_t)i*Dc*Dc,  wph, wpl, (size_t)Dc*Dc);
        do_split(w1   + (size_t)i*FFc*Dc, w1h, w1l, (size_t)FFc*Dc);
        do_split(w2   + (size_t)i*Dc*FFc, w2h, w2l, (size_t)Dc*FFc);

        layernorm_kernel<true><<<Mc, blk>>>(h, ln1g + (size_t)i*Dc, ln1b + (size_t)i*Dc,
                                            nullptr, hnh, hnl);

        // qkv = hn @ wqkv^T + bqkv  -> split planes
        tc_gemm<true,false,0,1><<<dim3(D3c/128, Mc/128, 1), blk, SMEM_DYN>>>(
            hnh, hnl, Dc, wqh, wql, Dc, bqkv + (size_t)i*D3c, nullptr,
            nullptr, qvh, qvl, D3c, Dc, 1.0f, 0,0,0,0,0,0, 1);

        transpose_v<<<dim3(Lc/32, HDc/32, Bc*Hc), blk>>>(qvh, qvl, vth, vtl);

        // scores = scale * Q @ K^T  (batched over b,h) -> fp32
        tc_gemm<false,false,0,0><<<dim3(Lc/128, Lc/128, Bc*Hc), blk, SMEM_DYN>>>(
            qvh, qvl, D3c,
            qvh + Dc, qvl + Dc, D3c,
            nullptr, nullptr,
            sc, nullptr, nullptr, Lc, HDc, 0.0625f,
            (long)Lc*D3c, (long)HDc,
            (long)Lc*D3c, (long)HDc,
            (long)Hc*Lc*Lc, (long)Lc*Lc,
            Hc);

        softmax_kernel<<<Bc*Hc*Lc, blk>>>(sc, ph, pl);

        // o = P @ Vt^T (batched) -> split planes
        tc_gemm<false,false,0,1><<<dim3(HDc/128, Lc/128, Bc*Hc), blk, SMEM_DYN>>>(
            ph, pl, Lc,
            vth, vtl, Lc,
            nullptr, nullptr,
            nullptr, oh, ol, Dc, Lc, 1.0f,
            (long)Hc*Lc*Lc, (long)Lc*Lc,
            (long)Hc*HDc*Lc, (long)HDc*Lc,
            (long)Lc*Dc, (long)HDc,
            Hc);

        // h = h + o @ wproj^T + bproj
        tc_gemm<true,true,0,0><<<dim3(Dc/128, Mc/128, 1), blk, SMEM_DYN>>>(
            oh, ol, Dc, wph, wpl, Dc, bprj + (size_t)i*Dc, h,
            h, nullptr, nullptr, Dc, Dc, 1.0f, 0,0,0,0,0,0, 1);

        layernorm_kernel<true><<<Mc, blk>>>(h, ln2g + (size_t)i*Dc, ln2b + (size_t)i*Dc,
                                            nullptr, hnh, hnl);

        // f = gelu(hn @ w1^T + b1) -> split planes
        tc_gemm<true,false,1,1><<<dim3(FFc/128, Mc/128, 1), blk, SMEM_DYN>>>(
            hnh, hnl, Dc, w1h, w1l, Dc, b1 + (size_t)i*FFc, nullptr,
            nullptr, fh, fl, FFc, Dc, 1.0f, 0,0,0,0,0,0, 1);

        // h = h + f @ w2^T + b2
        tc_gemm<true,true,0,0><<<dim3(Dc/128, Mc/128, 1), blk, SMEM_DYN>>>(
            fh, fl, FFc, w2h, w2l, FFc, b2 + (size_t)i*Dc, h,
            h, nullptr, nullptr, Dc, FFc, 1.0f, 0,0,0,0,0,0, 1);
    }

    layernorm_kernel<false><<<Mc, blk>>>(h, lnfg, lnfb, out, nullptr, nullptr);
}

// round 5
// speedup vs baseline: 1.1378x; 1.1378x over previous
#include <cuda_runtime.h>
#include <cuda_bf16.h>
#include <math.h>
#include <stdint.h>

// ---------------- problem constants ----------------
#define Bc   4
#define Lc   2048
#define Dc   1024
#define Hc   4
#define HDc  256
#define NLc  2
#define FFc  4096
#define Mc   (Bc*Lc)     // 8192 tokens
#define D3c  (3*Dc)      // 3072

typedef __nv_bfloat16 bf16;

// ---------------- device scratch (static; no allocations) ----------------
__device__ float g_h  [(size_t)Mc*Dc];            // residual fp32
__device__ float g_sc [(size_t)Bc*Hc*Lc*Lc];      // scores fp32
// split bf16 planes
__device__ __align__(16) bf16 g_xh [(size_t)Mc*D3c],  g_xl [(size_t)Mc*D3c];
__device__ __align__(16) bf16 g_w3h[(size_t)Dc*D3c],  g_w3l[(size_t)Dc*D3c];
__device__ __align__(16) bf16 g_hnh[(size_t)Mc*Dc],   g_hnl[(size_t)Mc*Dc];
__device__ __align__(16) bf16 g_wqh[(size_t)D3c*Dc],  g_wql[(size_t)D3c*Dc];
__device__ __align__(16) bf16 g_wph[(size_t)Dc*Dc],   g_wpl[(size_t)Dc*Dc];
__device__ __align__(16) bf16 g_w1h[(size_t)FFc*Dc],  g_w1l[(size_t)FFc*Dc];
__device__ __align__(16) bf16 g_w2h[(size_t)Dc*FFc],  g_w2l[(size_t)Dc*FFc];
__device__ __align__(16) bf16 g_qvh[(size_t)Mc*D3c],  g_qvl[(size_t)Mc*D3c];
__device__ __align__(16) bf16 g_vth[(size_t)Bc*Hc*HDc*Lc], g_vtl[(size_t)Bc*Hc*HDc*Lc];
__device__ __align__(16) bf16 g_ph [(size_t)Bc*Hc*Lc*Lc],  g_pl [(size_t)Bc*Hc*Lc*Lc];
__device__ __align__(16) bf16 g_oh [(size_t)Mc*Dc],   g_ol [(size_t)Mc*Dc];
__device__ __align__(16) bf16 g_fh [(size_t)Mc*FFc],  g_fl [(size_t)Mc*FFc];

// ---------------- helpers ----------------
__device__ __forceinline__ uint32_t smem_u32(const void* p) {
    uint32_t a;
    asm("{ .reg .u64 t; cvta.to.shared.u64 t, %1; cvt.u32.u64 %0, t; }" : "=r"(a) : "l"(p));
    return a;
}
__device__ __forceinline__ void ldsm4(uint32_t* r, uint32_t addr) {
    asm volatile("ldmatrix.sync.aligned.m8n8.x4.shared.b16 {%0,%1,%2,%3}, [%4];"
        : "=r"(r[0]), "=r"(r[1]), "=r"(r[2]), "=r"(r[3]) : "r"(addr));
}
__device__ __forceinline__ void mma16816(float* d, const uint32_t* a, const uint32_t* b) {
    asm volatile(
        "mma.sync.aligned.m16n8k16.row.col.f32.bf16.bf16.f32 "
        "{%0,%1,%2,%3}, {%4,%5,%6,%7}, {%8,%9}, {%0,%1,%2,%3};"
        : "+f"(d[0]), "+f"(d[1]), "+f"(d[2]), "+f"(d[3])
        : "r"(a[0]), "r"(a[1]), "r"(a[2]), "r"(a[3]), "r"(b[0]), "r"(b[1]));
}
__device__ __forceinline__ float gelu_exact(float x) {
    return 0.5f * x * (1.0f + erff(x * 0.70710678118654752440f));
}
// split fp32x4 -> hi/lo bf16x4 packed as uint2
__device__ __forceinline__ void split4(float4 v, uint2& Hh, uint2& Ll) {
    bf16 hx = __float2bfloat16_rn(v.x);
    bf16 hy = __float2bfloat16_rn(v.y);
    bf16 hz = __float2bfloat16_rn(v.z);
    bf16 hw = __float2bfloat16_rn(v.w);
    union { __nv_bfloat162 b2[2]; uint2 u; } H, L;
    H.b2[0] = __halves2bfloat162(hx, hy);
    H.b2[1] = __halves2bfloat162(hz, hw);
    L.b2[0] = __halves2bfloat162(__float2bfloat16_rn(v.x - __bfloat162float(hx)),
                                 __float2bfloat16_rn(v.y - __bfloat162float(hy)));
    L.b2[1] = __halves2bfloat162(__float2bfloat16_rn(v.z - __bfloat162float(hz)),
                                 __float2bfloat16_rn(v.w - __bfloat162float(hw)));
    Hh = H.u; Ll = L.u;
}

// ---------------- bf16 split GEMM (R3 mainloop + pre-split planes) ----------------
// C[M,N] = act(scale * (Ah+Al)(Bh+Bl)^T + bias + resid), 3-term MMA.
// Planes [*,K] K-major. Tile 128x128, KC=64, double-buffered smem, reg prefetch.
#define KC     64
#define SKB    72                   // smem row stride in bf16 elems (144B, conflict-free)
#define TILE_B (128*SKB*2)          // 18432 B per 128x64 plane tile
#define STAGE_B (4*TILE_B)          // 73728 B
#define SMEM_DYN (2*STAGE_B)        // 147456 B

template<bool HB, bool HR, int ACT, int OUT>   // OUT: 0 = fp32 C, 1 = split (Ch,Cl)
__global__ __launch_bounds__(256, 1) void tc_gemm(
    const bf16* __restrict__ Ah, const bf16* __restrict__ Al, int lda,
    const bf16* __restrict__ Bh, const bf16* __restrict__ Bl, int ldb,
    const float* __restrict__ bias,
    const float* __restrict__ resid,
    float* __restrict__ C, bf16* __restrict__ Ch, bf16* __restrict__ Cl, int ldc,
    int K, float scale,
    long aso, long asi, long bso, long bsi, long cso, long csi, int zinner)
{
    const int z  = blockIdx.z;
    const int zo = z / zinner;
    const int zi = z - zo * zinner;
    const size_t aofs = (size_t)zo * aso + (size_t)zi * asi;
    const size_t bofs = (size_t)zo * bso + (size_t)zi * bsi;
    const size_t cofs = (size_t)zo * cso + (size_t)zi * csi;
    Ah += aofs; Al += aofs;
    Bh += bofs; Bl += bofs;
    if (OUT == 0) C += cofs; else { Ch += cofs; Cl += cofs; }

    extern __shared__ char dsm[];
    const uint32_t sb32 = smem_u32(dsm);

    const int tid  = threadIdx.x;
    const int wid  = tid >> 5;
    const int lane = tid & 31;
    const int wr   = wid & 3;
    const int wc   = wid >> 2;
    const int row0 = blockIdx.y * 128;
    const int col0 = blockIdx.x * 128;

    // loader indexing: 1024 slots of 16B (8 bf16) per plane tile; 4 per thread
    const int lr0 = tid >> 3;          // base row (stride 32 over 4 iters)
    const int lc8 = (tid & 7) << 3;    // col in bf16 elems (0..56)

    const bf16* A0h = Ah + (size_t)row0 * lda;
    const bf16* A0l = Al + (size_t)row0 * lda;
    const bf16* B0h = Bh + (size_t)col0 * ldb;
    const bf16* B0l = Bl + (size_t)col0 * ldb;

    float acc[2][8][4];
    #pragma unroll
    for (int mt = 0; mt < 2; mt++)
        #pragma unroll
        for (int nt = 0; nt < 8; nt++)
            #pragma unroll
            for (int j = 0; j < 4; j++) acc[mt][nt][j] = 0.0f;

    const int nc = K / KC;

    // ---- prologue: fill stage 0 directly ----
    #pragma unroll
    for (int it = 0; it < 4; it++) {
        int r = lr0 + it * 32;
        uint32_t doff = (uint32_t)(r * SKB + lc8) * 2;
        *(uint4*)(dsm + 0*TILE_B + doff) = *(const uint4*)(A0h + (size_t)r * lda + lc8);
        *(uint4*)(dsm + 1*TILE_B + doff) = *(const uint4*)(A0l + (size_t)r * lda + lc8);
        *(uint4*)(dsm + 2*TILE_B + doff) = *(const uint4*)(B0h + (size_t)r * ldb + lc8);
        *(uint4*)(dsm + 3*TILE_B + doff) = *(const uint4*)(B0l + (size_t)r * ldb + lc8);
    }
    __syncthreads();

    const int ro = lane & 15;
    const int co = (lane >> 4) << 3;

    for (int c = 0; c < nc; c++) {
        const int s = c & 1;
        const uint32_t sOff = sb32 + (uint32_t)s * STAGE_B;
        char* dst = dsm + (size_t)(s ^ 1) * STAGE_B;
        const bool pf = (c + 1 < nc);
        const int kn = (c + 1) * KC;

        uint4 ra[8];
        if (pf) {
            #pragma unroll
            for (int it = 0; it < 4; it++) {
                int r = lr0 + it * 32;
                ra[it]     = *(const uint4*)(A0h + (size_t)r * lda + kn + lc8);
                ra[it + 4] = *(const uint4*)(A0l + (size_t)r * lda + kn + lc8);
            }
        }

        // ---- ksteps 0..1 ----
        #pragma unroll
        for (int ks = 0; ks < 2; ks++) {
            const int k0 = ks * 16;
            uint32_t ah[2][4], al[2][4];
            #pragma unroll
            for (int mt = 0; mt < 2; mt++) {
                uint32_t off = (uint32_t)((32*wr + 16*mt + ro) * SKB + k0 + co) * 2;
                ldsm4(ah[mt], sOff + 0*TILE_B + off);
                ldsm4(al[mt], sOff + 1*TILE_B + off);
            }
            uint32_t bh[8][2], bl[8][2];
            #pragma unroll
            for (int p = 0; p < 4; p++) {
                uint32_t off = (uint32_t)((64*wc + 16*p + ro) * SKB + k0 + co) * 2;
                uint32_t r[4];
                ldsm4(r, sOff + 2*TILE_B + off);
                bh[2*p][0] = r[0];   bh[2*p][1] = r[2];
                bh[2*p+1][0] = r[1]; bh[2*p+1][1] = r[3];
                ldsm4(r, sOff + 3*TILE_B + off);
                bl[2*p][0] = r[0];   bl[2*p][1] = r[2];
                bl[2*p+1][0] = r[1]; bl[2*p+1][1] = r[3];
            }
            #pragma unroll
            for (int mt = 0; mt < 2; mt++)
                #pragma unroll
                for (int nt = 0; nt < 8; nt++) {
                    mma16816(acc[mt][nt], ah[mt], bh[nt]);
                    mma16816(acc[mt][nt], al[mt], bh[nt]);
                    mma16816(acc[mt][nt], ah[mt], bl[nt]);
                }
        }

        if (pf) {
            #pragma unroll
            for (int it = 0; it < 4; it++) {
                int r = lr0 + it * 32;
                uint32_t doff = (uint32_t)(r * SKB + lc8) * 2;
                *(uint4*)(dst + 0*TILE_B + doff) = ra[it];
                *(uint4*)(dst + 1*TILE_B + doff) = ra[it + 4];
            }
            #pragma unroll
            for (int it = 0; it < 4; it++) {
                int r = lr0 + it * 32;
                ra[it]     = *(const uint4*)(B0h + (size_t)r * ldb + kn + lc8);
                ra[it + 4] = *(const uint4*)(B0l + (size_t)r * ldb + kn + lc8);
            }
        }

        // ---- ksteps 2..3 ----
        #pragma unroll
        for (int ks = 2; ks < 4; ks++) {
            const int k0 = ks * 16;
            uint32_t ah[2][4], al[2][4];
            #pragma unroll
            for (int mt = 0; mt < 2; mt++) {
                uint32_t off = (uint32_t)((32*wr + 16*mt + ro) * SKB + k0 + co) * 2;
                ldsm4(ah[mt], sOff + 0*TILE_B + off);
                ldsm4(al[mt], sOff + 1*TILE_B + off);
            }
            uint32_t bh[8][2], bl[8][2];
            #pragma unroll
            for (int p = 0; p < 4; p++) {
                uint32_t off = (uint32_t)((64*wc + 16*p + ro) * SKB + k0 + co) * 2;
                uint32_t r[4];
                ldsm4(r, sOff + 2*TILE_B + off);
                bh[2*p][0] = r[0];   bh[2*p][1] = r[2];
                bh[2*p+1][0] = r[1]; bh[2*p+1][1] = r[3];
                ldsm4(r, sOff + 3*TILE_B + off);
                bl[2*p][0] = r[0];   bl[2*p][1] = r[2];
                bl[2*p+1][0] = r[1]; bl[2*p+1][1] = r[3];
            }
            #pragma unroll
            for (int mt = 0; mt < 2; mt++)
                #pragma unroll
                for (int nt = 0; nt < 8; nt++) {
                    mma16816(acc[mt][nt], ah[mt], bh[nt]);
                    mma16816(acc[mt][nt], al[mt], bh[nt]);
                    mma16816(acc[mt][nt], ah[mt], bl[nt]);
                }
        }

        if (pf) {
            #pragma unroll
            for (int it = 0; it < 4; it++) {
                int r = lr0 + it * 32;
                uint32_t doff = (uint32_t)(r * SKB + lc8) * 2;
                *(uint4*)(dst + 2*TILE_B + doff) = ra[it];
                *(uint4*)(dst + 3*TILE_B + doff) = ra[it + 4];
            }
        }
        __syncthreads();
    }

    // ---- epilogue ----
    #pragma unroll
    for (int mt = 0; mt < 2; mt++) {
        #pragma unroll
        for (int nt = 0; nt < 8; nt++) {
            const int r0 = row0 + 32*wr + 16*mt + (lane >> 2);
            const int cc = col0 + 64*wc + 8*nt + 2*(lane & 3);
            float2 bv = make_float2(0.f, 0.f);
            if (HB) bv = *(const float2*)&bias[cc];
            #pragma unroll
            for (int hh = 0; hh < 2; hh++) {
                const int r = r0 + hh * 8;
                float v0 = acc[mt][nt][2*hh]     * scale;
                float v1 = acc[mt][nt][2*hh + 1] * scale;
                if (HB) { v0 += bv.x; v1 += bv.y; }
                if (HR) {
                    float2 rv = *(const float2*)&resid[(size_t)r * ldc + cc];
                    v0 += rv.x; v1 += rv.y;
                }
                if (ACT == 1) { v0 = gelu_exact(v0); v1 = gelu_exact(v1); }
                if (OUT == 0) {
                    *(float2*)&C[(size_t)r * ldc + cc] = make_float2(v0, v1);
                } else {
                    bf16 h0 = __float2bfloat16_rn(v0);
                    bf16 h1 = __float2bfloat16_rn(v1);
                    *(__nv_bfloat162*)&Ch[(size_t)r * ldc + cc] = __halves2bfloat162(h0, h1);
                    *(__nv_bfloat162*)&Cl[(size_t)r * ldc + cc] =
                        __halves2bfloat162(__float2bfloat16_rn(v0 - __bfloat162float(h0)),
                                           __float2bfloat16_rn(v1 - __bfloat162float(h1)));
                }
            }
        }
    }
}

// ---------------- split: fp32 -> (hi, lo) bf16 planes ----------------
__global__ __launch_bounds__(256) void split_kernel(const float4* __restrict__ src,
                                                    uint2* __restrict__ h,
                                                    uint2* __restrict__ l, int n4)
{
    int i = blockIdx.x * 256 + threadIdx.x;
    if (i < n4) {
        uint2 H, L;
        split4(src[i], H, L);
        h[i] = H; l[i] = L;
    }
}

// ---------------- V transpose on split planes ----------------
__global__ __launch_bounds__(256) void transpose_v(const bf16* __restrict__ qh,
                                                   const bf16* __restrict__ ql,
                                                   bf16* __restrict__ vth,
                                                   bf16* __restrict__ vtl)
{
    __shared__ bf16 th[32][34], tl[32][34];
    const int bh = blockIdx.z, b = bh / Hc, h = bh % Hc;
    const int q0 = blockIdx.x * 32, d0 = blockIdx.y * 32;
    const int tx = threadIdx.x & 31, ty = threadIdx.x >> 5;
    const size_t so = (size_t)b * Lc * D3c + 2 * Dc + h * HDc;
    #pragma unroll
    for (int i = ty; i < 32; i += 8) {
        th[i][tx] = qh[so + (size_t)(q0 + i) * D3c + d0 + tx];
        tl[i][tx] = ql[so + (size_t)(q0 + i) * D3c + d0 + tx];
    }
    __syncthreads();
    const size_t dofs = (size_t)bh * HDc * Lc;
    #pragma unroll
    for (int i = ty; i < 32; i += 8) {
        vth[dofs + (size_t)(d0 + i) * Lc + q0 + tx] = th[tx][i];
        vtl[dofs + (size_t)(d0 + i) * Lc + q0 + tx] = tl[tx][i];
    }
}

// ---------------- layernorm (fp32 in, split bf16 out or fp32 out) ----------------
template<bool SPLIT>
__global__ __launch_bounds__(256)
void layernorm_kernel(const float* __restrict__ x, const float* __restrict__ g,
                      const float* __restrict__ b,
                      float* __restrict__ outF, bf16* __restrict__ outH, bf16* __restrict__ outL)
{
    const int row = blockIdx.x;
    const int t   = threadIdx.x;
    const float4 v = ((const float4*)(x + (size_t)row * Dc))[t];

    float s1 = v.x + v.y + v.z + v.w;
    float s2 = v.x*v.x + v.y*v.y + v.z*v.z + v.w*v.w;

    __shared__ float sh1[8], sh2[8];
    #pragma unroll
    for (int o = 16; o > 0; o >>= 1) {
        s1 += __shfl_down_sync(0xffffffffu, s1, o);
        s2 += __shfl_down_sync(0xffffffffu, s2, o);
    }
    if ((t & 31) == 0) { sh1[t >> 5] = s1; sh2[t >> 5] = s2; }
    __syncthreads();
    if (t < 8) {
        s1 = sh1[t]; s2 = sh2[t];
        #pragma unroll
        for (int o = 4; o > 0; o >>= 1) {
            s1 += __shfl_down_sync(0xffu, s1, o);
            s2 += __shfl_down_sync(0xffu, s2, o);
        }
        if (t == 0) { sh1[0] = s1; sh2[0] = s2; }
    }
    __syncthreads();

    const float mean = sh1[0] * (1.0f / Dc);
    const float var  = sh2[0] * (1.0f / Dc) - mean * mean;
    const float rstd = rsqrtf(var + 1e-5f);

    const float4 gv = ((const float4*)g)[t];
    const float4 bv = ((const float4*)b)[t];
    float4 r;
    r.x = (v.x - mean) * rstd * gv.x + bv.x;
    r.y = (v.y - mean) * rstd * gv.y + bv.y;
    r.z = (v.z - mean) * rstd * gv.z + bv.z;
    r.w = (v.w - mean) * rstd * gv.w + bv.w;
    if (SPLIT) {
        uint2 H, L;
        split4(r, H, L);
        ((uint2*)(outH + (size_t)row * Dc))[t] = H;
        ((uint2*)(outL + (size_t)row * Dc))[t] = L;
    } else {
        ((float4*)(outF + (size_t)row * Dc))[t] = r;
    }
}

// ---------------- softmax (fp32 in, split bf16 out) ----------------
__global__ __launch_bounds__(256)
void softmax_kernel(const float* __restrict__ s, bf16* __restrict__ ph, bf16* __restrict__ pl)
{
    const size_t row = blockIdx.x;
    const float4* p = (const float4*)(s + row * (size_t)Lc);
    const int t = threadIdx.x;

    float4 a = p[t];
    float4 c = p[t + 256];

    float mx = fmaxf(fmaxf(fmaxf(a.x, a.y), fmaxf(a.z, a.w)),
                     fmaxf(fmaxf(c.x, c.y), fmaxf(c.z, c.w)));

    __shared__ float sh[8];
    #pragma unroll
    for (int o = 16; o > 0; o >>= 1) mx = fmaxf(mx, __shfl_down_sync(0xffffffffu, mx, o));
    if ((t & 31) == 0) sh[t >> 5] = mx;
    __syncthreads();
    if (t < 8) {
        mx = sh[t];
        #pragma unroll
        for (int o = 4; o > 0; o >>= 1) mx = fmaxf(mx, __shfl_down_sync(0xffu, mx, o));
        if (t == 0) sh[0] = mx;
    }
    __syncthreads();
    mx = sh[0];
    __syncthreads();

    a.x = expf(a.x - mx); a.y = expf(a.y - mx); a.z = expf(a.z - mx); a.w = expf(a.w - mx);
    c.x = expf(c.x - mx); c.y = expf(c.y - mx); c.z = expf(c.z - mx); c.w = expf(c.w - mx);

    float sm = a.x + a.y + a.z + a.w + c.x + c.y + c.z + c.w;
    #pragma unroll
    for (int o = 16; o > 0; o >>= 1) sm += __shfl_down_sync(0xffffffffu, sm, o);
    if ((t & 31) == 0) sh[t >> 5] = sm;
    __syncthreads();
    if (t < 8) {
        sm = sh[t];
        #pragma unroll
        for (int o = 4; o > 0; o >>= 1) sm += __shfl_down_sync(0xffu, sm, o);
        if (t == 0) sh[0] = sm;
    }
    __syncthreads();
    const float inv = 1.0f / sh[0];

    a.x *= inv; a.y *= inv; a.z *= inv; a.w *= inv;
    c.x *= inv; c.y *= inv; c.z *= inv; c.w *= inv;

    uint2 H, L;
    split4(a, H, L);
    ((uint2*)(ph + row * (size_t)Lc))[t] = H;
    ((uint2*)(pl + row * (size_t)Lc))[t] = L;
    split4(c, H, L);
    ((uint2*)(ph + row * (size_t)Lc))[t + 256] = H;
    ((uint2*)(pl + row * (size_t)Lc))[t + 256] = L;
}

// ---------------- host side ----------------
static void do_split(const float* src, bf16* h, bf16* l, size_t n) {
    int n4 = (int)(n / 4);
    split_kernel<<<(n4 + 255) / 256, 256>>>((const float4*)src, (uint2*)h, (uint2*)l, n4);
}

extern "C" void kernel_launch(void* const* d_in, const int* in_sizes, int n_in,
                              void* d_out, int out_size)
{
    const float* x    = (const float*)d_in[0];
    const float* w3d  = (const float*)d_in[1];
    const float* b3d  = (const float*)d_in[2];
    const float* ln1g = (const float*)d_in[3];
    const float* ln1b = (const float*)d_in[4];
    const float* wqkv = (const float*)d_in[5];
    const float* bqkv = (const float*)d_in[6];
    const float* wprj = (const float*)d_in[7];
    const float* bprj = (const float*)d_in[8];
    const float* ln2g = (const float*)d_in[9];
    const float* ln2b = (const float*)d_in[10];
    const float* w1   = (const float*)d_in[11];
    const float* b1   = (const float*)d_in[12];
    const float* w2   = (const float*)d_in[13];
    const float* b2   = (const float*)d_in[14];
    const float* lnfg = (const float*)d_in[15];
    const float* lnfb = (const float*)d_in[16];
    float* out = (float*)d_out;

    float *h, *sc;
    bf16 *xh,*xl,*w3h,*w3l,*hnh,*hnl,*wqh,*wql,*wph,*wpl,*w1h,*w1l,*w2h,*w2l;
    bf16 *qvh,*qvl,*vth,*vtl,*ph,*pl,*oh,*ol,*fh,*fl;
    cudaGetSymbolAddress((void**)&h,   g_h);
    cudaGetSymbolAddress((void**)&sc,  g_sc);
    cudaGetSymbolAddress((void**)&xh,  g_xh);  cudaGetSymbolAddress((void**)&xl,  g_xl);
    cudaGetSymbolAddress((void**)&w3h, g_w3h); cudaGetSymbolAddress((void**)&w3l, g_w3l);
    cudaGetSymbolAddress((void**)&hnh, g_hnh); cudaGetSymbolAddress((void**)&hnl, g_hnl);
    cudaGetSymbolAddress((void**)&wqh, g_wqh); cudaGetSymbolAddress((void**)&wql, g_wql);
    cudaGetSymbolAddress((void**)&wph, g_wph); cudaGetSymbolAddress((void**)&wpl, g_wpl);
    cudaGetSymbolAddress((void**)&w1h, g_w1h); cudaGetSymbolAddress((void**)&w1l, g_w1l);
    cudaGetSymbolAddress((void**)&w2h, g_w2h); cudaGetSymbolAddress((void**)&w2l, g_w2l);
    cudaGetSymbolAddress((void**)&qvh, g_qvh); cudaGetSymbolAddress((void**)&qvl, g_qvl);
    cudaGetSymbolAddress((void**)&vth, g_vth); cudaGetSymbolAddress((void**)&vtl, g_vtl);
    cudaGetSymbolAddress((void**)&ph,  g_ph);  cudaGetSymbolAddress((void**)&pl,  g_pl);
    cudaGetSymbolAddress((void**)&oh,  g_oh);  cudaGetSymbolAddress((void**)&ol,  g_ol);
    cudaGetSymbolAddress((void**)&fh,  g_fh);  cudaGetSymbolAddress((void**)&fl,  g_fl);

    cudaFuncSetAttribute(tc_gemm<true,false,0,0>,  cudaFuncAttributeMaxDynamicSharedMemorySize, SMEM_DYN);
    cudaFuncSetAttribute(tc_gemm<true,false,0,1>,  cudaFuncAttributeMaxDynamicSharedMemorySize, SMEM_DYN);
    cudaFuncSetAttribute(tc_gemm<false,false,0,0>, cudaFuncAttributeMaxDynamicSharedMemorySize, SMEM_DYN);
    cudaFuncSetAttribute(tc_gemm<false,false,0,1>, cudaFuncAttributeMaxDynamicSharedMemorySize, SMEM_DYN);
    cudaFuncSetAttribute(tc_gemm<true,true,0,0>,   cudaFuncAttributeMaxDynamicSharedMemorySize, SMEM_DYN);
    cudaFuncSetAttribute(tc_gemm<true,false,1,1>,  cudaFuncAttributeMaxDynamicSharedMemorySize, SMEM_DYN);

    const dim3 blk(256);

    // one-time splits
    do_split(x,   xh,  xl,  (size_t)Mc * D3c);
    do_split(w3d, w3h, w3l, (size_t)Dc * D3c);

    // ---- embed: h = x @ w3d^T + b3d ----
    tc_gemm<true,false,0,0><<<dim3(Dc/128, Mc/128, 1), blk, SMEM_DYN>>>(
        xh, xl, D3c, w3h, w3l, D3c, b3d, nullptr,
        h, nullptr, nullptr, Dc, D3c, 1.0f, 0,0,0,0,0,0, 1);

    for (int i = 0; i < NLc; i++) {
        do_split(wqkv + (size_t)i*D3c*Dc, wqh, wql, (size_t)D3c*Dc);
        do_split(wprj + (size_t)i*Dc*Dc,  wph, wpl, (size_t)Dc*Dc);
        do_split(w1   + (size_t)i*FFc*Dc, w1h, w1l, (size_t)FFc*Dc);
        do_split(w2   + (size_t)i*Dc*FFc, w2h, w2l, (size_t)Dc*FFc);

        layernorm_kernel<true><<<Mc, blk>>>(h, ln1g + (size_t)i*Dc, ln1b + (size_t)i*Dc,
                                            nullptr, hnh, hnl);

        // qkv = hn @ wqkv^T + bqkv  -> split planes
        tc_gemm<true,false,0,1><<<dim3(D3c/128, Mc/128, 1), blk, SMEM_DYN>>>(
            hnh, hnl, Dc, wqh, wql, Dc, bqkv + (size_t)i*D3c, nullptr,
            nullptr, qvh, qvl, D3c, Dc, 1.0f, 0,0,0,0,0,0, 1);

        transpose_v<<<dim3(Lc/32, HDc/32, Bc*Hc), blk>>>(qvh, qvl, vth, vtl);

        // scores = scale * Q @ K^T  (batched over b,h) -> fp32
        tc_gemm<false,false,0,0><<<dim3(Lc/128, Lc/128, Bc*Hc), blk, SMEM_DYN>>>(
            qvh, qvl, D3c,
            qvh + Dc, qvl + Dc, D3c,
            nullptr, nullptr,
            sc, nullptr, nullptr, Lc, HDc, 0.0625f,
            (long)Lc*D3c, (long)HDc,
            (long)Lc*D3c, (long)HDc,
            (long)Hc*Lc*Lc, (long)Lc*Lc,
            Hc);

        softmax_kernel<<<Bc*Hc*Lc, blk>>>(sc, ph, pl);

        // o = P @ Vt^T (batched) -> split planes
        tc_gemm<false,false,0,1><<<dim3(HDc/128, Lc/128, Bc*Hc), blk, SMEM_DYN>>>(
            ph, pl, Lc,
            vth, vtl, Lc,
            nullptr, nullptr,
            nullptr, oh, ol, Dc, Lc, 1.0f,
            (long)Hc*Lc*Lc, (long)Lc*Lc,
            (long)Hc*HDc*Lc, (long)HDc*Lc,
            (long)Lc*Dc, (long)HDc,
            Hc);

        // h = h + o @ wproj^T + bproj
        tc_gemm<true,true,0,0><<<dim3(Dc/128, Mc/128, 1), blk, SMEM_DYN>>>(
            oh, ol, Dc, wph, wpl, Dc, bprj + (size_t)i*Dc, h,
            h, nullptr, nullptr, Dc, Dc, 1.0f, 0,0,0,0,0,0, 1);

        layernorm_kernel<true><<<Mc, blk>>>(h, ln2g + (size_t)i*Dc, ln2b + (size_t)i*Dc,
                                            nullptr, hnh, hnl);

        // f = gelu(hn @ w1^T + b1) -> split planes
        tc_gemm<true,false,1,1><<<dim3(FFc/128, Mc/128, 1), blk, SMEM_DYN>>>(
            hnh, hnl, Dc, w1h, w1l, Dc, b1 + (size_t)i*FFc, nullptr,
            nullptr, fh, fl, FFc, Dc, 1.0f, 0,0,0,0,0,0, 1);

        // h = h + f @ w2^T + b2
        tc_gemm<true,true,0,0><<<dim3(Dc/128, Mc/128, 1), blk, SMEM_DYN>>>(
            fh, fl, FFc, w2h, w2l, FFc, b2 + (size_t)i*Dc, h,
            h, nullptr, nullptr, Dc, FFc, 1.0f, 0,0,0,0,0,0, 1);
    }

    layernorm_kernel<false><<<Mc, blk>>>(h, lnfg, lnfb, out, nullptr, nullptr);
}

// round 6
// speedup vs baseline: 1.4954x; 1.3143x over previous
#include <cuda_runtime.h>
#include <cuda_bf16.h>
#include <cuda_fp16.h>
#include <math.h>
#include <stdint.h>

// ---------------- problem constants ----------------
#define Bc   4
#define Lc   2048
#define Dc   1024
#define Hc   4
#define HDc  256
#define NLc  2
#define FFc  4096
#define Mc   (Bc*Lc)     // 8192 tokens
#define D3c  (3*Dc)      // 3072

typedef __nv_bfloat16 bf16;

// ---------------- device scratch (static; no allocations) ----------------
__device__ float g_h  [(size_t)Mc*Dc];            // residual fp32
__device__ float g_sc [(size_t)Bc*Hc*Lc*Lc];      // scores fp32
// bf16 split planes (embed + scores path)
__device__ __align__(16) bf16 g_xh [(size_t)Mc*D3c],  g_xl [(size_t)Mc*D3c];
__device__ __align__(16) bf16 g_w3h[(size_t)Dc*D3c],  g_w3l[(size_t)Dc*D3c];
__device__ __align__(16) bf16 g_qvh[(size_t)Mc*D3c],  g_qvl[(size_t)Mc*D3c];
// fp16 planes
__device__ __align__(16) __half g_hnh[(size_t)Mc*Dc],   g_hnl[(size_t)Mc*Dc];
__device__ __align__(16) __half g_wq [(size_t)D3c*Dc];
__device__ __align__(16) __half g_wp [(size_t)Dc*Dc];
__device__ __align__(16) __half g_w1 [(size_t)FFc*Dc];
__device__ __align__(16) __half g_w2 [(size_t)Dc*FFc];
__device__ __align__(16) __half g_vt [(size_t)Bc*Hc*HDc*Lc];
__device__ __align__(16) __half g_ph [(size_t)Bc*Hc*Lc*Lc], g_pl [(size_t)Bc*Hc*Lc*Lc];
__device__ __align__(16) __half g_oh [(size_t)Mc*Dc],   g_ol [(size_t)Mc*Dc];
__device__ __align__(16) __half g_fh [(size_t)Mc*FFc],  g_fl [(size_t)Mc*FFc];

// ---------------- helpers ----------------
__device__ __forceinline__ uint32_t smem_u32(const void* p) {
    uint32_t a;
    asm("{ .reg .u64 t; cvta.to.shared.u64 t, %1; cvt.u32.u64 %0, t; }" : "=r"(a) : "l"(p));
    return a;
}
__device__ __forceinline__ void ldsm4(uint32_t* r, uint32_t addr) {
    asm volatile("ldmatrix.sync.aligned.m8n8.x4.shared.b16 {%0,%1,%2,%3}, [%4];"
        : "=r"(r[0]), "=r"(r[1]), "=r"(r[2]), "=r"(r[3]) : "r"(addr));
}
__device__ __forceinline__ void mma_bf(float* d, const uint32_t* a, const uint32_t* b) {
    asm volatile(
        "mma.sync.aligned.m16n8k16.row.col.f32.bf16.bf16.f32 "
        "{%0,%1,%2,%3}, {%4,%5,%6,%7}, {%8,%9}, {%0,%1,%2,%3};"
        : "+f"(d[0]), "+f"(d[1]), "+f"(d[2]), "+f"(d[3])
        : "r"(a[0]), "r"(a[1]), "r"(a[2]), "r"(a[3]), "r"(b[0]), "r"(b[1]));
}
__device__ __forceinline__ void mma_hf(float* d, const uint32_t* a, const uint32_t* b) {
    asm volatile(
        "mma.sync.aligned.m16n8k16.row.col.f32.f16.f16.f32 "
        "{%0,%1,%2,%3}, {%4,%5,%6,%7}, {%8,%9}, {%0,%1,%2,%3};"
        : "+f"(d[0]), "+f"(d[1]), "+f"(d[2]), "+f"(d[3])
        : "r"(a[0]), "r"(a[1]), "r"(a[2]), "r"(a[3]), "r"(b[0]), "r"(b[1]));
}
__device__ __forceinline__ float gelu_exact(float x) {
    return 0.5f * x * (1.0f + erff(x * 0.70710678118654752440f));
}
// split fp32x4 -> hi/lo bf16x4 packed as uint2
__device__ __forceinline__ void split4b(float4 v, uint2& Hh, uint2& Ll) {
    bf16 hx = __float2bfloat16_rn(v.x);
    bf16 hy = __float2bfloat16_rn(v.y);
    bf16 hz = __float2bfloat16_rn(v.z);
    bf16 hw = __float2bfloat16_rn(v.w);
    union { __nv_bfloat162 b2[2]; uint2 u; } H, L;
    H.b2[0] = __halves2bfloat162(hx, hy);
    H.b2[1] = __halves2bfloat162(hz, hw);
    L.b2[0] = __halves2bfloat162(__float2bfloat16_rn(v.x - __bfloat162float(hx)),
                                 __float2bfloat16_rn(v.y - __bfloat162float(hy)));
    L.b2[1] = __halves2bfloat162(__float2bfloat16_rn(v.z - __bfloat162float(hz)),
                                 __float2bfloat16_rn(v.w - __bfloat162float(hw)));
    Hh = H.u; Ll = L.u;
}
// split fp32x4 -> hi/lo fp16x4 packed as uint2
__device__ __forceinline__ void split4h(float4 v, uint2& Hh, uint2& Ll) {
    __half hx = __float2half_rn(v.x);
    __half hy = __float2half_rn(v.y);
    __half hz = __float2half_rn(v.z);
    __half hw = __float2half_rn(v.w);
    union { __half2 h2[2]; uint2 u; } H, L;
    H.h2[0] = __halves2half2(hx, hy);
    H.h2[1] = __halves2half2(hz, hw);
    L.h2[0] = __halves2half2(__float2half_rn(v.x - __half2float(hx)),
                             __float2half_rn(v.y - __half2float(hy)));
    L.h2[1] = __halves2half2(__float2half_rn(v.z - __half2float(hz)),
                             __float2half_rn(v.w - __half2float(hw)));
    Hh = H.u; Ll = L.u;
}
__device__ __forceinline__ uint2 conv4h(float4 v) {
    union { __half2 h2[2]; uint2 u; } H;
    H.h2[0] = __halves2half2(__float2half_rn(v.x), __float2half_rn(v.y));
    H.h2[1] = __halves2half2(__float2half_rn(v.z), __float2half_rn(v.w));
    return H.u;
}

// ================= bf16 3-term GEMM (embed + scores) =================
// C[M,N] = scale * (Ah+Al)(Bh+Bl)^T + bias. fp32 out.
#define KC     64
#define SKB    72
#define TILE_B (128*SKB*2)          // 18432 B
#define STG_BF (4*TILE_B)           // 73728 B
#define SM_BF  (2*STG_BF)           // 147456 B

template<bool HB>
__global__ __launch_bounds__(256, 1) void tc_gbf(
    const bf16* __restrict__ Ah, const bf16* __restrict__ Al, int lda,
    const bf16* __restrict__ Bh, const bf16* __restrict__ Bl, int ldb,
    const float* __restrict__ bias,
    float* __restrict__ C, int ldc,
    int K, float scale,
    long aso, long asi, long bso, long bsi, long cso, long csi, int zinner)
{
    const int z  = blockIdx.z;
    const int zo = z / zinner;
    const int zi = z - zo * zinner;
    const size_t aofs = (size_t)zo * aso + (size_t)zi * asi;
    const size_t bofs = (size_t)zo * bso + (size_t)zi * bsi;
    Ah += aofs; Al += aofs;
    Bh += bofs; Bl += bofs;
    C  += (size_t)zo * cso + (size_t)zi * csi;

    extern __shared__ char dsm[];
    const uint32_t sb32 = smem_u32(dsm);

    const int tid  = threadIdx.x;
    const int wid  = tid >> 5;
    const int lane = tid & 31;
    const int wr   = wid & 3;
    const int wc   = wid >> 2;
    const int row0 = blockIdx.y * 128;
    const int col0 = blockIdx.x * 128;

    const int lr0 = tid >> 3;
    const int lc8 = (tid & 7) << 3;

    const bf16* A0h = Ah + (size_t)row0 * lda;
    const bf16* A0l = Al + (size_t)row0 * lda;
    const bf16* B0h = Bh + (size_t)col0 * ldb;
    const bf16* B0l = Bl + (size_t)col0 * ldb;

    float acc[2][8][4];
    #pragma unroll
    for (int mt = 0; mt < 2; mt++)
        #pragma unroll
        for (int nt = 0; nt < 8; nt++)
            #pragma unroll
            for (int j = 0; j < 4; j++) acc[mt][nt][j] = 0.0f;

    const int nc = K / KC;

    #pragma unroll
    for (int it = 0; it < 4; it++) {
        int r = lr0 + it * 32;
        uint32_t doff = (uint32_t)(r * SKB + lc8) * 2;
        *(uint4*)(dsm + 0*TILE_B + doff) = *(const uint4*)(A0h + (size_t)r * lda + lc8);
        *(uint4*)(dsm + 1*TILE_B + doff) = *(const uint4*)(A0l + (size_t)r * lda + lc8);
        *(uint4*)(dsm + 2*TILE_B + doff) = *(const uint4*)(B0h + (size_t)r * ldb + lc8);
        *(uint4*)(dsm + 3*TILE_B + doff) = *(const uint4*)(B0l + (size_t)r * ldb + lc8);
    }
    __syncthreads();

    const int ro = lane & 15;
    const int co = (lane >> 4) << 3;

    for (int c = 0; c < nc; c++) {
        const int s = c & 1;
        const uint32_t sOff = sb32 + (uint32_t)s * STG_BF;
        char* dst = dsm + (size_t)(s ^ 1) * STG_BF;
        const bool pf = (c + 1 < nc);
        const int kn = (c + 1) * KC;

        uint4 ra[8];
        if (pf) {
            #pragma unroll
            for (int it = 0; it < 4; it++) {
                int r = lr0 + it * 32;
                ra[it]     = *(const uint4*)(A0h + (size_t)r * lda + kn + lc8);
                ra[it + 4] = *(const uint4*)(A0l + (size_t)r * lda + kn + lc8);
            }
        }

        #pragma unroll
        for (int ks = 0; ks < 2; ks++) {
            const int k0 = ks * 16;
            uint32_t ah[2][4], al[2][4];
            #pragma unroll
            for (int mt = 0; mt < 2; mt++) {
                uint32_t off = (uint32_t)((32*wr + 16*mt + ro) * SKB + k0 + co) * 2;
                ldsm4(ah[mt], sOff + 0*TILE_B + off);
                ldsm4(al[mt], sOff + 1*TILE_B + off);
            }
            uint32_t bh[8][2], bl[8][2];
            #pragma unroll
            for (int p = 0; p < 4; p++) {
                uint32_t off = (uint32_t)((64*wc + 16*p + ro) * SKB + k0 + co) * 2;
                uint32_t r[4];
                ldsm4(r, sOff + 2*TILE_B + off);
                bh[2*p][0] = r[0];   bh[2*p][1] = r[2];
                bh[2*p+1][0] = r[1]; bh[2*p+1][1] = r[3];
                ldsm4(r, sOff + 3*TILE_B + off);
                bl[2*p][0] = r[0];   bl[2*p][1] = r[2];
                bl[2*p+1][0] = r[1]; bl[2*p+1][1] = r[3];
            }
            #pragma unroll
            for (int mt = 0; mt < 2; mt++)
                #pragma unroll
                for (int nt = 0; nt < 8; nt++) {
                    mma_bf(acc[mt][nt], ah[mt], bh[nt]);
                    mma_bf(acc[mt][nt], al[mt], bh[nt]);
                    mma_bf(acc[mt][nt], ah[mt], bl[nt]);
                }
        }

        if (pf) {
            #pragma unroll
            for (int it = 0; it < 4; it++) {
                int r = lr0 + it * 32;
                uint32_t doff = (uint32_t)(r * SKB + lc8) * 2;
                *(uint4*)(dst + 0*TILE_B + doff) = ra[it];
                *(uint4*)(dst + 1*TILE_B + doff) = ra[it + 4];
            }
            #pragma unroll
            for (int it = 0; it < 4; it++) {
                int r = lr0 + it * 32;
                ra[it]     = *(const uint4*)(B0h + (size_t)r * ldb + kn + lc8);
                ra[it + 4] = *(const uint4*)(B0l + (size_t)r * ldb + kn + lc8);
            }
        }

        #pragma unroll
        for (int ks = 2; ks < 4; ks++) {
            const int k0 = ks * 16;
            uint32_t ah[2][4], al[2][4];
            #pragma unroll
            for (int mt = 0; mt < 2; mt++) {
                uint32_t off = (uint32_t)((32*wr + 16*mt + ro) * SKB + k0 + co) * 2;
                ldsm4(ah[mt], sOff + 0*TILE_B + off);
                ldsm4(al[mt], sOff + 1*TILE_B + off);
            }
            uint32_t bh[8][2], bl[8][2];
            #pragma unroll
            for (int p = 0; p < 4; p++) {
                uint32_t off = (uint32_t)((64*wc + 16*p + ro) * SKB + k0 + co) * 2;
                uint32_t r[4];
                ldsm4(r, sOff + 2*TILE_B + off);
                bh[2*p][0] = r[0];   bh[2*p][1] = r[2];
                bh[2*p+1][0] = r[1]; bh[2*p+1][1] = r[3];
                ldsm4(r, sOff + 3*TILE_B + off);
                bl[2*p][0] = r[0];   bl[2*p][1] = r[2];
                bl[2*p+1][0] = r[1]; bl[2*p+1][1] = r[3];
            }
            #pragma unroll
            for (int mt = 0; mt < 2; mt++)
                #pragma unroll
                for (int nt = 0; nt < 8; nt++) {
                    mma_bf(acc[mt][nt], ah[mt], bh[nt]);
                    mma_bf(acc[mt][nt], al[mt], bh[nt]);
                    mma_bf(acc[mt][nt], ah[mt], bl[nt]);
                }
        }

        if (pf) {
            #pragma unroll
            for (int it = 0; it < 4; it++) {
                int r = lr0 + it * 32;
                uint32_t doff = (uint32_t)(r * SKB + lc8) * 2;
                *(uint4*)(dst + 2*TILE_B + doff) = ra[it];
                *(uint4*)(dst + 3*TILE_B + doff) = ra[it + 4];
            }
        }
        __syncthreads();
    }

    #pragma unroll
    for (int mt = 0; mt < 2; mt++) {
        #pragma unroll
        for (int nt = 0; nt < 8; nt++) {
            const int r0 = row0 + 32*wr + 16*mt + (lane >> 2);
            const int cc = col0 + 64*wc + 8*nt + 2*(lane & 3);
            float2 bv = make_float2(0.f, 0.f);
            if (HB) bv = *(const float2*)&bias[cc];
            #pragma unroll
            for (int hh = 0; hh < 2; hh++) {
                const int r = r0 + hh * 8;
                float v0 = acc[mt][nt][2*hh]     * scale;
                float v1 = acc[mt][nt][2*hh + 1] * scale;
                if (HB) { v0 += bv.x; v1 += bv.y; }
                *(float2*)&C[(size_t)r * ldc + cc] = make_float2(v0, v1);
            }
        }
    }
}

// ================= fp16 2-term GEMM (all weight GEMMs + PV) =================
// C[M,N] = act(scale * (Ah+Al) @ Bh^T + bias + resid)
// OUT: 0 = fp32 C; 1 = fp16 pair; 2 = bf16 pair
#define STG_HF (3*TILE_B)           // 55296 B
#define SM_HF  (2*STG_HF)           // 110592 B

template<bool HB, bool HR, int ACT, int OUT>
__global__ __launch_bounds__(256, 1) void tc_ghf(
    const __half* __restrict__ Ah, const __half* __restrict__ Al, int lda,
    const __half* __restrict__ Bh, int ldb,
    const float* __restrict__ bias,
    const float* __restrict__ resid,
    float* __restrict__ C, void* __restrict__ Cho, void* __restrict__ Clo, int ldc,
    int K, float scale,
    long aso, long asi, long bso, long bsi, long cso, long csi, int zinner)
{
    const int z  = blockIdx.z;
    const int zo = z / zinner;
    const int zi = z - zo * zinner;
    const size_t aofs = (size_t)zo * aso + (size_t)zi * asi;
    const size_t bofs = (size_t)zo * bso + (size_t)zi * bsi;
    const size_t cofs = (size_t)zo * cso + (size_t)zi * csi;
    Ah += aofs; Al += aofs;
    Bh += bofs;

    extern __shared__ char dsm[];
    const uint32_t sb32 = smem_u32(dsm);

    const int tid  = threadIdx.x;
    const int wid  = tid >> 5;
    const int lane = tid & 31;
    const int wr   = wid & 3;
    const int wc   = wid >> 2;
    const int row0 = blockIdx.y * 128;
    const int col0 = blockIdx.x * 128;

    const int lr0 = tid >> 3;
    const int lc8 = (tid & 7) << 3;

    const __half* A0h = Ah + (size_t)row0 * lda;
    const __half* A0l = Al + (size_t)row0 * lda;
    const __half* B0h = Bh + (size_t)col0 * ldb;

    float acc[2][8][4];
    #pragma unroll
    for (int mt = 0; mt < 2; mt++)
        #pragma unroll
        for (int nt = 0; nt < 8; nt++)
            #pragma unroll
            for (int j = 0; j < 4; j++) acc[mt][nt][j] = 0.0f;

    const int nc = K / KC;

    #pragma unroll
    for (int it = 0; it < 4; it++) {
        int r = lr0 + it * 32;
        uint32_t doff = (uint32_t)(r * SKB + lc8) * 2;
        *(uint4*)(dsm + 0*TILE_B + doff) = *(const uint4*)(A0h + (size_t)r * lda + lc8);
        *(uint4*)(dsm + 1*TILE_B + doff) = *(const uint4*)(A0l + (size_t)r * lda + lc8);
        *(uint4*)(dsm + 2*TILE_B + doff) = *(const uint4*)(B0h + (size_t)r * ldb + lc8);
    }
    __syncthreads();

    const int ro = lane & 15;
    const int co = (lane >> 4) << 3;

    for (int c = 0; c < nc; c++) {
        const int s = c & 1;
        const uint32_t sOff = sb32 + (uint32_t)s * STG_HF;
        char* dst = dsm + (size_t)(s ^ 1) * STG_HF;
        const bool pf = (c + 1 < nc);
        const int kn = (c + 1) * KC;

        uint4 ra[8];
        if (pf) {
            #pragma unroll
            for (int it = 0; it < 4; it++) {
                int r = lr0 + it * 32;
                ra[it]     = *(const uint4*)(A0h + (size_t)r * lda + kn + lc8);
                ra[it + 4] = *(const uint4*)(A0l + (size_t)r * lda + kn + lc8);
            }
        }

        #pragma unroll
        for (int ks = 0; ks < 2; ks++) {
            const int k0 = ks * 16;
            uint32_t ah[2][4], al[2][4];
            #pragma unroll
            for (int mt = 0; mt < 2; mt++) {
                uint32_t off = (uint32_t)((32*wr + 16*mt + ro) * SKB + k0 + co) * 2;
                ldsm4(ah[mt], sOff + 0*TILE_B + off);
                ldsm4(al[mt], sOff + 1*TILE_B + off);
            }
            uint32_t bh[8][2];
            #pragma unroll
            for (int p = 0; p < 4; p++) {
                uint32_t off = (uint32_t)((64*wc + 16*p + ro) * SKB + k0 + co) * 2;
                uint32_t r[4];
                ldsm4(r, sOff + 2*TILE_B + off);
                bh[2*p][0] = r[0];   bh[2*p][1] = r[2];
                bh[2*p+1][0] = r[1]; bh[2*p+1][1] = r[3];
            }
            #pragma unroll
            for (int mt = 0; mt < 2; mt++)
                #pragma unroll
                for (int nt = 0; nt < 8; nt++) {
                    mma_hf(acc[mt][nt], ah[mt], bh[nt]);
                    mma_hf(acc[mt][nt], al[mt], bh[nt]);
                }
        }

        if (pf) {
            #pragma unroll
            for (int it = 0; it < 4; it++) {
                int r = lr0 + it * 32;
                uint32_t doff = (uint32_t)(r * SKB + lc8) * 2;
                *(uint4*)(dst + 0*TILE_B + doff) = ra[it];
                *(uint4*)(dst + 1*TILE_B + doff) = ra[it + 4];
            }
            #pragma unroll
            for (int it = 0; it < 4; it++) {
                int r = lr0 + it * 32;
                ra[it] = *(const uint4*)(B0h + (size_t)r * ldb + kn + lc8);
            }
        }

        #pragma unroll
        for (int ks = 2; ks < 4; ks++) {
            const int k0 = ks * 16;
            uint32_t ah[2][4], al[2][4];
            #pragma unroll
            for (int mt = 0; mt < 2; mt++) {
                uint32_t off = (uint32_t)((32*wr + 16*mt + ro) * SKB + k0 + co) * 2;
                ldsm4(ah[mt], sOff + 0*TILE_B + off);
                ldsm4(al[mt], sOff + 1*TILE_B + off);
            }
            uint32_t bh[8][2];
            #pragma unroll
            for (int p = 0; p < 4; p++) {
                uint32_t off = (uint32_t)((64*wc + 16*p + ro) * SKB + k0 + co) * 2;
                uint32_t r[4];
                ldsm4(r, sOff + 2*TILE_B + off);
                bh[2*p][0] = r[0];   bh[2*p][1] = r[2];
                bh[2*p+1][0] = r[1]; bh[2*p+1][1] = r[3];
            }
            #pragma unroll
            for (int mt = 0; mt < 2; mt++)
                #pragma unroll
                for (int nt = 0; nt < 8; nt++) {
                    mma_hf(acc[mt][nt], ah[mt], bh[nt]);
                    mma_hf(acc[mt][nt], al[mt], bh[nt]);
                }
        }

        if (pf) {
            #pragma unroll
            for (int it = 0; it < 4; it++) {
                int r = lr0 + it * 32;
                uint32_t doff = (uint32_t)(r * SKB + lc8) * 2;
                *(uint4*)(dst + 2*TILE_B + doff) = ra[it];
            }
        }
        __syncthreads();
    }

    // ---- epilogue ----
    float* Cp = (OUT == 0) ? C + cofs : nullptr;
    __half* ChH = (OUT == 1) ? (__half*)Cho + cofs : nullptr;
    __half* ClH = (OUT == 1) ? (__half*)Clo + cofs : nullptr;
    bf16*   ChB = (OUT == 2) ? (bf16*)Cho + cofs : nullptr;
    bf16*   ClB = (OUT == 2) ? (bf16*)Clo + cofs : nullptr;
    const float* R = HR ? resid : nullptr;

    #pragma unroll
    for (int mt = 0; mt < 2; mt++) {
        #pragma unroll
        for (int nt = 0; nt < 8; nt++) {
            const int r0 = row0 + 32*wr + 16*mt + (lane >> 2);
            const int cc = col0 + 64*wc + 8*nt + 2*(lane & 3);
            float2 bv = make_float2(0.f, 0.f);
            if (HB) bv = *(const float2*)&bias[cc];
            #pragma unroll
            for (int hh = 0; hh < 2; hh++) {
                const int r = r0 + hh * 8;
                float v0 = acc[mt][nt][2*hh]     * scale;
                float v1 = acc[mt][nt][2*hh + 1] * scale;
                if (HB) { v0 += bv.x; v1 += bv.y; }
                if (HR) {
                    float2 rv = *(const float2*)&R[(size_t)r * ldc + cc];
                    v0 += rv.x; v1 += rv.y;
                }
                if (ACT == 1) { v0 = gelu_exact(v0); v1 = gelu_exact(v1); }
                if (OUT == 0) {
                    *(float2*)&Cp[(size_t)r * ldc + cc] = make_float2(v0, v1);
                } else if (OUT == 1) {
                    __half h0 = __float2half_rn(v0);
                    __half h1 = __float2half_rn(v1);
                    *(__half2*)&ChH[(size_t)r * ldc + cc] = __halves2half2(h0, h1);
                    *(__half2*)&ClH[(size_t)r * ldc + cc] =
                        __halves2half2(__float2half_rn(v0 - __half2float(h0)),
                                       __float2half_rn(v1 - __half2float(h1)));
                } else {
                    bf16 h0 = __float2bfloat16_rn(v0);
                    bf16 h1 = __float2bfloat16_rn(v1);
                    *(__nv_bfloat162*)&ChB[(size_t)r * ldc + cc] = __halves2bfloat162(h0, h1);
                    *(__nv_bfloat162*)&ClB[(size_t)r * ldc + cc] =
                        __halves2bfloat162(__float2bfloat16_rn(v0 - __bfloat162float(h0)),
                                           __float2bfloat16_rn(v1 - __bfloat162float(h1)));
                }
            }
        }
    }
}

// ---------------- converters ----------------
__global__ __launch_bounds__(256) void split_bf_kernel(const float4* __restrict__ src,
                                                       uint2* __restrict__ h,
                                                       uint2* __restrict__ l, int n4)
{
    int i = blockIdx.x * 256 + threadIdx.x;
    if (i < n4) { uint2 H, L; split4b(src[i], H, L); h[i] = H; l[i] = L; }
}
__global__ __launch_bounds__(256) void conv_hf_kernel(const float4* __restrict__ src,
                                                      uint2* __restrict__ h, int n4)
{
    int i = blockIdx.x * 256 + threadIdx.x;
    if (i < n4) h[i] = conv4h(src[i]);
}

// ---------------- V transpose: bf16 pair qkv -> fp16 Vt ----------------
__global__ __launch_bounds__(256) void transpose_v(const bf16* __restrict__ qh,
                                                   const bf16* __restrict__ ql,
                                                   __half* __restrict__ vt)
{
    __shared__ float t[32][33];
    const int bh = blockIdx.z, b = bh / Hc, h = bh % Hc;
    const int q0 = blockIdx.x * 32, d0 = blockIdx.y * 32;
    const int tx = threadIdx.x & 31, ty = threadIdx.x >> 5;
    const size_t so = (size_t)b * Lc * D3c + 2 * Dc + h * HDc;
    #pragma unroll
    for (int i = ty; i < 32; i += 8) {
        size_t idx = so + (size_t)(q0 + i) * D3c + d0 + tx;
        t[i][tx] = __bfloat162float(qh[idx]) + __bfloat162float(ql[idx]);
    }
    __syncthreads();
    const size_t dofs = (size_t)bh * HDc * Lc;
    #pragma unroll
    for (int i = ty; i < 32; i += 8)
        vt[dofs + (size_t)(d0 + i) * Lc + q0 + tx] = __float2half_rn(t[tx][i]);
}

// ---------------- layernorm: fp32 in; OMODE 0 = fp32 out, 1 = fp16 pair ----------------
template<int OMODE>
__global__ __launch_bounds__(256)
void layernorm_kernel(const float* __restrict__ x, const float* __restrict__ g,
                      const float* __restrict__ b,
                      float* __restrict__ outF, __half* __restrict__ outH, __half* __restrict__ outL)
{
    const int row = blockIdx.x;
    const int t   = threadIdx.x;
    const float4 v = ((const float4*)(x + (size_t)row * Dc))[t];

    float s1 = v.x + v.y + v.z + v.w;
    float s2 = v.x*v.x + v.y*v.y + v.z*v.z + v.w*v.w;

    __shared__ float sh1[8], sh2[8];
    #pragma unroll
    for (int o = 16; o > 0; o >>= 1) {
        s1 += __shfl_down_sync(0xffffffffu, s1, o);
        s2 += __shfl_down_sync(0xffffffffu, s2, o);
    }
    if ((t & 31) == 0) { sh1[t >> 5] = s1; sh2[t >> 5] = s2; }
    __syncthreads();
    if (t < 8) {
        s1 = sh1[t]; s2 = sh2[t];
        #pragma unroll
        for (int o = 4; o > 0; o >>= 1) {
            s1 += __shfl_down_sync(0xffu, s1, o);
            s2 += __shfl_down_sync(0xffu, s2, o);
        }
        if (t == 0) { sh1[0] = s1; sh2[0] = s2; }
    }
    __syncthreads();

    const float mean = sh1[0] * (1.0f / Dc);
    const float var  = sh2[0] * (1.0f / Dc) - mean * mean;
    const float rstd = rsqrtf(var + 1e-5f);

    const float4 gv = ((const float4*)g)[t];
    const float4 bv = ((const float4*)b)[t];
    float4 r;
    r.x = (v.x - mean) * rstd * gv.x + bv.x;
    r.y = (v.y - mean) * rstd * gv.y + bv.y;
    r.z = (v.z - mean) * rstd * gv.z + bv.z;
    r.w = (v.w - mean) * rstd * gv.w + bv.w;
    if (OMODE == 1) {
        uint2 H, L;
        split4h(r, H, L);
        ((uint2*)(outH + (size_t)row * Dc))[t] = H;
        ((uint2*)(outL + (size_t)row * Dc))[t] = L;
    } else {
        ((float4*)(outF + (size_t)row * Dc))[t] = r;
    }
}

// ---------------- softmax: fp32 in, fp16 pair out ----------------
__global__ __launch_bounds__(256)
void softmax_kernel(const float* __restrict__ s, __half* __restrict__ ph, __half* __restrict__ pl)
{
    const size_t row = blockIdx.x;
    const float4* p = (const float4*)(s + row * (size_t)Lc);
    const int t = threadIdx.x;

    float4 a = p[t];
    float4 c = p[t + 256];

    float mx = fmaxf(fmaxf(fmaxf(a.x, a.y), fmaxf(a.z, a.w)),
                     fmaxf(fmaxf(c.x, c.y), fmaxf(c.z, c.w)));

    __shared__ float sh[8];
    #pragma unroll
    for (int o = 16; o > 0; o >>= 1) mx = fmaxf(mx, __shfl_down_sync(0xffffffffu, mx, o));
    if ((t & 31) == 0) sh[t >> 5] = mx;
    __syncthreads();
    if (t < 8) {
        mx = sh[t];
        #pragma unroll
        for (int o = 4; o > 0; o >>= 1) mx = fmaxf(mx, __shfl_down_sync(0xffu, mx, o));
        if (t == 0) sh[0] = mx;
    }
    __syncthreads();
    mx = sh[0];
    __syncthreads();

    a.x = expf(a.x - mx); a.y = expf(a.y - mx); a.z = expf(a.z - mx); a.w = expf(a.w - mx);
    c.x = expf(c.x - mx); c.y = expf(c.y - mx); c.z = expf(c.z - mx); c.w = expf(c.w - mx);

    float sm = a.x + a.y + a.z + a.w + c.x + c.y + c.z + c.w;
    #pragma unroll
    for (int o = 16; o > 0; o >>= 1) sm += __shfl_down_sync(0xffffffffu, sm, o);
    if ((t & 31) == 0) sh[t >> 5] = sm;
    __syncthreads();
    if (t < 8) {
        sm = sh[t];
        #pragma unroll
        for (int o = 4; o > 0; o >>= 1) sm += __shfl_down_sync(0xffu, sm, o);
        if (t == 0) sh[0] = sm;
    }
    __syncthreads();
    const float inv = 1.0f / sh[0];

    a.x *= inv; a.y *= inv; a.z *= inv; a.w *= inv;
    c.x *= inv; c.y *= inv; c.z *= inv; c.w *= inv;

    uint2 H, L;
    split4h(a, H, L);
    ((uint2*)(ph + row * (size_t)Lc))[t] = H;
    ((uint2*)(pl + row * (size_t)Lc))[t] = L;
    split4h(c, H, L);
    ((uint2*)(ph + row * (size_t)Lc))[t + 256] = H;
    ((uint2*)(pl + row * (size_t)Lc))[t + 256] = L;
}

// ---------------- host side ----------------
static void do_split_bf(const float* src, bf16* h, bf16* l, size_t n) {
    int n4 = (int)(n / 4);
    split_bf_kernel<<<(n4 + 255) / 256, 256>>>((const float4*)src, (uint2*)h, (uint2*)l, n4);
}
static void do_conv_hf(const float* src, __half* h, size_t n) {
    int n4 = (int)(n / 4);
    conv_hf_kernel<<<(n4 + 255) / 256, 256>>>((const float4*)src, (uint2*)h, n4);
}

extern "C" void kernel_launch(void* const* d_in, const int* in_sizes, int n_in,
                              void* d_out, int out_size)
{
    const float* x    = (const float*)d_in[0];
    const float* w3d  = (const float*)d_in[1];
    const float* b3d  = (const float*)d_in[2];
    const float* ln1g = (const float*)d_in[3];
    const float* ln1b = (const float*)d_in[4];
    const float* wqkv = (const float*)d_in[5];
    const float* bqkv = (const float*)d_in[6];
    const float* wprj = (const float*)d_in[7];
    const float* bprj = (const float*)d_in[8];
    const float* ln2g = (const float*)d_in[9];
    const float* ln2b = (const float*)d_in[10];
    const float* w1   = (const float*)d_in[11];
    const float* b1   = (const float*)d_in[12];
    const float* w2   = (const float*)d_in[13];
    const float* b2   = (const float*)d_in[14];
    const float* lnfg = (const float*)d_in[15];
    const float* lnfb = (const float*)d_in[16];
    float* out = (float*)d_out;

    float *h, *sc;
    bf16 *xh,*xl,*w3h,*w3l,*qvh,*qvl;
    __half *hnh,*hnl,*wq,*wp,*w1p,*w2p,*vt,*ph,*pl,*oh,*ol,*fh,*fl;
    cudaGetSymbolAddress((void**)&h,   g_h);
    cudaGetSymbolAddress((void**)&sc,  g_sc);
    cudaGetSymbolAddress((void**)&xh,  g_xh);  cudaGetSymbolAddress((void**)&xl,  g_xl);
    cudaGetSymbolAddress((void**)&w3h, g_w3h); cudaGetSymbolAddress((void**)&w3l, g_w3l);
    cudaGetSymbolAddress((void**)&qvh, g_qvh); cudaGetSymbolAddress((void**)&qvl, g_qvl);
    cudaGetSymbolAddress((void**)&hnh, g_hnh); cudaGetSymbolAddress((void**)&hnl, g_hnl);
    cudaGetSymbolAddress((void**)&wq,  g_wq);
    cudaGetSymbolAddress((void**)&wp,  g_wp);
    cudaGetSymbolAddress((void**)&w1p, g_w1);
    cudaGetSymbolAddress((void**)&w2p, g_w2);
    cudaGetSymbolAddress((void**)&vt,  g_vt);
    cudaGetSymbolAddress((void**)&ph,  g_ph);  cudaGetSymbolAddress((void**)&pl,  g_pl);
    cudaGetSymbolAddress((void**)&oh,  g_oh);  cudaGetSymbolAddress((void**)&ol,  g_ol);
    cudaGetSymbolAddress((void**)&fh,  g_fh);  cudaGetSymbolAddress((void**)&fl,  g_fl);

    cudaFuncSetAttribute(tc_gbf<true>,  cudaFuncAttributeMaxDynamicSharedMemorySize, SM_BF);
    cudaFuncSetAttribute(tc_gbf<false>, cudaFuncAttributeMaxDynamicSharedMemorySize, SM_BF);
    cudaFuncSetAttribute(tc_ghf<true,false,0,2>,  cudaFuncAttributeMaxDynamicSharedMemorySize, SM_HF);
    cudaFuncSetAttribute(tc_ghf<false,false,0,1>, cudaFuncAttributeMaxDynamicSharedMemorySize, SM_HF);
    cudaFuncSetAttribute(tc_ghf<true,true,0,0>,   cudaFuncAttributeMaxDynamicSharedMemorySize, SM_HF);
    cudaFuncSetAttribute(tc_ghf<true,false,1,1>,  cudaFuncAttributeMaxDynamicSharedMemorySize, SM_HF);

    const dim3 blk(256);

    // launch order arranged so launch index 5 (ncu -s 5 -c 1) is the qkv GEMM
    do_split_bf(x,   xh,  xl,  (size_t)Mc * D3c);            // 0
    do_split_bf(w3d, w3h, w3l, (size_t)Dc * D3c);            // 1

    // ---- embed (bf16 3-term): h = x @ w3d^T + b3d ----
    tc_gbf<true><<<dim3(Dc/128, Mc/128, 1), blk, SM_BF>>>(   // 2
        xh, xl, D3c, w3h, w3l, D3c, b3d, h, Dc, D3c, 1.0f, 0,0,0,0,0,0, 1);

    for (int i = 0; i < NLc; i++) {
        do_conv_hf(wqkv + (size_t)i*D3c*Dc, wq, (size_t)D3c*Dc);              // 3

        layernorm_kernel<1><<<Mc, blk>>>(h, ln1g + (size_t)i*Dc, ln1b + (size_t)i*Dc,
                                         nullptr, hnh, hnl);                   // 4

        // qkv = hn @ wqkv^T + bqkv -> bf16 pair                               // 5 (profiled)
        tc_ghf<true,false,0,2><<<dim3(D3c/128, Mc/128, 1), blk, SM_HF>>>(
            hnh, hnl, Dc, wq, Dc, bqkv + (size_t)i*D3c, nullptr,
            nullptr, qvh, qvl, D3c, Dc, 1.0f, 0,0,0,0,0,0, 1);

        transpose_v<<<dim3(Lc/32, HDc/32, Bc*Hc), blk>>>(qvh, qvl, vt);

        // scores (bf16 3-term) = scale * Q @ K^T
        tc_gbf<false><<<dim3(Lc/128, Lc/128, Bc*Hc), blk, SM_BF>>>(
            qvh, qvl, D3c,
            qvh + Dc, qvl + Dc, D3c,
            nullptr,
            sc, Lc, HDc, 0.0625f,
            (long)Lc*D3c, (long)HDc,
            (long)Lc*D3c, (long)HDc,
            (long)Hc*Lc*Lc, (long)Lc*Lc,
            Hc);

        softmax_kernel<<<Bc*Hc*Lc, blk>>>(sc, ph, pl);

        // o = P @ Vt^T (fp16 2-term) -> fp16 pair
        tc_ghf<false,false,0,1><<<dim3(HDc/128, Lc/128, Bc*Hc), blk, SM_HF>>>(
            ph, pl, Lc,
            vt, Lc,
            nullptr, nullptr,
            nullptr, oh, ol, Dc, Lc, 1.0f,
            (long)Hc*Lc*Lc, (long)Lc*Lc,
            (long)Hc*HDc*Lc, (long)HDc*Lc,
            (long)Lc*Dc, (long)HDc,
            Hc);

        do_conv_hf(wprj + (size_t)i*Dc*Dc, wp, (size_t)Dc*Dc);

        // h = h + o @ wproj^T + bproj
        tc_ghf<true,true,0,0><<<dim3(Dc/128, Mc/128, 1), blk, SM_HF>>>(
            oh, ol, Dc, wp, Dc, bprj + (size_t)i*Dc, h,
            h, nullptr, nullptr, Dc, Dc, 1.0f, 0,0,0,0,0,0, 1);

        layernorm_kernel<1><<<Mc, blk>>>(h, ln2g + (size_t)i*Dc, ln2b + (size_t)i*Dc,
                                         nullptr, hnh, hnl);

        do_conv_hf(w1 + (size_t)i*FFc*Dc, w1p, (size_t)FFc*Dc);

        // f = gelu(hn @ w1^T + b1) -> fp16 pair
        tc_ghf<true,false,1,1><<<dim3(FFc/128, Mc/128, 1), blk, SM_HF>>>(
            hnh, hnl, Dc, w1p, Dc, b1 + (size_t)i*FFc, nullptr,
            nullptr, fh, fl, FFc, Dc, 1.0f, 0,0,0,0,0,0, 1);

        do_conv_hf(w2 + (size_t)i*Dc*FFc, w2p, (size_t)Dc*FFc);

        // h = h + f @ w2^T + b2
        tc_ghf<true,true,0,0><<<dim3(Dc/128, Mc/128, 1), blk, SM_HF>>>(
            fh, fl, FFc, w2p, FFc, b2 + (size_t)i*Dc, h,
            h, nullptr, nullptr, Dc, FFc, 1.0f, 0,0,0,0,0,0, 1);
    }

    layernorm_kernel<0><<<Mc, blk>>>(h, lnfg, lnfb, out, nullptr, nullptr);
}

// round 7
// speedup vs baseline: 1.6975x; 1.1351x over previous
#include <cuda_runtime.h>
#include <cuda_fp16.h>
#include <math.h>
#include <stdint.h>

// ---------------- problem constants ----------------
#define Bc   4
#define Lc   2048
#define Dc   1024
#define Hc   4
#define HDc  256
#define NLc  2
#define FFc  4096
#define Mc   (Bc*Lc)     // 8192 tokens
#define D3c  (3*Dc)      // 3072

// ---------------- device scratch (static; no allocations) ----------------
__device__ float g_h  [(size_t)Mc*Dc];            // residual fp32
__device__ float g_sc [(size_t)Bc*Hc*Lc*Lc];      // scores fp32
// fp16 planes
__device__ __align__(16) __half g_xh [(size_t)Mc*D3c],  g_xl [(size_t)Mc*D3c];
__device__ __align__(16) __half g_w3 [(size_t)Dc*D3c];
__device__ __align__(16) __half g_hnh[(size_t)Mc*Dc],   g_hnl[(size_t)Mc*Dc];
__device__ __align__(16) __half g_wq [(size_t)D3c*Dc];
__device__ __align__(16) __half g_wp [(size_t)Dc*Dc];
__device__ __align__(16) __half g_w1 [(size_t)FFc*Dc];
__device__ __align__(16) __half g_w2 [(size_t)Dc*FFc];
__device__ __align__(16) __half g_qvh[(size_t)Mc*D3c],  g_qvl[(size_t)Mc*D3c];
__device__ __align__(16) __half g_vt [(size_t)Bc*Hc*HDc*Lc];
__device__ __align__(16) __half g_p  [(size_t)Bc*Hc*Lc*Lc];
__device__ __align__(16) __half g_oh [(size_t)Mc*Dc],   g_ol [(size_t)Mc*Dc];
__device__ __align__(16) __half g_fh [(size_t)Mc*FFc],  g_fl [(size_t)Mc*FFc];

// ---------------- helpers ----------------
__device__ __forceinline__ uint32_t smem_u32(const void* p) {
    uint32_t a;
    asm("{ .reg .u64 t; cvta.to.shared.u64 t, %1; cvt.u32.u64 %0, t; }" : "=r"(a) : "l"(p));
    return a;
}
__device__ __forceinline__ void ldsm4(uint32_t* r, uint32_t addr) {
    asm volatile("ldmatrix.sync.aligned.m8n8.x4.shared.b16 {%0,%1,%2,%3}, [%4];"
        : "=r"(r[0]), "=r"(r[1]), "=r"(r[2]), "=r"(r[3]) : "r"(addr));
}
__device__ __forceinline__ void mma_hf(float* d, const uint32_t* a, const uint32_t* b) {
    asm volatile(
        "mma.sync.aligned.m16n8k16.row.col.f32.f16.f16.f32 "
        "{%0,%1,%2,%3}, {%4,%5,%6,%7}, {%8,%9}, {%0,%1,%2,%3};"
        : "+f"(d[0]), "+f"(d[1]), "+f"(d[2]), "+f"(d[3])
        : "r"(a[0]), "r"(a[1]), "r"(a[2]), "r"(a[3]), "r"(b[0]), "r"(b[1]));
}
__device__ __forceinline__ float gelu_exact(float x) {
    return 0.5f * x * (1.0f + erff(x * 0.70710678118654752440f));
}
// split fp32x4 -> hi/lo fp16x4 packed as uint2
__device__ __forceinline__ void split4h(float4 v, uint2& Hh, uint2& Ll) {
    __half hx = __float2half_rn(v.x);
    __half hy = __float2half_rn(v.y);
    __half hz = __float2half_rn(v.z);
    __half hw = __float2half_rn(v.w);
    union { __half2 h2[2]; uint2 u; } H, L;
    H.h2[0] = __halves2half2(hx, hy);
    H.h2[1] = __halves2half2(hz, hw);
    L.h2[0] = __halves2half2(__float2half_rn(v.x - __half2float(hx)),
                             __float2half_rn(v.y - __half2float(hy)));
    L.h2[1] = __halves2half2(__float2half_rn(v.z - __half2float(hz)),
                             __float2half_rn(v.w - __half2float(hw)));
    Hh = H.u; Ll = L.u;
}
__device__ __forceinline__ uint2 conv4h(float4 v) {
    union { __half2 h2[2]; uint2 u; } H;
    H.h2[0] = __halves2half2(__float2half_rn(v.x), __float2half_rn(v.y));
    H.h2[1] = __halves2half2(__float2half_rn(v.z), __float2half_rn(v.w));
    return H.u;
}

// ================= fp16 GEMM, TERMS in {1,2} =================
// C[M,N] = act(scale * (Ah [+Al]) @ Bh^T + bias + resid)
// OUT: 0 = fp32 C; 1 = fp16 pair
#define KC     64
#define SKB    72
#define TILE_B (128*SKB*2)          // 18432 B

template<int TERMS, bool HB, bool HR, int ACT, int OUT>
__global__ __launch_bounds__(256, 1) void tc_ghf(
    const __half* __restrict__ Ah, const __half* __restrict__ Al, int lda,
    const __half* __restrict__ Bh, int ldb,
    const float* __restrict__ bias,
    const float* __restrict__ resid,
    float* __restrict__ C, __half* __restrict__ Cho, __half* __restrict__ Clo, int ldc,
    int K, float scale,
    long aso, long asi, long bso, long bsi, long cso, long csi, int zinner)
{
    constexpr uint32_t BOFF = (uint32_t)TERMS * TILE_B;       // B tile smem offset
    constexpr uint32_t STG  = (uint32_t)(TERMS + 1) * TILE_B; // stage bytes

    const int z  = blockIdx.z;
    const int zo = z / zinner;
    const int zi = z - zo * zinner;
    const size_t aofs = (size_t)zo * aso + (size_t)zi * asi;
    const size_t bofs = (size_t)zo * bso + (size_t)zi * bsi;
    const size_t cofs = (size_t)zo * cso + (size_t)zi * csi;
    Ah += aofs;
    if (TERMS == 2) Al += aofs;
    Bh += bofs;

    extern __shared__ char dsm[];
    const uint32_t sb32 = smem_u32(dsm);

    const int tid  = threadIdx.x;
    const int wid  = tid >> 5;
    const int lane = tid & 31;
    const int wr   = wid & 3;
    const int wc   = wid >> 2;
    const int row0 = blockIdx.y * 128;
    const int col0 = blockIdx.x * 128;

    const int lr0 = tid >> 3;
    const int lc8 = (tid & 7) << 3;

    const __half* A0h = Ah + (size_t)row0 * lda;
    const __half* A0l = (TERMS == 2) ? Al + (size_t)row0 * lda : nullptr;
    const __half* B0h = Bh + (size_t)col0 * ldb;

    float acc[2][8][4];
    #pragma unroll
    for (int mt = 0; mt < 2; mt++)
        #pragma unroll
        for (int nt = 0; nt < 8; nt++)
            #pragma unroll
            for (int j = 0; j < 4; j++) acc[mt][nt][j] = 0.0f;

    const int nc = K / KC;

    // ---- prologue: stage 0 ----
    #pragma unroll
    for (int it = 0; it < 4; it++) {
        int r = lr0 + it * 32;
        uint32_t doff = (uint32_t)(r * SKB + lc8) * 2;
        *(uint4*)(dsm + 0*TILE_B + doff) = *(const uint4*)(A0h + (size_t)r * lda + lc8);
        if (TERMS == 2)
            *(uint4*)(dsm + 1*TILE_B + doff) = *(const uint4*)(A0l + (size_t)r * lda + lc8);
        *(uint4*)(dsm + BOFF + doff) = *(const uint4*)(B0h + (size_t)r * ldb + lc8);
    }
    __syncthreads();

    const int ro = lane & 15;
    const int co = (lane >> 4) << 3;

    for (int c = 0; c < nc; c++) {
        const int s = c & 1;
        const uint32_t sOff = sb32 + (uint32_t)s * STG;
        char* dst = dsm + (size_t)(s ^ 1) * STG;
        const bool pf = (c + 1 < nc);
        const int kn = (c + 1) * KC;

        uint4 ra[8];
        if (pf) {
            #pragma unroll
            for (int it = 0; it < 4; it++) {
                int r = lr0 + it * 32;
                ra[it] = *(const uint4*)(A0h + (size_t)r * lda + kn + lc8);
                if (TERMS == 2)
                    ra[it + 4] = *(const uint4*)(A0l + (size_t)r * lda + kn + lc8);
            }
        }

        #pragma unroll
        for (int ks = 0; ks < 2; ks++) {
            const int k0 = ks * 16;
            uint32_t ah[2][4], al[2][4];
            #pragma unroll
            for (int mt = 0; mt < 2; mt++) {
                uint32_t off = (uint32_t)((32*wr + 16*mt + ro) * SKB + k0 + co) * 2;
                ldsm4(ah[mt], sOff + 0*TILE_B + off);
                if (TERMS == 2) ldsm4(al[mt], sOff + 1*TILE_B + off);
            }
            uint32_t bh[8][2];
            #pragma unroll
            for (int p = 0; p < 4; p++) {
                uint32_t off = (uint32_t)((64*wc + 16*p + ro) * SKB + k0 + co) * 2;
                uint32_t r[4];
                ldsm4(r, sOff + BOFF + off);
                bh[2*p][0] = r[0];   bh[2*p][1] = r[2];
                bh[2*p+1][0] = r[1]; bh[2*p+1][1] = r[3];
            }
            #pragma unroll
            for (int mt = 0; mt < 2; mt++)
                #pragma unroll
                for (int nt = 0; nt < 8; nt++) {
                    mma_hf(acc[mt][nt], ah[mt], bh[nt]);
                    if (TERMS == 2) mma_hf(acc[mt][nt], al[mt], bh[nt]);
                }
        }

        if (pf) {
            #pragma unroll
            for (int it = 0; it < 4; it++) {
                int r = lr0 + it * 32;
                uint32_t doff = (uint32_t)(r * SKB + lc8) * 2;
                *(uint4*)(dst + 0*TILE_B + doff) = ra[it];
                if (TERMS == 2)
                    *(uint4*)(dst + 1*TILE_B + doff) = ra[it + 4];
            }
            #pragma unroll
            for (int it = 0; it < 4; it++) {
                int r = lr0 + it * 32;
                ra[it] = *(const uint4*)(B0h + (size_t)r * ldb + kn + lc8);
            }
        }

        #pragma unroll
        for (int ks = 2; ks < 4; ks++) {
            const int k0 = ks * 16;
            uint32_t ah[2][4], al[2][4];
            #pragma unroll
            for (int mt = 0; mt < 2; mt++) {
                uint32_t off = (uint32_t)((32*wr + 16*mt + ro) * SKB + k0 + co) * 2;
                ldsm4(ah[mt], sOff + 0*TILE_B + off);
                if (TERMS == 2) ldsm4(al[mt], sOff + 1*TILE_B + off);
            }
            uint32_t bh[8][2];
            #pragma unroll
            for (int p = 0; p < 4; p++) {
                uint32_t off = (uint32_t)((64*wc + 16*p + ro) * SKB + k0 + co) * 2;
                uint32_t r[4];
                ldsm4(r, sOff + BOFF + off);
                bh[2*p][0] = r[0];   bh[2*p][1] = r[2];
                bh[2*p+1][0] = r[1]; bh[2*p+1][1] = r[3];
            }
            #pragma unroll
            for (int mt = 0; mt < 2; mt++)
                #pragma unroll
                for (int nt = 0; nt < 8; nt++) {
                    mma_hf(acc[mt][nt], ah[mt], bh[nt]);
                    if (TERMS == 2) mma_hf(acc[mt][nt], al[mt], bh[nt]);
                }
        }

        if (pf) {
            #pragma unroll
            for (int it = 0; it < 4; it++) {
                int r = lr0 + it * 32;
                uint32_t doff = (uint32_t)(r * SKB + lc8) * 2;
                *(uint4*)(dst + BOFF + doff) = ra[it];
            }
        }
        __syncthreads();
    }

    // ---- epilogue ----
    float*  Cp  = (OUT == 0) ? C + cofs : nullptr;
    __half* ChH = (OUT == 1) ? Cho + cofs : nullptr;
    __half* ClH = (OUT == 1) ? Clo + cofs : nullptr;
    const float* R = HR ? resid : nullptr;

    #pragma unroll
    for (int mt = 0; mt < 2; mt++) {
        #pragma unroll
        for (int nt = 0; nt < 8; nt++) {
            const int r0 = row0 + 32*wr + 16*mt + (lane >> 2);
            const int cc = col0 + 64*wc + 8*nt + 2*(lane & 3);
            float2 bv = make_float2(0.f, 0.f);
            if (HB) bv = *(const float2*)&bias[cc];
            #pragma unroll
            for (int hh = 0; hh < 2; hh++) {
                const int r = r0 + hh * 8;
                float v0 = acc[mt][nt][2*hh]     * scale;
                float v1 = acc[mt][nt][2*hh + 1] * scale;
                if (HB) { v0 += bv.x; v1 += bv.y; }
                if (HR) {
                    float2 rv = *(const float2*)&R[(size_t)r * ldc + cc];
                    v0 += rv.x; v1 += rv.y;
                }
                if (ACT == 1) { v0 = gelu_exact(v0); v1 = gelu_exact(v1); }
                if (OUT == 0) {
                    *(float2*)&Cp[(size_t)r * ldc + cc] = make_float2(v0, v1);
                } else {
                    __half h0 = __float2half_rn(v0);
                    __half h1 = __float2half_rn(v1);
                    *(__half2*)&ChH[(size_t)r * ldc + cc] = __halves2half2(h0, h1);
                    *(__half2*)&ClH[(size_t)r * ldc + cc] =
                        __halves2half2(__float2half_rn(v0 - __half2float(h0)),
                                       __float2half_rn(v1 - __half2float(h1)));
                }
            }
        }
    }
}

// ---------------- converters ----------------
__global__ __launch_bounds__(256) void split_hf_kernel(const float4* __restrict__ src,
                                                       uint2* __restrict__ h,
                                                       uint2* __restrict__ l, int n4)
{
    int i = blockIdx.x * 256 + threadIdx.x;
    if (i < n4) { uint2 H, L; split4h(src[i], H, L); h[i] = H; l[i] = L; }
}
__global__ __launch_bounds__(256) void conv_hf_kernel(const float4* __restrict__ src,
                                                      uint2* __restrict__ h, int n4)
{
    int i = blockIdx.x * 256 + threadIdx.x;
    if (i < n4) h[i] = conv4h(src[i]);
}

// ---------------- V transpose: fp16 pair qkv -> fp16 Vt ----------------
__global__ __launch_bounds__(256) void transpose_v(const __half* __restrict__ qh,
                                                   const __half* __restrict__ ql,
                                                   __half* __restrict__ vt)
{
    __shared__ float t[32][33];
    const int bh = blockIdx.z, b = bh / Hc, h = bh % Hc;
    const int q0 = blockIdx.x * 32, d0 = blockIdx.y * 32;
    const int tx = threadIdx.x & 31, ty = threadIdx.x >> 5;
    const size_t so = (size_t)b * Lc * D3c + 2 * Dc + h * HDc;
    #pragma unroll
    for (int i = ty; i < 32; i += 8) {
        size_t idx = so + (size_t)(q0 + i) * D3c + d0 + tx;
        t[i][tx] = __half2float(qh[idx]) + __half2float(ql[idx]);
    }
    __syncthreads();
    const size_t dofs = (size_t)bh * HDc * Lc;
    #pragma unroll
    for (int i = ty; i < 32; i += 8)
        vt[dofs + (size_t)(d0 + i) * Lc + q0 + tx] = __float2half_rn(t[tx][i]);
}

// ---------------- layernorm: fp32 in; OMODE 0 = fp32 out, 1 = fp16 pair ----------------
template<int OMODE>
__global__ __launch_bounds__(256)
void layernorm_kernel(const float* __restrict__ x, const float* __restrict__ g,
                      const float* __restrict__ b,
                      float* __restrict__ outF, __half* __restrict__ outH, __half* __restrict__ outL)
{
    const int row = blockIdx.x;
    const int t   = threadIdx.x;
    const float4 v = ((const float4*)(x + (size_t)row * Dc))[t];

    float s1 = v.x + v.y + v.z + v.w;
    float s2 = v.x*v.x + v.y*v.y + v.z*v.z + v.w*v.w;

    __shared__ float sh1[8], sh2[8];
    #pragma unroll
    for (int o = 16; o > 0; o >>= 1) {
        s1 += __shfl_down_sync(0xffffffffu, s1, o);
        s2 += __shfl_down_sync(0xffffffffu, s2, o);
    }
    if ((t & 31) == 0) { sh1[t >> 5] = s1; sh2[t >> 5] = s2; }
    __syncthreads();
    if (t < 8) {
        s1 = sh1[t]; s2 = sh2[t];
        #pragma unroll
        for (int o = 4; o > 0; o >>= 1) {
            s1 += __shfl_down_sync(0xffu, s1, o);
            s2 += __shfl_down_sync(0xffu, s2, o);
        }
        if (t == 0) { sh1[0] = s1; sh2[0] = s2; }
    }
    __syncthreads();

    const float mean = sh1[0] * (1.0f / Dc);
    const float var  = sh2[0] * (1.0f / Dc) - mean * mean;
    const float rstd = rsqrtf(var + 1e-5f);

    const float4 gv = ((const float4*)g)[t];
    const float4 bv = ((const float4*)b)[t];
    float4 r;
    r.x = (v.x - mean) * rstd * gv.x + bv.x;
    r.y = (v.y - mean) * rstd * gv.y + bv.y;
    r.z = (v.z - mean) * rstd * gv.z + bv.z;
    r.w = (v.w - mean) * rstd * gv.w + bv.w;
    if (OMODE == 1) {
        uint2 H, L;
        split4h(r, H, L);
        ((uint2*)(outH + (size_t)row * Dc))[t] = H;
        ((uint2*)(outL + (size_t)row * Dc))[t] = L;
    } else {
        ((float4*)(outF + (size_t)row * Dc))[t] = r;
    }
}

// ---------------- softmax: fp32 in, fp16 (hi only) out ----------------
__global__ __launch_bounds__(256)
void softmax_kernel(const float* __restrict__ s, __half* __restrict__ pp)
{
    const size_t row = blockIdx.x;
    const float4* p = (const float4*)(s + row * (size_t)Lc);
    const int t = threadIdx.x;

    float4 a = p[t];
    float4 c = p[t + 256];

    float mx = fmaxf(fmaxf(fmaxf(a.x, a.y), fmaxf(a.z, a.w)),
                     fmaxf(fmaxf(c.x, c.y), fmaxf(c.z, c.w)));

    __shared__ float sh[8];
    #pragma unroll
    for (int o = 16; o > 0; o >>= 1) mx = fmaxf(mx, __shfl_down_sync(0xffffffffu, mx, o));
    if ((t & 31) == 0) sh[t >> 5] = mx;
    __syncthreads();
    if (t < 8) {
        mx = sh[t];
        #pragma unroll
        for (int o = 4; o > 0; o >>= 1) mx = fmaxf(mx, __shfl_down_sync(0xffu, mx, o));
        if (t == 0) sh[0] = mx;
    }
    __syncthreads();
    mx = sh[0];
    __syncthreads();

    a.x = expf(a.x - mx); a.y = expf(a.y - mx); a.z = expf(a.z - mx); a.w = expf(a.w - mx);
    c.x = expf(c.x - mx); c.y = expf(c.y - mx); c.z = expf(c.z - mx); c.w = expf(c.w - mx);

    float sm = a.x + a.y + a.z + a.w + c.x + c.y + c.z + c.w;
    #pragma unroll
    for (int o = 16; o > 0; o >>= 1) sm += __shfl_down_sync(0xffffffffu, sm, o);
    if ((t & 31) == 0) sh[t >> 5] = sm;
    __syncthreads();
    if (t < 8) {
        sm = sh[t];
        #pragma unroll
        for (int o = 4; o > 0; o >>= 1) sm += __shfl_down_sync(0xffu, sm, o);
        if (t == 0) sh[0] = sm;
    }
    __syncthreads();
    const float inv = 1.0f / sh[0];

    a.x *= inv; a.y *= inv; a.z *= inv; a.w *= inv;
    c.x *= inv; c.y *= inv; c.z *= inv; c.w *= inv;

    ((uint2*)(pp + row * (size_t)Lc))[t]       = conv4h(a);
    ((uint2*)(pp + row * (size_t)Lc))[t + 256] = conv4h(c);
}

// ---------------- host side ----------------
static void do_split_hf(const float* src, __half* h, __half* l, size_t n) {
    int n4 = (int)(n / 4);
    split_hf_kernel<<<(n4 + 255) / 256, 256>>>((const float4*)src, (uint2*)h, (uint2*)l, n4);
}
static void do_conv_hf(const float* src, __half* h, size_t n) {
    int n4 = (int)(n / 4);
    conv_hf_kernel<<<(n4 + 255) / 256, 256>>>((const float4*)src, (uint2*)h, n4);
}

extern "C" void kernel_launch(void* const* d_in, const int* in_sizes, int n_in,
                              void* d_out, int out_size)
{
    const float* x    = (const float*)d_in[0];
    const float* w3d  = (const float*)d_in[1];
    const float* b3d  = (const float*)d_in[2];
    const float* ln1g = (const float*)d_in[3];
    const float* ln1b = (const float*)d_in[4];
    const float* wqkv = (const float*)d_in[5];
    const float* bqkv = (const float*)d_in[6];
    const float* wprj = (const float*)d_in[7];
    const float* bprj = (const float*)d_in[8];
    const float* ln2g = (const float*)d_in[9];
    const float* ln2b = (const float*)d_in[10];
    const float* w1   = (const float*)d_in[11];
    const float* b1   = (const float*)d_in[12];
    const float* w2   = (const float*)d_in[13];
    const float* b2   = (const float*)d_in[14];
    const float* lnfg = (const float*)d_in[15];
    const float* lnfb = (const float*)d_in[16];
    float* out = (float*)d_out;

    float *h, *sc;
    __half *xh,*xl,*w3,*hnh,*hnl,*wq,*wp,*w1p,*w2p,*qvh,*qvl,*vt,*pp,*oh,*ol,*fh,*fl;
    cudaGetSymbolAddress((void**)&h,   g_h);
    cudaGetSymbolAddress((void**)&sc,  g_sc);
    cudaGetSymbolAddress((void**)&xh,  g_xh);  cudaGetSymbolAddress((void**)&xl,  g_xl);
    cudaGetSymbolAddress((void**)&w3,  g_w3);
    cudaGetSymbolAddress((void**)&hnh, g_hnh); cudaGetSymbolAddress((void**)&hnl, g_hnl);
    cudaGetSymbolAddress((void**)&wq,  g_wq);
    cudaGetSymbolAddress((void**)&wp,  g_wp);
    cudaGetSymbolAddress((void**)&w1p, g_w1);
    cudaGetSymbolAddress((void**)&w2p, g_w2);
    cudaGetSymbolAddress((void**)&qvh, g_qvh); cudaGetSymbolAddress((void**)&qvl, g_qvl);
    cudaGetSymbolAddress((void**)&vt,  g_vt);
    cudaGetSymbolAddress((void**)&pp,  g_p);
    cudaGetSymbolAddress((void**)&oh,  g_oh);  cudaGetSymbolAddress((void**)&ol,  g_ol);
    cudaGetSymbolAddress((void**)&fh,  g_fh);  cudaGetSymbolAddress((void**)&fl,  g_fl);

    const int SM2 = 2 * 3 * TILE_B;   // TERMS=2 smem (110592)
    const int SM1 = 2 * 2 * TILE_B;   // TERMS=1 smem (73728)
    cudaFuncSetAttribute(tc_ghf<2,true,false,0,0>,  cudaFuncAttributeMaxDynamicSharedMemorySize, SM2);
    cudaFuncSetAttribute(tc_ghf<2,true,false,0,1>,  cudaFuncAttributeMaxDynamicSharedMemorySize, SM2);
    cudaFuncSetAttribute(tc_ghf<2,false,false,0,0>, cudaFuncAttributeMaxDynamicSharedMemorySize, SM2);
    cudaFuncSetAttribute(tc_ghf<1,false,false,0,1>, cudaFuncAttributeMaxDynamicSharedMemorySize, SM1);
    cudaFuncSetAttribute(tc_ghf<2,true,true,0,0>,   cudaFuncAttributeMaxDynamicSharedMemorySize, SM2);
    cudaFuncSetAttribute(tc_ghf<2,true,false,1,1>,  cudaFuncAttributeMaxDynamicSharedMemorySize, SM2);

    const dim3 blk(256);

    // one-time conversions
    do_split_hf(x,  xh, xl, (size_t)Mc * D3c);
    do_conv_hf(w3d, w3, (size_t)Dc * D3c);

    // ---- embed (fp16 2-term): h = x @ w3d^T + b3d ----
    tc_ghf<2,true,false,0,0><<<dim3(Dc/128, Mc/128, 1), blk, SM2>>>(
        xh, xl, D3c, w3, D3c, b3d, nullptr,
        h, nullptr, nullptr, Dc, D3c, 1.0f, 0,0,0,0,0,0, 1);

    for (int i = 0; i < NLc; i++) {
        do_conv_hf(wqkv + (size_t)i*D3c*Dc, wq, (size_t)D3c*Dc);

        layernorm_kernel<1><<<Mc, blk>>>(h, ln1g + (size_t)i*Dc, ln1b + (size_t)i*Dc,
                                         nullptr, hnh, hnl);

        // qkv = hn @ wqkv^T + bqkv -> fp16 pair
        tc_ghf<2,true,false,0,1><<<dim3(D3c/128, Mc/128, 1), blk, SM2>>>(
            hnh, hnl, Dc, wq, Dc, bqkv + (size_t)i*D3c, nullptr,
            nullptr, qvh, qvl, D3c, Dc, 1.0f, 0,0,0,0,0,0, 1);

        transpose_v<<<dim3(Lc/32, HDc/32, Bc*Hc), blk>>>(qvh, qvl, vt);

        // scores (fp16 2-term) = scale * Q @ K^T ; K hi plane only
        tc_ghf<2,false,false,0,0><<<dim3(Lc/128, Lc/128, Bc*Hc), blk, SM2>>>(
            qvh, qvl, D3c,
            qvh + Dc, D3c,
            nullptr, nullptr,
            sc, nullptr, nullptr, Lc, HDc, 0.0625f,
            (long)Lc*D3c, (long)HDc,
            (long)Lc*D3c, (long)HDc,
            (long)Hc*Lc*Lc, (long)Lc*Lc,
            Hc);

        softmax_kernel<<<Bc*Hc*Lc, blk>>>(sc, pp);

        // o = P @ Vt^T (fp16 1-term) -> fp16 pair
        tc_ghf<1,false,false,0,1><<<dim3(HDc/128, Lc/128, Bc*Hc), blk, SM1>>>(
            pp, nullptr, Lc,
            vt, Lc,
            nullptr, nullptr,
            nullptr, oh, ol, Dc, Lc, 1.0f,
            (long)Hc*Lc*Lc, (long)Lc*Lc,
            (long)Hc*HDc*Lc, (long)HDc*Lc,
            (long)Lc*Dc, (long)HDc,
            Hc);

        do_conv_hf(wprj + (size_t)i*Dc*Dc, wp, (size_t)Dc*Dc);

        // h = h + o @ wproj^T + bproj
        tc_ghf<2,true,true,0,0><<<dim3(Dc/128, Mc/128, 1), blk, SM2>>>(
            oh, ol, Dc, wp, Dc, bprj + (size_t)i*Dc, h,
            h, nullptr, nullptr, Dc, Dc, 1.0f, 0,0,0,0,0,0, 1);

        layernorm_kernel<1><<<Mc, blk>>>(h, ln2g + (size_t)i*Dc, ln2b + (size_t)i*Dc,
                                         nullptr, hnh, hnl);

        do_conv_hf(w1 + (size_t)i*FFc*Dc, w1p, (size_t)FFc*Dc);

        // f = gelu(hn @ w1^T + b1) -> fp16 pair
        tc_ghf<2,true,false,1,1><<<dim3(FFc/128, Mc/128, 1), blk, SM2>>>(
            hnh, hnl, Dc, w1p, Dc, b1 + (size_t)i*FFc, nullptr,
            nullptr, fh, fl, FFc, Dc, 1.0f, 0,0,0,0,0,0, 1);

        do_conv_hf(w2 + (size_t)i*Dc*FFc, w2p, (size_t)Dc*FFc);

        // h = h + f @ w2^T + b2
        tc_ghf<2,true,true,0,0><<<dim3(Dc/128, Mc/128, 1), blk, SM2>>>(
            fh, fl, FFc, w2p, FFc, b2 + (size_t)i*Dc, h,
            h, nullptr, nullptr, Dc, FFc, 1.0f, 0,0,0,0,0,0, 1);
    }

    layernorm_kernel<0><<<Mc, blk>>>(h, lnfg, lnfb, out, nullptr, nullptr);
}

// round 8
// speedup vs baseline: 2.0686x; 1.2186x over previous
#include <cuda_runtime.h>
#include <cuda_fp16.h>
#include <math.h>
#include <stdint.h>

// ---------------- problem constants ----------------
#define Bc   4
#define Lc   2048
#define Dc   1024
#define Hc   4
#define HDc  256
#define NLc  2
#define FFc  4096
#define Mc   (Bc*Lc)     // 8192 tokens
#define D3c  (3*Dc)      // 3072

// ---------------- device scratch (static; no allocations) ----------------
__device__ float g_h  [(size_t)Mc*Dc];            // residual fp32
__device__ float g_sc [(size_t)Bc*Hc*Lc*Lc];      // scores fp32
// fp16 planes
__device__ __align__(16) __half g_xh [(size_t)Mc*D3c],  g_xl [(size_t)Mc*D3c];
__device__ __align__(16) __half g_w3 [(size_t)Dc*D3c];
__device__ __align__(16) __half g_hnh[(size_t)Mc*Dc],   g_hnl[(size_t)Mc*Dc];
__device__ __align__(16) __half g_wq [(size_t)D3c*Dc];
__device__ __align__(16) __half g_wp [(size_t)Dc*Dc];
__device__ __align__(16) __half g_w1 [(size_t)FFc*Dc];
__device__ __align__(16) __half g_w2 [(size_t)Dc*FFc];
__device__ __align__(16) __half g_qvh[(size_t)Mc*D3c],  g_qvl[(size_t)Mc*D3c];
__device__ __align__(16) __half g_vt [(size_t)Bc*Hc*HDc*Lc];
__device__ __align__(16) __half g_p  [(size_t)Bc*Hc*Lc*Lc];
__device__ __align__(16) __half g_oh [(size_t)Mc*Dc],   g_ol [(size_t)Mc*Dc];
__device__ __align__(16) __half g_fh [(size_t)Mc*FFc];

// ---------------- helpers ----------------
__device__ __forceinline__ uint32_t smem_u32(const void* p) {
    uint32_t a;
    asm("{ .reg .u64 t; cvta.to.shared.u64 t, %1; cvt.u32.u64 %0, t; }" : "=r"(a) : "l"(p));
    return a;
}
__device__ __forceinline__ void ldsm4(uint32_t* r, uint32_t addr) {
    asm volatile("ldmatrix.sync.aligned.m8n8.x4.shared.b16 {%0,%1,%2,%3}, [%4];"
        : "=r"(r[0]), "=r"(r[1]), "=r"(r[2]), "=r"(r[3]) : "r"(addr));
}
__device__ __forceinline__ void mma_hf(float* d, const uint32_t* a, const uint32_t* b) {
    asm volatile(
        "mma.sync.aligned.m16n8k16.row.col.f32.f16.f16.f32 "
        "{%0,%1,%2,%3}, {%4,%5,%6,%7}, {%8,%9}, {%0,%1,%2,%3};"
        : "+f"(d[0]), "+f"(d[1]), "+f"(d[2]), "+f"(d[3])
        : "r"(a[0]), "r"(a[1]), "r"(a[2]), "r"(a[3]), "r"(b[0]), "r"(b[1]));
}
__device__ __forceinline__ float gelu_exact(float x) {
    return 0.5f * x * (1.0f + erff(x * 0.70710678118654752440f));
}
// split fp32x4 -> hi/lo fp16x4 packed as uint2
__device__ __forceinline__ void split4h(float4 v, uint2& Hh, uint2& Ll) {
    __half hx = __float2half_rn(v.x);
    __half hy = __float2half_rn(v.y);
    __half hz = __float2half_rn(v.z);
    __half hw = __float2half_rn(v.w);
    union { __half2 h2[2]; uint2 u; } H, L;
    H.h2[0] = __halves2half2(hx, hy);
    H.h2[1] = __halves2half2(hz, hw);
    L.h2[0] = __halves2half2(__float2half_rn(v.x - __half2float(hx)),
                             __float2half_rn(v.y - __half2float(hy)));
    L.h2[1] = __halves2half2(__float2half_rn(v.z - __half2float(hz)),
                             __float2half_rn(v.w - __half2float(hw)));
    Hh = H.u; Ll = L.u;
}
__device__ __forceinline__ uint2 conv4h(float4 v) {
    union { __half2 h2[2]; uint2 u; } H;
    H.h2[0] = __halves2half2(__float2half_rn(v.x), __float2half_rn(v.y));
    H.h2[1] = __halves2half2(__float2half_rn(v.z), __float2half_rn(v.w));
    return H.u;
}

// ================= fp16 GEMM, TERMS in {1,2} =================
// C[M,N] = act(scale * (Ah [+Al]) @ Bh^T + bias + resid)
// OUT: 0 = fp32 C; 1 = fp16 pair; 2 = fp16 hi only
#define KC     64
#define SKB    72
#define TILE_B (128*SKB*2)          // 18432 B

template<int TERMS, bool HB, bool HR, int ACT, int OUT>
__global__ __launch_bounds__(256, 1) void tc_ghf(
    const __half* __restrict__ Ah, const __half* __restrict__ Al, int lda,
    const __half* __restrict__ Bh, int ldb,
    const float* __restrict__ bias,
    const float* __restrict__ resid,
    float* __restrict__ C, __half* __restrict__ Cho, __half* __restrict__ Clo, int ldc,
    int K, float scale,
    long aso, long asi, long bso, long bsi, long cso, long csi, int zinner)
{
    constexpr uint32_t BOFF = (uint32_t)TERMS * TILE_B;       // B tile smem offset
    constexpr uint32_t STG  = (uint32_t)(TERMS + 1) * TILE_B; // stage bytes

    const int z  = blockIdx.z;
    const int zo = z / zinner;
    const int zi = z - zo * zinner;
    const size_t aofs = (size_t)zo * aso + (size_t)zi * asi;
    const size_t bofs = (size_t)zo * bso + (size_t)zi * bsi;
    const size_t cofs = (size_t)zo * cso + (size_t)zi * csi;
    Ah += aofs;
    if (TERMS == 2) Al += aofs;
    Bh += bofs;

    extern __shared__ char dsm[];
    const uint32_t sb32 = smem_u32(dsm);

    const int tid  = threadIdx.x;
    const int wid  = tid >> 5;
    const int lane = tid & 31;
    const int wr   = wid & 3;
    const int wc   = wid >> 2;
    const int row0 = blockIdx.y * 128;
    const int col0 = blockIdx.x * 128;

    const int lr0 = tid >> 3;
    const int lc8 = (tid & 7) << 3;

    const __half* A0h = Ah + (size_t)row0 * lda;
    const __half* A0l = (TERMS == 2) ? Al + (size_t)row0 * lda : nullptr;
    const __half* B0h = Bh + (size_t)col0 * ldb;

    float acc[2][8][4];
    #pragma unroll
    for (int mt = 0; mt < 2; mt++)
        #pragma unroll
        for (int nt = 0; nt < 8; nt++)
            #pragma unroll
            for (int j = 0; j < 4; j++) acc[mt][nt][j] = 0.0f;

    const int nc = K / KC;

    // ---- prologue: stage 0 ----
    #pragma unroll
    for (int it = 0; it < 4; it++) {
        int r = lr0 + it * 32;
        uint32_t doff = (uint32_t)(r * SKB + lc8) * 2;
        *(uint4*)(dsm + 0*TILE_B + doff) = *(const uint4*)(A0h + (size_t)r * lda + lc8);
        if (TERMS == 2)
            *(uint4*)(dsm + 1*TILE_B + doff) = *(const uint4*)(A0l + (size_t)r * lda + lc8);
        *(uint4*)(dsm + BOFF + doff) = *(const uint4*)(B0h + (size_t)r * ldb + lc8);
    }
    __syncthreads();

    const int ro = lane & 15;
    const int co = (lane >> 4) << 3;

    for (int c = 0; c < nc; c++) {
        const int s = c & 1;
        const uint32_t sOff = sb32 + (uint32_t)s * STG;
        char* dst = dsm + (size_t)(s ^ 1) * STG;
        const bool pf = (c + 1 < nc);
        const int kn = (c + 1) * KC;

        uint4 ra[8];
        if (pf) {
            #pragma unroll
            for (int it = 0; it < 4; it++) {
                int r = lr0 + it * 32;
                ra[it] = *(const uint4*)(A0h + (size_t)r * lda + kn + lc8);
                if (TERMS == 2)
                    ra[it + 4] = *(const uint4*)(A0l + (size_t)r * lda + kn + lc8);
            }
        }

        #pragma unroll
        for (int ks = 0; ks < 2; ks++) {
            const int k0 = ks * 16;
            uint32_t ah[2][4], al[2][4];
            #pragma unroll
            for (int mt = 0; mt < 2; mt++) {
                uint32_t off = (uint32_t)((32*wr + 16*mt + ro) * SKB + k0 + co) * 2;
                ldsm4(ah[mt], sOff + 0*TILE_B + off);
                if (TERMS == 2) ldsm4(al[mt], sOff + 1*TILE_B + off);
            }
            uint32_t bh[8][2];
            #pragma unroll
            for (int p = 0; p < 4; p++) {
                uint32_t off = (uint32_t)((64*wc + 16*p + ro) * SKB + k0 + co) * 2;
                uint32_t r[4];
                ldsm4(r, sOff + BOFF + off);
                bh[2*p][0] = r[0];   bh[2*p][1] = r[2];
                bh[2*p+1][0] = r[1]; bh[2*p+1][1] = r[3];
            }
            #pragma unroll
            for (int mt = 0; mt < 2; mt++)
                #pragma unroll
                for (int nt = 0; nt < 8; nt++) {
                    mma_hf(acc[mt][nt], ah[mt], bh[nt]);
                    if (TERMS == 2) mma_hf(acc[mt][nt], al[mt], bh[nt]);
                }
        }

        if (pf) {
            #pragma unroll
            for (int it = 0; it < 4; it++) {
                int r = lr0 + it * 32;
                uint32_t doff = (uint32_t)(r * SKB + lc8) * 2;
                *(uint4*)(dst + 0*TILE_B + doff) = ra[it];
                if (TERMS == 2)
                    *(uint4*)(dst + 1*TILE_B + doff) = ra[it + 4];
            }
            #pragma unroll
            for (int it = 0; it < 4; it++) {
                int r = lr0 + it * 32;
                ra[it] = *(const uint4*)(B0h + (size_t)r * ldb + kn + lc8);
            }
        }

        #pragma unroll
        for (int ks = 2; ks < 4; ks++) {
            const int k0 = ks * 16;
            uint32_t ah[2][4], al[2][4];
            #pragma unroll
            for (int mt = 0; mt < 2; mt++) {
                uint32_t off = (uint32_t)((32*wr + 16*mt + ro) * SKB + k0 + co) * 2;
                ldsm4(ah[mt], sOff + 0*TILE_B + off);
                if (TERMS == 2) ldsm4(al[mt], sOff + 1*TILE_B + off);
            }
            uint32_t bh[8][2];
            #pragma unroll
            for (int p = 0; p < 4; p++) {
                uint32_t off = (uint32_t)((64*wc + 16*p + ro) * SKB + k0 + co) * 2;
                uint32_t r[4];
                ldsm4(r, sOff + BOFF + off);
                bh[2*p][0] = r[0];   bh[2*p][1] = r[2];
                bh[2*p+1][0] = r[1]; bh[2*p+1][1] = r[3];
            }
            #pragma unroll
            for (int mt = 0; mt < 2; mt++)
                #pragma unroll
                for (int nt = 0; nt < 8; nt++) {
                    mma_hf(acc[mt][nt], ah[mt], bh[nt]);
                    if (TERMS == 2) mma_hf(acc[mt][nt], al[mt], bh[nt]);
                }
        }

        if (pf) {
            #pragma unroll
            for (int it = 0; it < 4; it++) {
                int r = lr0 + it * 32;
                uint32_t doff = (uint32_t)(r * SKB + lc8) * 2;
                *(uint4*)(dst + BOFF + doff) = ra[it];
            }
        }
        __syncthreads();
    }

    // ---- epilogue ----
    float*  Cp  = (OUT == 0) ? C + cofs : nullptr;
    __half* ChH = (OUT != 0) ? Cho + cofs : nullptr;
    __half* ClH = (OUT == 1) ? Clo + cofs : nullptr;
    const float* R = HR ? resid : nullptr;

    #pragma unroll
    for (int mt = 0; mt < 2; mt++) {
        #pragma unroll
        for (int nt = 0; nt < 8; nt++) {
            const int r0 = row0 + 32*wr + 16*mt + (lane >> 2);
            const int cc = col0 + 64*wc + 8*nt + 2*(lane & 3);
            float2 bv = make_float2(0.f, 0.f);
            if (HB) bv = *(const float2*)&bias[cc];
            #pragma unroll
            for (int hh = 0; hh < 2; hh++) {
                const int r = r0 + hh * 8;
                float v0 = acc[mt][nt][2*hh]     * scale;
                float v1 = acc[mt][nt][2*hh + 1] * scale;
                if (HB) { v0 += bv.x; v1 += bv.y; }
                if (HR) {
                    float2 rv = *(const float2*)&R[(size_t)r * ldc + cc];
                    v0 += rv.x; v1 += rv.y;
                }
                if (ACT == 1) { v0 = gelu_exact(v0); v1 = gelu_exact(v1); }
                if (OUT == 0) {
                    *(float2*)&Cp[(size_t)r * ldc + cc] = make_float2(v0, v1);
                } else {
                    __half h0 = __float2half_rn(v0);
                    __half h1 = __float2half_rn(v1);
                    *(__half2*)&ChH[(size_t)r * ldc + cc] = __halves2half2(h0, h1);
                    if (OUT == 1) {
                        *(__half2*)&ClH[(size_t)r * ldc + cc] =
                            __halves2half2(__float2half_rn(v0 - __half2float(h0)),
                                           __float2half_rn(v1 - __half2float(h1)));
                    }
                }
            }
        }
    }
}

// ---------------- converters ----------------
__global__ __launch_bounds__(256) void split_hf_kernel(const float4* __restrict__ src,
                                                       uint2* __restrict__ h,
                                                       uint2* __restrict__ l, int n4)
{
    int i = blockIdx.x * 256 + threadIdx.x;
    if (i < n4) { uint2 H, L; split4h(src[i], H, L); h[i] = H; l[i] = L; }
}
__global__ __launch_bounds__(256) void conv_hf_kernel(const float4* __restrict__ src,
                                                      uint2* __restrict__ h, int n4)
{
    int i = blockIdx.x * 256 + threadIdx.x;
    if (i < n4) h[i] = conv4h(src[i]);
}

// ---------------- V transpose: fp16 pair qkv -> fp16 Vt ----------------
__global__ __launch_bounds__(256) void transpose_v(const __half* __restrict__ qh,
                                                   const __half* __restrict__ ql,
                                                   __half* __restrict__ vt)
{
    __shared__ float t[32][33];
    const int bh = blockIdx.z, b = bh / Hc, h = bh % Hc;
    const int q0 = blockIdx.x * 32, d0 = blockIdx.y * 32;
    const int tx = threadIdx.x & 31, ty = threadIdx.x >> 5;
    const size_t so = (size_t)b * Lc * D3c + 2 * Dc + h * HDc;
    #pragma unroll
    for (int i = ty; i < 32; i += 8) {
        size_t idx = so + (size_t)(q0 + i) * D3c + d0 + tx;
        t[i][tx] = __half2float(qh[idx]) + __half2float(ql[idx]);
    }
    __syncthreads();
    const size_t dofs = (size_t)bh * HDc * Lc;
    #pragma unroll
    for (int i = ty; i < 32; i += 8)
        vt[dofs + (size_t)(d0 + i) * Lc + q0 + tx] = __float2half_rn(t[tx][i]);
}

// ---------------- layernorm: fp32 in; OMODE 0 = fp32 out, 1 = fp16 pair ----------------
template<int OMODE>
__global__ __launch_bounds__(256)
void layernorm_kernel(const float* __restrict__ x, const float* __restrict__ g,
                      const float* __restrict__ b,
                      float* __restrict__ outF, __half* __restrict__ outH, __half* __restrict__ outL)
{
    const int row = blockIdx.x;
    const int t   = threadIdx.x;
    const float4 v = ((const float4*)(x + (size_t)row * Dc))[t];

    float s1 = v.x + v.y + v.z + v.w;
    float s2 = v.x*v.x + v.y*v.y + v.z*v.z + v.w*v.w;

    __shared__ float sh1[8], sh2[8];
    #pragma unroll
    for (int o = 16; o > 0; o >>= 1) {
        s1 += __shfl_down_sync(0xffffffffu, s1, o);
        s2 += __shfl_down_sync(0xffffffffu, s2, o);
    }
    if ((t & 31) == 0) { sh1[t >> 5] = s1; sh2[t >> 5] = s2; }
    __syncthreads();
    if (t < 8) {
        s1 = sh1[t]; s2 = sh2[t];
        #pragma unroll
        for (int o = 4; o > 0; o >>= 1) {
            s1 += __shfl_down_sync(0xffu, s1, o);
            s2 += __shfl_down_sync(0xffu, s2, o);
        }
        if (t == 0) { sh1[0] = s1; sh2[0] = s2; }
    }
    __syncthreads();

    const float mean = sh1[0] * (1.0f / Dc);
    const float var  = sh2[0] * (1.0f / Dc) - mean * mean;
    const float rstd = rsqrtf(var + 1e-5f);

    const float4 gv = ((const float4*)g)[t];
    const float4 bv = ((const float4*)b)[t];
    float4 r;
    r.x = (v.x - mean) * rstd * gv.x + bv.x;
    r.y = (v.y - mean) * rstd * gv.y + bv.y;
    r.z = (v.z - mean) * rstd * gv.z + bv.z;
    r.w = (v.w - mean) * rstd * gv.w + bv.w;
    if (OMODE == 1) {
        uint2 H, L;
        split4h(r, H, L);
        ((uint2*)(outH + (size_t)row * Dc))[t] = H;
        ((uint2*)(outL + (size_t)row * Dc))[t] = L;
    } else {
        ((float4*)(outF + (size_t)row * Dc))[t] = r;
    }
}

// ---------------- softmax: fp32 in, fp16 (hi only) out ----------------
__global__ __launch_bounds__(256)
void softmax_kernel(const float* __restrict__ s, __half* __restrict__ pp)
{
    const size_t row = blockIdx.x;
    const float4* p = (const float4*)(s + row * (size_t)Lc);
    const int t = threadIdx.x;

    float4 a = p[t];
    float4 c = p[t + 256];

    float mx = fmaxf(fmaxf(fmaxf(a.x, a.y), fmaxf(a.z, a.w)),
                     fmaxf(fmaxf(c.x, c.y), fmaxf(c.z, c.w)));

    __shared__ float sh[8];
    #pragma unroll
    for (int o = 16; o > 0; o >>= 1) mx = fmaxf(mx, __shfl_down_sync(0xffffffffu, mx, o));
    if ((t & 31) == 0) sh[t >> 5] = mx;
    __syncthreads();
    if (t < 8) {
        mx = sh[t];
        #pragma unroll
        for (int o = 4; o > 0; o >>= 1) mx = fmaxf(mx, __shfl_down_sync(0xffu, mx, o));
        if (t == 0) sh[0] = mx;
    }
    __syncthreads();
    mx = sh[0];
    __syncthreads();

    a.x = expf(a.x - mx); a.y = expf(a.y - mx); a.z = expf(a.z - mx); a.w = expf(a.w - mx);
    c.x = expf(c.x - mx); c.y = expf(c.y - mx); c.z = expf(c.z - mx); c.w = expf(c.w - mx);

    float sm = a.x + a.y + a.z + a.w + c.x + c.y + c.z + c.w;
    #pragma unroll
    for (int o = 16; o > 0; o >>= 1) sm += __shfl_down_sync(0xffffffffu, sm, o);
    if ((t & 31) == 0) sh[t >> 5] = sm;
    __syncthreads();
    if (t < 8) {
        sm = sh[t];
        #pragma unroll
        for (int o = 4; o > 0; o >>= 1) sm += __shfl_down_sync(0xffu, sm, o);
        if (t == 0) sh[0] = sm;
    }
    __syncthreads();
    const float inv = 1.0f / sh[0];

    a.x *= inv; a.y *= inv; a.z *= inv; a.w *= inv;
    c.x *= inv; c.y *= inv; c.z *= inv; c.w *= inv;

    ((uint2*)(pp + row * (size_t)Lc))[t]       = conv4h(a);
    ((uint2*)(pp + row * (size_t)Lc))[t + 256] = conv4h(c);
}

// ---------------- host side ----------------
static void do_split_hf(const float* src, __half* h, __half* l, size_t n) {
    int n4 = (int)(n / 4);
    split_hf_kernel<<<(n4 + 255) / 256, 256>>>((const float4*)src, (uint2*)h, (uint2*)l, n4);
}
static void do_conv_hf(const float* src, __half* h, size_t n) {
    int n4 = (int)(n / 4);
    conv_hf_kernel<<<(n4 + 255) / 256, 256>>>((const float4*)src, (uint2*)h, n4);
}

extern "C" void kernel_launch(void* const* d_in, const int* in_sizes, int n_in,
                              void* d_out, int out_size)
{
    const float* x    = (const float*)d_in[0];
    const float* w3d  = (const float*)d_in[1];
    const float* b3d  = (const float*)d_in[2];
    const float* ln1g = (const float*)d_in[3];
    const float* ln1b = (const float*)d_in[4];
    const float* wqkv = (const float*)d_in[5];
    const float* bqkv = (const float*)d_in[6];
    const float* wprj = (const float*)d_in[7];
    const float* bprj = (const float*)d_in[8];
    const float* ln2g = (const float*)d_in[9];
    const float* ln2b = (const float*)d_in[10];
    const float* w1   = (const float*)d_in[11];
    const float* b1   = (const float*)d_in[12];
    const float* w2   = (const float*)d_in[13];
    const float* b2   = (const float*)d_in[14];
    const float* lnfg = (const float*)d_in[15];
    const float* lnfb = (const float*)d_in[16];
    float* out = (float*)d_out;

    float *h, *sc;
    __half *xh,*xl,*w3,*hnh,*hnl,*wq,*wp,*w1p,*w2p,*qvh,*qvl,*vt,*pp,*oh,*ol,*fh;
    cudaGetSymbolAddress((void**)&h,   g_h);
    cudaGetSymbolAddress((void**)&sc,  g_sc);
    cudaGetSymbolAddress((void**)&xh,  g_xh);  cudaGetSymbolAddress((void**)&xl,  g_xl);
    cudaGetSymbolAddress((void**)&w3,  g_w3);
    cudaGetSymbolAddress((void**)&hnh, g_hnh); cudaGetSymbolAddress((void**)&hnl, g_hnl);
    cudaGetSymbolAddress((void**)&wq,  g_wq);
    cudaGetSymbolAddress((void**)&wp,  g_wp);
    cudaGetSymbolAddress((void**)&w1p, g_w1);
    cudaGetSymbolAddress((void**)&w2p, g_w2);
    cudaGetSymbolAddress((void**)&qvh, g_qvh); cudaGetSymbolAddress((void**)&qvl, g_qvl);
    cudaGetSymbolAddress((void**)&vt,  g_vt);
    cudaGetSymbolAddress((void**)&pp,  g_p);
    cudaGetSymbolAddress((void**)&oh,  g_oh);  cudaGetSymbolAddress((void**)&ol,  g_ol);
    cudaGetSymbolAddress((void**)&fh,  g_fh);

    const int SM2 = 2 * 3 * TILE_B;   // TERMS=2 smem (110592)
    const int SM1 = 2 * 2 * TILE_B;   // TERMS=1 smem (73728)
    cudaFuncSetAttribute(tc_ghf<2,true,false,0,0>,  cudaFuncAttributeMaxDynamicSharedMemorySize, SM2);
    cudaFuncSetAttribute(tc_ghf<2,true,false,0,1>,  cudaFuncAttributeMaxDynamicSharedMemorySize, SM2);
    cudaFuncSetAttribute(tc_ghf<2,false,false,0,0>, cudaFuncAttributeMaxDynamicSharedMemorySize, SM2);
    cudaFuncSetAttribute(tc_ghf<1,false,false,0,1>, cudaFuncAttributeMaxDynamicSharedMemorySize, SM1);
    cudaFuncSetAttribute(tc_ghf<2,true,true,0,0>,   cudaFuncAttributeMaxDynamicSharedMemorySize, SM2);
    cudaFuncSetAttribute(tc_ghf<1,true,false,1,2>,  cudaFuncAttributeMaxDynamicSharedMemorySize, SM1);
    cudaFuncSetAttribute(tc_ghf<1,true,true,0,0>,   cudaFuncAttributeMaxDynamicSharedMemorySize, SM1);

    const dim3 blk(256);

    // one-time conversions
    do_split_hf(x,  xh, xl, (size_t)Mc * D3c);
    do_conv_hf(w3d, w3, (size_t)Dc * D3c);

    // ---- embed (fp16 2-term): h = x @ w3d^T + b3d ----
    tc_ghf<2,true,false,0,0><<<dim3(Dc/128, Mc/128, 1), blk, SM2>>>(
        xh, xl, D3c, w3, D3c, b3d, nullptr,
        h, nullptr, nullptr, Dc, D3c, 1.0f, 0,0,0,0,0,0, 1);

    for (int i = 0; i < NLc; i++) {
        do_conv_hf(wqkv + (size_t)i*D3c*Dc, wq, (size_t)D3c*Dc);

        layernorm_kernel<1><<<Mc, blk>>>(h, ln1g + (size_t)i*Dc, ln1b + (size_t)i*Dc,
                                         nullptr, hnh, hnl);

        // qkv = hn @ wqkv^T + bqkv -> fp16 pair
        tc_ghf<2,true,false,0,1><<<dim3(D3c/128, Mc/128, 1), blk, SM2>>>(
            hnh, hnl, Dc, wq, Dc, bqkv + (size_t)i*D3c, nullptr,
            nullptr, qvh, qvl, D3c, Dc, 1.0f, 0,0,0,0,0,0, 1);

        transpose_v<<<dim3(Lc/32, HDc/32, Bc*Hc), blk>>>(qvh, qvl, vt);

        // scores (fp16 2-term) = scale * Q @ K^T ; K hi plane only
        tc_ghf<2,false,false,0,0><<<dim3(Lc/128, Lc/128, Bc*Hc), blk, SM2>>>(
            qvh, qvl, D3c,
            qvh + Dc, D3c,
            nullptr, nullptr,
            sc, nullptr, nullptr, Lc, HDc, 0.0625f,
            (long)Lc*D3c, (long)HDc,
            (long)Lc*D3c, (long)HDc,
            (long)Hc*Lc*Lc, (long)Lc*Lc,
            Hc);

        softmax_kernel<<<Bc*Hc*Lc, blk>>>(sc, pp);

        // o = P @ Vt^T (fp16 1-term) -> fp16 pair
        tc_ghf<1,false,false,0,1><<<dim3(HDc/128, Lc/128, Bc*Hc), blk, SM1>>>(
            pp, nullptr, Lc,
            vt, Lc,
            nullptr, nullptr,
            nullptr, oh, ol, Dc, Lc, 1.0f,
            (long)Hc*Lc*Lc, (long)Lc*Lc,
            (long)Hc*HDc*Lc, (long)HDc*Lc,
            (long)Lc*Dc, (long)HDc,
            Hc);

        do_conv_hf(wprj + (size_t)i*Dc*Dc, wp, (size_t)Dc*Dc);

        // h = h + o @ wproj^T + bproj
        tc_ghf<2,true,true,0,0><<<dim3(Dc/128, Mc/128, 1), blk, SM2>>>(
            oh, ol, Dc, wp, Dc, bprj + (size_t)i*Dc, h,
            h, nullptr, nullptr, Dc, Dc, 1.0f, 0,0,0,0,0,0, 1);

        layernorm_kernel<1><<<Mc, blk>>>(h, ln2g + (size_t)i*Dc, ln2b + (size_t)i*Dc,
                                         nullptr, hnh, hnl);

        do_conv_hf(w1 + (size_t)i*FFc*Dc, w1p, (size_t)FFc*Dc);

        // f = gelu(hn @ w1^T + b1) (fp16 1-term) -> fp16 hi only
        tc_ghf<1,true,false,1,2><<<dim3(FFc/128, Mc/128, 1), blk, SM1>>>(
            hnh, nullptr, Dc, w1p, Dc, b1 + (size_t)i*FFc, nullptr,
            nullptr, fh, nullptr, FFc, Dc, 1.0f, 0,0,0,0,0,0, 1);

        do_conv_hf(w2 + (size_t)i*Dc*FFc, w2p, (size_t)Dc*FFc);

        // h = h + f @ w2^T + b2 (fp16 1-term)
        tc_ghf<1,true,true,0,0><<<dim3(Dc/128, Mc/128, 1), blk, SM1>>>(
            fh, nullptr, FFc, w2p, FFc, b2 + (size_t)i*Dc, h,
            h, nullptr, nullptr, Dc, FFc, 1.0f, 0,0,0,0,0,0, 1);
    }

    layernorm_kernel<0><<<Mc, blk>>>(h, lnfg, lnfb, out, nullptr, nullptr);
}

// round 9
// speedup vs baseline: 2.6577x; 1.2848x over previous
#include <cuda_runtime.h>
#include <cuda_fp16.h>
#include <math.h>
#include <stdint.h>

// ---------------- problem constants ----------------
#define Bc   4
#define Lc   2048
#define Dc   1024
#define Hc   4
#define HDc  256
#define NLc  2
#define FFc  4096
#define Mc   (Bc*Lc)     // 8192 tokens
#define D3c  (3*Dc)      // 3072

// ---------------- device scratch (static; no allocations) ----------------
__device__ float g_h  [(size_t)Mc*Dc];            // residual fp32
__device__ float g_sc [(size_t)Bc*Hc*Lc*Lc];      // scores fp32
// fp16 planes (hi only — all GEMMs are 1-term now)
__device__ __align__(16) __half g_x  [(size_t)Mc*D3c];
__device__ __align__(16) __half g_w3 [(size_t)Dc*D3c];
__device__ __align__(16) __half g_hn [(size_t)Mc*Dc];
__device__ __align__(16) __half g_wq [(size_t)D3c*Dc];
__device__ __align__(16) __half g_wp [(size_t)Dc*Dc];
__device__ __align__(16) __half g_w1 [(size_t)FFc*Dc];
__device__ __align__(16) __half g_w2 [(size_t)Dc*FFc];
__device__ __align__(16) __half g_qv [(size_t)Mc*D3c];
__device__ __align__(16) __half g_vt [(size_t)Bc*Hc*HDc*Lc];
__device__ __align__(16) __half g_p  [(size_t)Bc*Hc*Lc*Lc];
__device__ __align__(16) __half g_o  [(size_t)Mc*Dc];
__device__ __align__(16) __half g_f  [(size_t)Mc*FFc];

// ---------------- helpers ----------------
__device__ __forceinline__ uint32_t smem_u32(const void* p) {
    uint32_t a;
    asm("{ .reg .u64 t; cvta.to.shared.u64 t, %1; cvt.u32.u64 %0, t; }" : "=r"(a) : "l"(p));
    return a;
}
__device__ __forceinline__ void ldsm4(uint32_t* r, uint32_t addr) {
    asm volatile("ldmatrix.sync.aligned.m8n8.x4.shared.b16 {%0,%1,%2,%3}, [%4];"
        : "=r"(r[0]), "=r"(r[1]), "=r"(r[2]), "=r"(r[3]) : "r"(addr));
}
__device__ __forceinline__ void mma_hf(float* d, const uint32_t* a, const uint32_t* b) {
    asm volatile(
        "mma.sync.aligned.m16n8k16.row.col.f32.f16.f16.f32 "
        "{%0,%1,%2,%3}, {%4,%5,%6,%7}, {%8,%9}, {%0,%1,%2,%3};"
        : "+f"(d[0]), "+f"(d[1]), "+f"(d[2]), "+f"(d[3])
        : "r"(a[0]), "r"(a[1]), "r"(a[2]), "r"(a[3]), "r"(b[0]), "r"(b[1]));
}
__device__ __forceinline__ float gelu_exact(float x) {
    return 0.5f * x * (1.0f + erff(x * 0.70710678118654752440f));
}
__device__ __forceinline__ uint2 conv4h(float4 v) {
    union { __half2 h2[2]; uint2 u; } H;
    H.h2[0] = __halves2half2(__float2half_rn(v.x), __float2half_rn(v.y));
    H.h2[1] = __halves2half2(__float2half_rn(v.z), __float2half_rn(v.w));
    return H.u;
}

// ================= fp16 1-term GEMM =================
// C[M,N] = act(scale * A @ B^T + bias + resid)
// OUT: 0 = fp32 C; 2 = fp16
#define KC     64
#define SKB    72
#define TILE_B (128*SKB*2)          // 18432 B
#define STG    (2*TILE_B)           // stage bytes (A + B)
#define SM1    (2*STG)              // 73728 B dynamic smem

template<bool HB, bool HR, int ACT, int OUT>
__global__ __launch_bounds__(256, 1) void tc_ghf(
    const __half* __restrict__ Ah, int lda,
    const __half* __restrict__ Bh, int ldb,
    const float* __restrict__ bias,
    const float* __restrict__ resid,
    float* __restrict__ C, __half* __restrict__ Cho, int ldc,
    int K, float scale,
    long aso, long asi, long bso, long bsi, long cso, long csi, int zinner)
{
    const int z  = blockIdx.z;
    const int zo = z / zinner;
    const int zi = z - zo * zinner;
    const size_t aofs = (size_t)zo * aso + (size_t)zi * asi;
    const size_t bofs = (size_t)zo * bso + (size_t)zi * bsi;
    const size_t cofs = (size_t)zo * cso + (size_t)zi * csi;
    Ah += aofs;
    Bh += bofs;

    extern __shared__ char dsm[];
    const uint32_t sb32 = smem_u32(dsm);

    const int tid  = threadIdx.x;
    const int wid  = tid >> 5;
    const int lane = tid & 31;
    const int wr   = wid & 3;
    const int wc   = wid >> 2;
    const int row0 = blockIdx.y * 128;
    const int col0 = blockIdx.x * 128;

    const int lr0 = tid >> 3;
    const int lc8 = (tid & 7) << 3;

    const __half* A0 = Ah + (size_t)row0 * lda;
    const __half* B0 = Bh + (size_t)col0 * ldb;

    float acc[2][8][4];
    #pragma unroll
    for (int mt = 0; mt < 2; mt++)
        #pragma unroll
        for (int nt = 0; nt < 8; nt++)
            #pragma unroll
            for (int j = 0; j < 4; j++) acc[mt][nt][j] = 0.0f;

    const int nc = K / KC;

    // ---- prologue: stage 0 ----
    #pragma unroll
    for (int it = 0; it < 4; it++) {
        int r = lr0 + it * 32;
        uint32_t doff = (uint32_t)(r * SKB + lc8) * 2;
        *(uint4*)(dsm + 0*TILE_B + doff) = *(const uint4*)(A0 + (size_t)r * lda + lc8);
        *(uint4*)(dsm + 1*TILE_B + doff) = *(const uint4*)(B0 + (size_t)r * ldb + lc8);
    }
    __syncthreads();

    const int ro = lane & 15;
    const int co = (lane >> 4) << 3;

    for (int c = 0; c < nc; c++) {
        const int s = c & 1;
        const uint32_t sOff = sb32 + (uint32_t)s * STG;
        char* dst = dsm + (size_t)(s ^ 1) * STG;
        const bool pf = (c + 1 < nc);
        const int kn = (c + 1) * KC;

        uint4 ra[4];
        if (pf) {
            #pragma unroll
            for (int it = 0; it < 4; it++) {
                int r = lr0 + it * 32;
                ra[it] = *(const uint4*)(A0 + (size_t)r * lda + kn + lc8);
            }
        }

        #pragma unroll
        for (int ks = 0; ks < 2; ks++) {
            const int k0 = ks * 16;
            uint32_t ah[2][4];
            #pragma unroll
            for (int mt = 0; mt < 2; mt++) {
                uint32_t off = (uint32_t)((32*wr + 16*mt + ro) * SKB + k0 + co) * 2;
                ldsm4(ah[mt], sOff + 0*TILE_B + off);
            }
            uint32_t bh[8][2];
            #pragma unroll
            for (int p = 0; p < 4; p++) {
                uint32_t off = (uint32_t)((64*wc + 16*p + ro) * SKB + k0 + co) * 2;
                uint32_t r[4];
                ldsm4(r, sOff + 1*TILE_B + off);
                bh[2*p][0] = r[0];   bh[2*p][1] = r[2];
                bh[2*p+1][0] = r[1]; bh[2*p+1][1] = r[3];
            }
            #pragma unroll
            for (int mt = 0; mt < 2; mt++)
                #pragma unroll
                for (int nt = 0; nt < 8; nt++)
                    mma_hf(acc[mt][nt], ah[mt], bh[nt]);
        }

        if (pf) {
            #pragma unroll
            for (int it = 0; it < 4; it++) {
                int r = lr0 + it * 32;
                uint32_t doff = (uint32_t)(r * SKB + lc8) * 2;
                *(uint4*)(dst + 0*TILE_B + doff) = ra[it];
            }
            #pragma unroll
            for (int it = 0; it < 4; it++) {
                int r = lr0 + it * 32;
                ra[it] = *(const uint4*)(B0 + (size_t)r * ldb + kn + lc8);
            }
        }

        #pragma unroll
        for (int ks = 2; ks < 4; ks++) {
            const int k0 = ks * 16;
            uint32_t ah[2][4];
            #pragma unroll
            for (int mt = 0; mt < 2; mt++) {
                uint32_t off = (uint32_t)((32*wr + 16*mt + ro) * SKB + k0 + co) * 2;
                ldsm4(ah[mt], sOff + 0*TILE_B + off);
            }
            uint32_t bh[8][2];
            #pragma unroll
            for (int p = 0; p < 4; p++) {
                uint32_t off = (uint32_t)((64*wc + 16*p + ro) * SKB + k0 + co) * 2;
                uint32_t r[4];
                ldsm4(r, sOff + 1*TILE_B + off);
                bh[2*p][0] = r[0];   bh[2*p][1] = r[2];
                bh[2*p+1][0] = r[1]; bh[2*p+1][1] = r[3];
            }
            #pragma unroll
            for (int mt = 0; mt < 2; mt++)
                #pragma unroll
                for (int nt = 0; nt < 8; nt++)
                    mma_hf(acc[mt][nt], ah[mt], bh[nt]);
        }

        if (pf) {
            #pragma unroll
            for (int it = 0; it < 4; it++) {
                int r = lr0 + it * 32;
                uint32_t doff = (uint32_t)(r * SKB + lc8) * 2;
                *(uint4*)(dst + 1*TILE_B + doff) = ra[it];
            }
        }
        __syncthreads();
    }

    // ---- epilogue ----
    float*  Cp  = (OUT == 0) ? C + cofs : nullptr;
    __half* ChH = (OUT == 2) ? Cho + cofs : nullptr;
    const float* R = HR ? resid : nullptr;

    #pragma unroll
    for (int mt = 0; mt < 2; mt++) {
        #pragma unroll
        for (int nt = 0; nt < 8; nt++) {
            const int r0 = row0 + 32*wr + 16*mt + (lane >> 2);
            const int cc = col0 + 64*wc + 8*nt + 2*(lane & 3);
            float2 bv = make_float2(0.f, 0.f);
            if (HB) bv = *(const float2*)&bias[cc];
            #pragma unroll
            for (int hh = 0; hh < 2; hh++) {
                const int r = r0 + hh * 8;
                float v0 = acc[mt][nt][2*hh]     * scale;
                float v1 = acc[mt][nt][2*hh + 1] * scale;
                if (HB) { v0 += bv.x; v1 += bv.y; }
                if (HR) {
                    float2 rv = *(const float2*)&R[(size_t)r * ldc + cc];
                    v0 += rv.x; v1 += rv.y;
                }
                if (ACT == 1) { v0 = gelu_exact(v0); v1 = gelu_exact(v1); }
                if (OUT == 0) {
                    *(float2*)&Cp[(size_t)r * ldc + cc] = make_float2(v0, v1);
                } else {
                    *(__half2*)&ChH[(size_t)r * ldc + cc] =
                        __halves2half2(__float2half_rn(v0), __float2half_rn(v1));
                }
            }
        }
    }
}

// ---------------- converter: fp32 -> fp16 ----------------
__global__ __launch_bounds__(256) void conv_hf_kernel(const float4* __restrict__ src,
                                                      uint2* __restrict__ h, int n4)
{
    int i = blockIdx.x * 256 + threadIdx.x;
    if (i < n4) h[i] = conv4h(src[i]);
}

// ---------------- V transpose: fp16 qkv -> fp16 Vt ----------------
__global__ __launch_bounds__(256) void transpose_v(const __half* __restrict__ qv,
                                                   __half* __restrict__ vt)
{
    __shared__ __half t[32][34];
    const int bh = blockIdx.z, b = bh / Hc, h = bh % Hc;
    const int q0 = blockIdx.x * 32, d0 = blockIdx.y * 32;
    const int tx = threadIdx.x & 31, ty = threadIdx.x >> 5;
    const size_t so = (size_t)b * Lc * D3c + 2 * Dc + h * HDc;
    #pragma unroll
    for (int i = ty; i < 32; i += 8)
        t[i][tx] = qv[so + (size_t)(q0 + i) * D3c + d0 + tx];
    __syncthreads();
    const size_t dofs = (size_t)bh * HDc * Lc;
    #pragma unroll
    for (int i = ty; i < 32; i += 8)
        vt[dofs + (size_t)(d0 + i) * Lc + q0 + tx] = t[tx][i];
}

// ---------------- layernorm: fp32 in; OMODE 0 = fp32 out, 1 = fp16 out ----------------
template<int OMODE>
__global__ __launch_bounds__(256)
void layernorm_kernel(const float* __restrict__ x, const float* __restrict__ g,
                      const float* __restrict__ b,
                      float* __restrict__ outF, __half* __restrict__ outH)
{
    const int row = blockIdx.x;
    const int t   = threadIdx.x;
    const float4 v = ((const float4*)(x + (size_t)row * Dc))[t];

    float s1 = v.x + v.y + v.z + v.w;
    float s2 = v.x*v.x + v.y*v.y + v.z*v.z + v.w*v.w;

    __shared__ float sh1[8], sh2[8];
    #pragma unroll
    for (int o = 16; o > 0; o >>= 1) {
        s1 += __shfl_down_sync(0xffffffffu, s1, o);
        s2 += __shfl_down_sync(0xffffffffu, s2, o);
    }
    if ((t & 31) == 0) { sh1[t >> 5] = s1; sh2[t >> 5] = s2; }
    __syncthreads();
    if (t < 8) {
        s1 = sh1[t]; s2 = sh2[t];
        #pragma unroll
        for (int o = 4; o > 0; o >>= 1) {
            s1 += __shfl_down_sync(0xffu, s1, o);
            s2 += __shfl_down_sync(0xffu, s2, o);
        }
        if (t == 0) { sh1[0] = s1; sh2[0] = s2; }
    }
    __syncthreads();

    const float mean = sh1[0] * (1.0f / Dc);
    const float var  = sh2[0] * (1.0f / Dc) - mean * mean;
    const float rstd = rsqrtf(var + 1e-5f);

    const float4 gv = ((const float4*)g)[t];
    const float4 bv = ((const float4*)b)[t];
    float4 r;
    r.x = (v.x - mean) * rstd * gv.x + bv.x;
    r.y = (v.y - mean) * rstd * gv.y + bv.y;
    r.z = (v.z - mean) * rstd * gv.z + bv.z;
    r.w = (v.w - mean) * rstd * gv.w + bv.w;
    if (OMODE == 1) {
        ((uint2*)(outH + (size_t)row * Dc))[t] = conv4h(r);
    } else {
        ((float4*)(outF + (size_t)row * Dc))[t] = r;
    }
}

// ---------------- softmax: fp32 in, fp16 out ----------------
__global__ __launch_bounds__(256)
void softmax_kernel(const float* __restrict__ s, __half* __restrict__ pp)
{
    const size_t row = blockIdx.x;
    const float4* p = (const float4*)(s + row * (size_t)Lc);
    const int t = threadIdx.x;

    float4 a = p[t];
    float4 c = p[t + 256];

    float mx = fmaxf(fmaxf(fmaxf(a.x, a.y), fmaxf(a.z, a.w)),
                     fmaxf(fmaxf(c.x, c.y), fmaxf(c.z, c.w)));

    __shared__ float sh[8];
    #pragma unroll
    for (int o = 16; o > 0; o >>= 1) mx = fmaxf(mx, __shfl_down_sync(0xffffffffu, mx, o));
    if ((t & 31) == 0) sh[t >> 5] = mx;
    __syncthreads();
    if (t < 8) {
        mx = sh[t];
        #pragma unroll
        for (int o = 4; o > 0; o >>= 1) mx = fmaxf(mx, __shfl_down_sync(0xffu, mx, o));
        if (t == 0) sh[0] = mx;
    }
    __syncthreads();
    mx = sh[0];
    __syncthreads();

    a.x = expf(a.x - mx); a.y = expf(a.y - mx); a.z = expf(a.z - mx); a.w = expf(a.w - mx);
    c.x = expf(c.x - mx); c.y = expf(c.y - mx); c.z = expf(c.z - mx); c.w = expf(c.w - mx);

    float sm = a.x + a.y + a.z + a.w + c.x + c.y + c.z + c.w;
    #pragma unroll
    for (int o = 16; o > 0; o >>= 1) sm += __shfl_down_sync(0xffffffffu, sm, o);
    if ((t & 31) == 0) sh[t >> 5] = sm;
    __syncthreads();
    if (t < 8) {
        sm = sh[t];
        #pragma unroll
        for (int o = 4; o > 0; o >>= 1) sm += __shfl_down_sync(0xffu, sm, o);
        if (t == 0) sh[0] = sm;
    }
    __syncthreads();
    const float inv = 1.0f / sh[0];

    a.x *= inv; a.y *= inv; a.z *= inv; a.w *= inv;
    c.x *= inv; c.y *= inv; c.z *= inv; c.w *= inv;

    ((uint2*)(pp + row * (size_t)Lc))[t]       = conv4h(a);
    ((uint2*)(pp + row * (size_t)Lc))[t + 256] = conv4h(c);
}

// ---------------- host side ----------------
static void do_conv_hf(const float* src, __half* h, size_t n) {
    int n4 = (int)(n / 4);
    conv_hf_kernel<<<(n4 + 255) / 256, 256>>>((const float4*)src, (uint2*)h, n4);
}

extern "C" void kernel_launch(void* const* d_in, const int* in_sizes, int n_in,
                              void* d_out, int out_size)
{
    const float* x    = (const float*)d_in[0];
    const float* w3d  = (const float*)d_in[1];
    const float* b3d  = (const float*)d_in[2];
    const float* ln1g = (const float*)d_in[3];
    const float* ln1b = (const float*)d_in[4];
    const float* wqkv = (const float*)d_in[5];
    const float* bqkv = (const float*)d_in[6];
    const float* wprj = (const float*)d_in[7];
    const float* bprj = (const float*)d_in[8];
    const float* ln2g = (const float*)d_in[9];
    const float* ln2b = (const float*)d_in[10];
    const float* w1   = (const float*)d_in[11];
    const float* b1   = (const float*)d_in[12];
    const float* w2   = (const float*)d_in[13];
    const float* b2   = (const float*)d_in[14];
    const float* lnfg = (const float*)d_in[15];
    const float* lnfb = (const float*)d_in[16];
    float* out = (float*)d_out;

    float *h, *sc;
    __half *xp,*w3,*hn,*wq,*wp,*w1p,*w2p,*qv,*vt,*pp,*op,*fp;
    cudaGetSymbolAddress((void**)&h,   g_h);
    cudaGetSymbolAddress((void**)&sc,  g_sc);
    cudaGetSymbolAddress((void**)&xp,  g_x);
    cudaGetSymbolAddress((void**)&w3,  g_w3);
    cudaGetSymbolAddress((void**)&hn,  g_hn);
    cudaGetSymbolAddress((void**)&wq,  g_wq);
    cudaGetSymbolAddress((void**)&wp,  g_wp);
    cudaGetSymbolAddress((void**)&w1p, g_w1);
    cudaGetSymbolAddress((void**)&w2p, g_w2);
    cudaGetSymbolAddress((void**)&qv,  g_qv);
    cudaGetSymbolAddress((void**)&vt,  g_vt);
    cudaGetSymbolAddress((void**)&pp,  g_p);
    cudaGetSymbolAddress((void**)&op,  g_o);
    cudaGetSymbolAddress((void**)&fp,  g_f);

    cudaFuncSetAttribute(tc_ghf<true,false,0,0>,  cudaFuncAttributeMaxDynamicSharedMemorySize, SM1);
    cudaFuncSetAttribute(tc_ghf<true,false,0,2>,  cudaFuncAttributeMaxDynamicSharedMemorySize, SM1);
    cudaFuncSetAttribute(tc_ghf<false,false,0,0>, cudaFuncAttributeMaxDynamicSharedMemorySize, SM1);
    cudaFuncSetAttribute(tc_ghf<false,false,0,2>, cudaFuncAttributeMaxDynamicSharedMemorySize, SM1);
    cudaFuncSetAttribute(tc_ghf<true,true,0,0>,   cudaFuncAttributeMaxDynamicSharedMemorySize, SM1);
    cudaFuncSetAttribute(tc_ghf<true,false,1,2>,  cudaFuncAttributeMaxDynamicSharedMemorySize, SM1);

    const dim3 blk(256);

    // one-time conversions
    do_conv_hf(x,   xp, (size_t)Mc * D3c);
    do_conv_hf(w3d, w3, (size_t)Dc * D3c);

    // ---- embed: h = x @ w3d^T + b3d ----
    tc_ghf<true,false,0,0><<<dim3(Dc/128, Mc/128, 1), blk, SM1>>>(
        xp, D3c, w3, D3c, b3d, nullptr,
        h, nullptr, Dc, D3c, 1.0f, 0,0,0,0,0,0, 1);

    for (int i = 0; i < NLc; i++) {
        do_conv_hf(wqkv + (size_t)i*D3c*Dc, wq, (size_t)D3c*Dc);

        layernorm_kernel<1><<<Mc, blk>>>(h, ln1g + (size_t)i*Dc, ln1b + (size_t)i*Dc,
                                         nullptr, hn);

        // qkv = hn @ wqkv^T + bqkv -> fp16
        tc_ghf<true,false,0,2><<<dim3(D3c/128, Mc/128, 1), blk, SM1>>>(
            hn, Dc, wq, Dc, bqkv + (size_t)i*D3c, nullptr,
            nullptr, qv, D3c, Dc, 1.0f, 0,0,0,0,0,0, 1);

        transpose_v<<<dim3(Lc/32, HDc/32, Bc*Hc), blk>>>(qv, vt);

        // scores = scale * Q @ K^T -> fp32
        tc_ghf<false,false,0,0><<<dim3(Lc/128, Lc/128, Bc*Hc), blk, SM1>>>(
            qv, D3c,
            qv + Dc, D3c,
            nullptr, nullptr,
            sc, nullptr, Lc, HDc, 0.0625f,
            (long)Lc*D3c, (long)HDc,
            (long)Lc*D3c, (long)HDc,
            (long)Hc*Lc*Lc, (long)Lc*Lc,
            Hc);

        softmax_kernel<<<Bc*Hc*Lc, blk>>>(sc, pp);

        // o = P @ Vt^T -> fp16
        tc_ghf<false,false,0,2><<<dim3(HDc/128, Lc/128, Bc*Hc), blk, SM1>>>(
            pp, Lc,
            vt, Lc,
            nullptr, nullptr,
            nullptr, op, Dc, Lc, 1.0f,
            (long)Hc*Lc*Lc, (long)Lc*Lc,
            (long)Hc*HDc*Lc, (long)HDc*Lc,
            (long)Lc*Dc, (long)HDc,
            Hc);

        do_conv_hf(wprj + (size_t)i*Dc*Dc, wp, (size_t)Dc*Dc);

        // h = h + o @ wproj^T + bproj
        tc_ghf<true,true,0,0><<<dim3(Dc/128, Mc/128, 1), blk, SM1>>>(
            op, Dc, wp, Dc, bprj + (size_t)i*Dc, h,
            h, nullptr, Dc, Dc, 1.0f, 0,0,0,0,0,0, 1);

        layernorm_kernel<1><<<Mc, blk>>>(h, ln2g + (size_t)i*Dc, ln2b + (size_t)i*Dc,
                                         nullptr, hn);

        do_conv_hf(w1 + (size_t)i*FFc*Dc, w1p, (size_t)FFc*Dc);

        // f = gelu(hn @ w1^T + b1) -> fp16
        tc_ghf<true,false,1,2><<<dim3(FFc/128, Mc/128, 1), blk, SM1>>>(
            hn, Dc, w1p, Dc, b1 + (size_t)i*FFc, nullptr,
            nullptr, fp, FFc, Dc, 1.0f, 0,0,0,0,0,0, 1);

        do_conv_hf(w2 + (size_t)i*Dc*FFc, w2p, (size_t)Dc*FFc);

        // h = h + f @ w2^T + b2
        tc_ghf<true,true,0,0><<<dim3(Dc/128, Mc/128, 1), blk, SM1>>>(
            fp, FFc, w2p, FFc, b2 + (size_t)i*Dc, h,
            h, nullptr, Dc, FFc, 1.0f, 0,0,0,0,0,0, 1);
    }

    layernorm_kernel<0><<<Mc, blk>>>(h, lnfg, lnfb, out, nullptr);
}

// round 10
// speedup vs baseline: 2.9496x; 1.1098x over previous
#include <cuda_runtime.h>
#include <cuda_fp16.h>
#include <math.h>
#include <stdint.h>

// ---------------- problem constants ----------------
#define Bc   4
#define Lc   2048
#define Dc   1024
#define Hc   4
#define HDc  256
#define NLc  2
#define FFc  4096
#define Mc   (Bc*Lc)     // 8192 tokens
#define D3c  (3*Dc)      // 3072

// ---------------- device scratch (static; no allocations) ----------------
__device__ float g_h  [(size_t)Mc*Dc];            // residual fp32
// fp16 planes
__device__ __align__(16) __half g_x  [(size_t)Mc*D3c];
__device__ __align__(16) __half g_w3 [(size_t)Dc*D3c];
__device__ __align__(16) __half g_hn [(size_t)Mc*Dc];
__device__ __align__(16) __half g_wq [(size_t)D3c*Dc];
__device__ __align__(16) __half g_wp [(size_t)Dc*Dc];
__device__ __align__(16) __half g_w1 [(size_t)FFc*Dc];
__device__ __align__(16) __half g_w2 [(size_t)Dc*FFc];
__device__ __align__(16) __half g_qv [(size_t)Mc*D3c];
__device__ __align__(16) __half g_vt [(size_t)Bc*Hc*HDc*Lc];
__device__ __align__(16) __half g_p  [(size_t)Bc*Hc*Lc*Lc];   // logits -> probs in place
__device__ __align__(16) __half g_o  [(size_t)Mc*Dc];
__device__ __align__(16) __half g_f  [(size_t)Mc*FFc];

// ---------------- helpers ----------------
__device__ __forceinline__ uint32_t smem_u32(const void* p) {
    uint32_t a;
    asm("{ .reg .u64 t; cvta.to.shared.u64 t, %1; cvt.u32.u64 %0, t; }" : "=r"(a) : "l"(p));
    return a;
}
__device__ __forceinline__ void ldsm4(uint32_t* r, uint32_t addr) {
    asm volatile("ldmatrix.sync.aligned.m8n8.x4.shared.b16 {%0,%1,%2,%3}, [%4];"
        : "=r"(r[0]), "=r"(r[1]), "=r"(r[2]), "=r"(r[3]) : "r"(addr));
}
__device__ __forceinline__ void mma_hf(float* d, const uint32_t* a, const uint32_t* b) {
    asm volatile(
        "mma.sync.aligned.m16n8k16.row.col.f32.f16.f16.f32 "
        "{%0,%1,%2,%3}, {%4,%5,%6,%7}, {%8,%9}, {%0,%1,%2,%3};"
        : "+f"(d[0]), "+f"(d[1]), "+f"(d[2]), "+f"(d[3])
        : "r"(a[0]), "r"(a[1]), "r"(a[2]), "r"(a[3]), "r"(b[0]), "r"(b[1]));
}
__device__ __forceinline__ float gelu_exact(float x) {
    return 0.5f * x * (1.0f + erff(x * 0.70710678118654752440f));
}
__device__ __forceinline__ uint2 conv4h(float4 v) {
    union { __half2 h2[2]; uint2 u; } H;
    H.h2[0] = __halves2half2(__float2half_rn(v.x), __float2half_rn(v.y));
    H.h2[1] = __halves2half2(__float2half_rn(v.z), __float2half_rn(v.w));
    return H.u;
}
__device__ __forceinline__ float4 h4_to_f4(uint2 u) {
    union { uint2 uu; __half2 h2[2]; } U; U.uu = u;
    float2 lo = __half22float2(U.h2[0]);
    float2 hi = __half22float2(U.h2[1]);
    return make_float4(lo.x, lo.y, hi.x, hi.y);
}

// ================= fp16 1-term GEMM =================
// C[M,N] = act(scale * A @ B^T + bias + resid)
// OUT: 0 = fp32 C; 2 = fp16
#define KC     64
#define SKB    72
#define TILE_B (128*SKB*2)          // 18432 B
#define STG    (2*TILE_B)           // stage bytes (A + B)
#define SM1    (2*STG)              // 73728 B dynamic smem

template<bool HB, bool HR, int ACT, int OUT>
__global__ __launch_bounds__(256, 2) void tc_ghf(
    const __half* __restrict__ Ah, int lda,
    const __half* __restrict__ Bh, int ldb,
    const float* __restrict__ bias,
    const float* __restrict__ resid,
    float* __restrict__ C, __half* __restrict__ Cho, int ldc,
    int K, float scale,
    long aso, long asi, long bso, long bsi, long cso, long csi, int zinner)
{
    const int z  = blockIdx.z;
    const int zo = z / zinner;
    const int zi = z - zo * zinner;
    const size_t aofs = (size_t)zo * aso + (size_t)zi * asi;
    const size_t bofs = (size_t)zo * bso + (size_t)zi * bsi;
    const size_t cofs = (size_t)zo * cso + (size_t)zi * csi;
    Ah += aofs;
    Bh += bofs;

    extern __shared__ char dsm[];
    const uint32_t sb32 = smem_u32(dsm);

    const int tid  = threadIdx.x;
    const int wid  = tid >> 5;
    const int lane = tid & 31;
    const int wr   = wid & 3;
    const int wc   = wid >> 2;
    const int row0 = blockIdx.y * 128;
    const int col0 = blockIdx.x * 128;

    const int lr0 = tid >> 3;
    const int lc8 = (tid & 7) << 3;

    const __half* A0 = Ah + (size_t)row0 * lda;
    const __half* B0 = Bh + (size_t)col0 * ldb;

    float acc[2][8][4];
    #pragma unroll
    for (int mt = 0; mt < 2; mt++)
        #pragma unroll
        for (int nt = 0; nt < 8; nt++)
            #pragma unroll
            for (int j = 0; j < 4; j++) acc[mt][nt][j] = 0.0f;

    const int nc = K / KC;

    // ---- prologue: stage 0 ----
    #pragma unroll
    for (int it = 0; it < 4; it++) {
        int r = lr0 + it * 32;
        uint32_t doff = (uint32_t)(r * SKB + lc8) * 2;
        *(uint4*)(dsm + 0*TILE_B + doff) = *(const uint4*)(A0 + (size_t)r * lda + lc8);
        *(uint4*)(dsm + 1*TILE_B + doff) = *(const uint4*)(B0 + (size_t)r * ldb + lc8);
    }
    __syncthreads();

    const int ro = lane & 15;
    const int co = (lane >> 4) << 3;

    for (int c = 0; c < nc; c++) {
        const int s = c & 1;
        const uint32_t sOff = sb32 + (uint32_t)s * STG;
        char* dst = dsm + (size_t)(s ^ 1) * STG;
        const bool pf = (c + 1 < nc);
        const int kn = (c + 1) * KC;

        uint4 ra[4];
        if (pf) {
            #pragma unroll
            for (int it = 0; it < 4; it++) {
                int r = lr0 + it * 32;
                ra[it] = *(const uint4*)(A0 + (size_t)r * lda + kn + lc8);
            }
        }

        #pragma unroll
        for (int ks = 0; ks < 2; ks++) {
            const int k0 = ks * 16;
            uint32_t ah[2][4];
            #pragma unroll
            for (int mt = 0; mt < 2; mt++) {
                uint32_t off = (uint32_t)((32*wr + 16*mt + ro) * SKB + k0 + co) * 2;
                ldsm4(ah[mt], sOff + 0*TILE_B + off);
            }
            uint32_t bh[8][2];
            #pragma unroll
            for (int p = 0; p < 4; p++) {
                uint32_t off = (uint32_t)((64*wc + 16*p + ro) * SKB + k0 + co) * 2;
                uint32_t r[4];
                ldsm4(r, sOff + 1*TILE_B + off);
                bh[2*p][0] = r[0];   bh[2*p][1] = r[2];
                bh[2*p+1][0] = r[1]; bh[2*p+1][1] = r[3];
            }
            #pragma unroll
            for (int mt = 0; mt < 2; mt++)
                #pragma unroll
                for (int nt = 0; nt < 8; nt++)
                    mma_hf(acc[mt][nt], ah[mt], bh[nt]);
        }

        if (pf) {
            #pragma unroll
            for (int it = 0; it < 4; it++) {
                int r = lr0 + it * 32;
                uint32_t doff = (uint32_t)(r * SKB + lc8) * 2;
                *(uint4*)(dst + 0*TILE_B + doff) = ra[it];
            }
            #pragma unroll
            for (int it = 0; it < 4; it++) {
                int r = lr0 + it * 32;
                ra[it] = *(const uint4*)(B0 + (size_t)r * ldb + kn + lc8);
            }
        }

        #pragma unroll
        for (int ks = 2; ks < 4; ks++) {
            const int k0 = ks * 16;
            uint32_t ah[2][4];
            #pragma unroll
            for (int mt = 0; mt < 2; mt++) {
                uint32_t off = (uint32_t)((32*wr + 16*mt + ro) * SKB + k0 + co) * 2;
                ldsm4(ah[mt], sOff + 0*TILE_B + off);
            }
            uint32_t bh[8][2];
            #pragma unroll
            for (int p = 0; p < 4; p++) {
                uint32_t off = (uint32_t)((64*wc + 16*p + ro) * SKB + k0 + co) * 2;
                uint32_t r[4];
                ldsm4(r, sOff + 1*TILE_B + off);
                bh[2*p][0] = r[0];   bh[2*p][1] = r[2];
                bh[2*p+1][0] = r[1]; bh[2*p+1][1] = r[3];
            }
            #pragma unroll
            for (int mt = 0; mt < 2; mt++)
                #pragma unroll
                for (int nt = 0; nt < 8; nt++)
                    mma_hf(acc[mt][nt], ah[mt], bh[nt]);
        }

        if (pf) {
            #pragma unroll
            for (int it = 0; it < 4; it++) {
                int r = lr0 + it * 32;
                uint32_t doff = (uint32_t)(r * SKB + lc8) * 2;
                *(uint4*)(dst + 1*TILE_B + doff) = ra[it];
            }
        }
        __syncthreads();
    }

    // ---- epilogue ----
    float*  Cp  = (OUT == 0) ? C + cofs : nullptr;
    __half* ChH = (OUT == 2) ? Cho + cofs : nullptr;
    const float* R = HR ? resid : nullptr;

    #pragma unroll
    for (int mt = 0; mt < 2; mt++) {
        #pragma unroll
        for (int nt = 0; nt < 8; nt++) {
            const int r0 = row0 + 32*wr + 16*mt + (lane >> 2);
            const int cc = col0 + 64*wc + 8*nt + 2*(lane & 3);
            float2 bv = make_float2(0.f, 0.f);
            if (HB) bv = *(const float2*)&bias[cc];
            #pragma unroll
            for (int hh = 0; hh < 2; hh++) {
                const int r = r0 + hh * 8;
                float v0 = acc[mt][nt][2*hh]     * scale;
                float v1 = acc[mt][nt][2*hh + 1] * scale;
                if (HB) { v0 += bv.x; v1 += bv.y; }
                if (HR) {
                    float2 rv = *(const float2*)&R[(size_t)r * ldc + cc];
                    v0 += rv.x; v1 += rv.y;
                }
                if (ACT == 1) { v0 = gelu_exact(v0); v1 = gelu_exact(v1); }
                if (OUT == 0) {
                    *(float2*)&Cp[(size_t)r * ldc + cc] = make_float2(v0, v1);
                } else {
                    *(__half2*)&ChH[(size_t)r * ldc + cc] =
                        __halves2half2(__float2half_rn(v0), __float2half_rn(v1));
                }
            }
        }
    }
}

// ---------------- converter: fp32 -> fp16 ----------------
__global__ __launch_bounds__(256) void conv_hf_kernel(const float4* __restrict__ src,
                                                      uint2* __restrict__ h, int n4)
{
    int i = blockIdx.x * 256 + threadIdx.x;
    if (i < n4) h[i] = conv4h(src[i]);
}

// ---------------- V transpose: fp16 qkv -> fp16 Vt ----------------
__global__ __launch_bounds__(256) void transpose_v(const __half* __restrict__ qv,
                                                   __half* __restrict__ vt)
{
    __shared__ __half t[32][34];
    const int bh = blockIdx.z, b = bh / Hc, h = bh % Hc;
    const int q0 = blockIdx.x * 32, d0 = blockIdx.y * 32;
    const int tx = threadIdx.x & 31, ty = threadIdx.x >> 5;
    const size_t so = (size_t)b * Lc * D3c + 2 * Dc + h * HDc;
    #pragma unroll
    for (int i = ty; i < 32; i += 8)
        t[i][tx] = qv[so + (size_t)(q0 + i) * D3c + d0 + tx];
    __syncthreads();
    const size_t dofs = (size_t)bh * HDc * Lc;
    #pragma unroll
    for (int i = ty; i < 32; i += 8)
        vt[dofs + (size_t)(d0 + i) * Lc + q0 + tx] = t[tx][i];
}

// ---------------- layernorm: fp32 in; OMODE 0 = fp32 out, 1 = fp16 out ----------------
template<int OMODE>
__global__ __launch_bounds__(256)
void layernorm_kernel(const float* __restrict__ x, const float* __restrict__ g,
                      const float* __restrict__ b,
                      float* __restrict__ outF, __half* __restrict__ outH)
{
    const int row = blockIdx.x;
    const int t   = threadIdx.x;
    const float4 v = ((const float4*)(x + (size_t)row * Dc))[t];

    float s1 = v.x + v.y + v.z + v.w;
    float s2 = v.x*v.x + v.y*v.y + v.z*v.z + v.w*v.w;

    __shared__ float sh1[8], sh2[8];
    #pragma unroll
    for (int o = 16; o > 0; o >>= 1) {
        s1 += __shfl_down_sync(0xffffffffu, s1, o);
        s2 += __shfl_down_sync(0xffffffffu, s2, o);
    }
    if ((t & 31) == 0) { sh1[t >> 5] = s1; sh2[t >> 5] = s2; }
    __syncthreads();
    if (t < 8) {
        s1 = sh1[t]; s2 = sh2[t];
        #pragma unroll
        for (int o = 4; o > 0; o >>= 1) {
            s1 += __shfl_down_sync(0xffu, s1, o);
            s2 += __shfl_down_sync(0xffu, s2, o);
        }
        if (t == 0) { sh1[0] = s1; sh2[0] = s2; }
    }
    __syncthreads();

    const float mean = sh1[0] * (1.0f / Dc);
    const float var  = sh2[0] * (1.0f / Dc) - mean * mean;
    const float rstd = rsqrtf(var + 1e-5f);

    const float4 gv = ((const float4*)g)[t];
    const float4 bv = ((const float4*)b)[t];
    float4 r;
    r.x = (v.x - mean) * rstd * gv.x + bv.x;
    r.y = (v.y - mean) * rstd * gv.y + bv.y;
    r.z = (v.z - mean) * rstd * gv.z + bv.z;
    r.w = (v.w - mean) * rstd * gv.w + bv.w;
    if (OMODE == 1) {
        ((uint2*)(outH + (size_t)row * Dc))[t] = conv4h(r);
    } else {
        ((float4*)(outF + (size_t)row * Dc))[t] = r;
    }
}

// ---------------- softmax: fp16 logits in, fp16 probs out (in place) ----------------
__global__ __launch_bounds__(256)
void softmax_kernel(__half* __restrict__ pp)
{
    const size_t row = blockIdx.x;
    uint2* p = (uint2*)(pp + row * (size_t)Lc);
    const int t = threadIdx.x;

    float4 a = h4_to_f4(p[t]);
    float4 c = h4_to_f4(p[t + 256]);

    float mx = fmaxf(fmaxf(fmaxf(a.x, a.y), fmaxf(a.z, a.w)),
                     fmaxf(fmaxf(c.x, c.y), fmaxf(c.z, c.w)));

    __shared__ float sh[8];
    #pragma unroll
    for (int o = 16; o > 0; o >>= 1) mx = fmaxf(mx, __shfl_down_sync(0xffffffffu, mx, o));
    if ((t & 31) == 0) sh[t >> 5] = mx;
    __syncthreads();
    if (t < 8) {
        mx = sh[t];
        #pragma unroll
        for (int o = 4; o > 0; o >>= 1) mx = fmaxf(mx, __shfl_down_sync(0xffu, mx, o));
        if (t == 0) sh[0] = mx;
    }
    __syncthreads();
    mx = sh[0];
    __syncthreads();

    a.x = expf(a.x - mx); a.y = expf(a.y - mx); a.z = expf(a.z - mx); a.w = expf(a.w - mx);
    c.x = expf(c.x - mx); c.y = expf(c.y - mx); c.z = expf(c.z - mx); c.w = expf(c.w - mx);

    float sm = a.x + a.y + a.z + a.w + c.x + c.y + c.z + c.w;
    #pragma unroll
    for (int o = 16; o > 0; o >>= 1) sm += __shfl_down_sync(0xffffffffu, sm, o);
    if ((t & 31) == 0) sh[t >> 5] = sm;
    __syncthreads();
    if (t < 8) {
        sm = sh[t];
        #pragma unroll
        for (int o = 4; o > 0; o >>= 1) sm += __shfl_down_sync(0xffu, sm, o);
        if (t == 0) sh[0] = sm;
    }
    __syncthreads();
    const float inv = 1.0f / sh[0];

    a.x *= inv; a.y *= inv; a.z *= inv; a.w *= inv;
    c.x *= inv; c.y *= inv; c.z *= inv; c.w *= inv;

    p[t]       = conv4h(a);
    p[t + 256] = conv4h(c);
}

// ---------------- host side ----------------
static void do_conv_hf(const float* src, __half* h, size_t n) {
    int n4 = (int)(n / 4);
    conv_hf_kernel<<<(n4 + 255) / 256, 256>>>((const float4*)src, (uint2*)h, n4);
}

extern "C" void kernel_launch(void* const* d_in, const int* in_sizes, int n_in,
                              void* d_out, int out_size)
{
    const float* x    = (const float*)d_in[0];
    const float* w3d  = (const float*)d_in[1];
    const float* b3d  = (const float*)d_in[2];
    const float* ln1g = (const float*)d_in[3];
    const float* ln1b = (const float*)d_in[4];
    const float* wqkv = (const float*)d_in[5];
    const float* bqkv = (const float*)d_in[6];
    const float* wprj = (const float*)d_in[7];
    const float* bprj = (const float*)d_in[8];
    const float* ln2g = (const float*)d_in[9];
    const float* ln2b = (const float*)d_in[10];
    const float* w1   = (const float*)d_in[11];
    const float* b1   = (const float*)d_in[12];
    const float* w2   = (const float*)d_in[13];
    const float* b2   = (const float*)d_in[14];
    const float* lnfg = (const float*)d_in[15];
    const float* lnfb = (const float*)d_in[16];
    float* out = (float*)d_out;

    float *h;
    __half *xp,*w3,*hn,*wq,*wp,*w1p,*w2p,*qv,*vt,*pp,*op,*fp;
    cudaGetSymbolAddress((void**)&h,   g_h);
    cudaGetSymbolAddress((void**)&xp,  g_x);
    cudaGetSymbolAddress((void**)&w3,  g_w3);
    cudaGetSymbolAddress((void**)&hn,  g_hn);
    cudaGetSymbolAddress((void**)&wq,  g_wq);
    cudaGetSymbolAddress((void**)&wp,  g_wp);
    cudaGetSymbolAddress((void**)&w1p, g_w1);
    cudaGetSymbolAddress((void**)&w2p, g_w2);
    cudaGetSymbolAddress((void**)&qv,  g_qv);
    cudaGetSymbolAddress((void**)&vt,  g_vt);
    cudaGetSymbolAddress((void**)&pp,  g_p);
    cudaGetSymbolAddress((void**)&op,  g_o);
    cudaGetSymbolAddress((void**)&fp,  g_f);

    cudaFuncSetAttribute(tc_ghf<true,false,0,0>,  cudaFuncAttributeMaxDynamicSharedMemorySize, SM1);
    cudaFuncSetAttribute(tc_ghf<true,false,0,2>,  cudaFuncAttributeMaxDynamicSharedMemorySize, SM1);
    cudaFuncSetAttribute(tc_ghf<false,false,0,2>, cudaFuncAttributeMaxDynamicSharedMemorySize, SM1);
    cudaFuncSetAttribute(tc_ghf<true,true,0,0>,   cudaFuncAttributeMaxDynamicSharedMemorySize, SM1);
    cudaFuncSetAttribute(tc_ghf<true,false,1,2>,  cudaFuncAttributeMaxDynamicSharedMemorySize, SM1);

    const dim3 blk(256);

    // one-time conversions
    do_conv_hf(x,   xp, (size_t)Mc * D3c);
    do_conv_hf(w3d, w3, (size_t)Dc * D3c);

    // ---- embed: h = x @ w3d^T + b3d ----
    tc_ghf<true,false,0,0><<<dim3(Dc/128, Mc/128, 1), blk, SM1>>>(
        xp, D3c, w3, D3c, b3d, nullptr,
        h, nullptr, Dc, D3c, 1.0f, 0,0,0,0,0,0, 1);

    for (int i = 0; i < NLc; i++) {
        do_conv_hf(wqkv + (size_t)i*D3c*Dc, wq, (size_t)D3c*Dc);

        layernorm_kernel<1><<<Mc, blk>>>(h, ln1g + (size_t)i*Dc, ln1b + (size_t)i*Dc,
                                         nullptr, hn);

        // qkv = hn @ wqkv^T + bqkv -> fp16
        tc_ghf<true,false,0,2><<<dim3(D3c/128, Mc/128, 1), blk, SM1>>>(
            hn, Dc, wq, Dc, bqkv + (size_t)i*D3c, nullptr,
            nullptr, qv, D3c, Dc, 1.0f, 0,0,0,0,0,0, 1);

        transpose_v<<<dim3(Lc/32, HDc/32, Bc*Hc), blk>>>(qv, vt);

        // logits = scale * Q @ K^T -> fp16 (into g_p)
        tc_ghf<false,false,0,2><<<dim3(Lc/128, Lc/128, Bc*Hc), blk, SM1>>>(
            qv, D3c,
            qv + Dc, D3c,
            nullptr, nullptr,
            nullptr, pp, Lc, HDc, 0.0625f,
            (long)Lc*D3c, (long)HDc,
            (long)Lc*D3c, (long)HDc,
            (long)Hc*Lc*Lc, (long)Lc*Lc,
            Hc);

        softmax_kernel<<<Bc*Hc*Lc, blk>>>(pp);   // in place

        // o = P @ Vt^T -> fp16
        tc_ghf<false,false,0,2><<<dim3(HDc/128, Lc/128, Bc*Hc), blk, SM1>>>(
            pp, Lc,
            vt, Lc,
            nullptr, nullptr,
            nullptr, op, Dc, Lc, 1.0f,
            (long)Hc*Lc*Lc, (long)Lc*Lc,
            (long)Hc*HDc*Lc, (long)HDc*Lc,
            (long)Lc*Dc, (long)HDc,
            Hc);

        do_conv_hf(wprj + (size_t)i*Dc*Dc, wp, (size_t)Dc*Dc);

        // h = h + o @ wproj^T + bproj
        tc_ghf<true,true,0,0><<<dim3(Dc/128, Mc/128, 1), blk, SM1>>>(
            op, Dc, wp, Dc, bprj + (size_t)i*Dc, h,
            h, nullptr, Dc, Dc, 1.0f, 0,0,0,0,0,0, 1);

        layernorm_kernel<1><<<Mc, blk>>>(h, ln2g + (size_t)i*Dc, ln2b + (size_t)i*Dc,
                                         nullptr, hn);

        do_conv_hf(w1 + (size_t)i*FFc*Dc, w1p, (size_t)FFc*Dc);

        // f = gelu(hn @ w1^T + b1) -> fp16
        tc_ghf<true,false,1,2><<<dim3(FFc/128, Mc/128, 1), blk, SM1>>>(
            hn, Dc, w1p, Dc, b1 + (size_t)i*FFc, nullptr,
            nullptr, fp, FFc, Dc, 1.0f, 0,0,0,0,0,0, 1);

        do_conv_hf(w2 + (size_t)i*Dc*FFc, w2p, (size_t)Dc*FFc);

        // h = h + f @ w2^T + b2
        tc_ghf<true,true,0,0><<<dim3(Dc/128, Mc/128, 1), blk, SM1>>>(
            fp, FFc, w2p, FFc, b2 + (size_t)i*Dc, h,
            h, nullptr, Dc, FFc, 1.0f, 0,0,0,0,0,0, 1);
    }

    layernorm_kernel<0><<<Mc, blk>>>(h, lnfg, lnfb, out, nullptr);
}

// round 11
// speedup vs baseline: 2.9786x; 1.0098x over previous
#include <cuda_runtime.h>
#include <cuda_fp16.h>
#include <math.h>
#include <stdint.h>

// ---------------- problem constants ----------------
#define Bc   4
#define Lc   2048
#define Dc   1024
#define Hc   4
#define HDc  256
#define NLc  2
#define FFc  4096
#define Mc   (Bc*Lc)     // 8192 tokens
#define D3c  (3*Dc)      // 3072

// ---------------- device scratch (static; no allocations) ----------------
__device__ float g_h  [(size_t)Mc*Dc];            // residual fp32
// fp16 planes
__device__ __align__(16) __half g_x  [(size_t)Mc*D3c];
__device__ __align__(16) __half g_w3 [(size_t)Dc*D3c];
__device__ __align__(16) __half g_hn [(size_t)Mc*Dc];
__device__ __align__(16) __half g_wq [(size_t)D3c*Dc];
__device__ __align__(16) __half g_wp [(size_t)Dc*Dc];
__device__ __align__(16) __half g_w1 [(size_t)FFc*Dc];
__device__ __align__(16) __half g_w2 [(size_t)Dc*FFc];
__device__ __align__(16) __half g_qv [(size_t)Mc*D3c];
__device__ __align__(16) __half g_vt [(size_t)Bc*Hc*HDc*Lc];
__device__ __align__(16) __half g_p  [(size_t)Bc*Hc*Lc*Lc];   // logits -> probs in place
__device__ __align__(16) __half g_o  [(size_t)Mc*Dc];
__device__ __align__(16) __half g_f  [(size_t)Mc*FFc];

// ---------------- helpers ----------------
__device__ __forceinline__ uint32_t smem_u32(const void* p) {
    uint32_t a;
    asm("{ .reg .u64 t; cvta.to.shared.u64 t, %1; cvt.u32.u64 %0, t; }" : "=r"(a) : "l"(p));
    return a;
}
__device__ __forceinline__ void ldsm4(uint32_t* r, uint32_t addr) {
    asm volatile("ldmatrix.sync.aligned.m8n8.x4.shared.b16 {%0,%1,%2,%3}, [%4];"
        : "=r"(r[0]), "=r"(r[1]), "=r"(r[2]), "=r"(r[3]) : "r"(addr));
}
__device__ __forceinline__ void mma_hf(float* d, const uint32_t* a, const uint32_t* b) {
    asm volatile(
        "mma.sync.aligned.m16n8k16.row.col.f32.f16.f16.f32 "
        "{%0,%1,%2,%3}, {%4,%5,%6,%7}, {%8,%9}, {%0,%1,%2,%3};"
        : "+f"(d[0]), "+f"(d[1]), "+f"(d[2]), "+f"(d[3])
        : "r"(a[0]), "r"(a[1]), "r"(a[2]), "r"(a[3]), "r"(b[0]), "r"(b[1]));
}
__device__ __forceinline__ void cpa16(uint32_t dst, const void* src) {
    asm volatile("cp.async.cg.shared.global [%0], [%1], 16;" :: "r"(dst), "l"(src));
}
#define CP_COMMIT() asm volatile("cp.async.commit_group;" ::: "memory")
#define CP_WAIT1()  asm volatile("cp.async.wait_group 1;"  ::: "memory")

__device__ __forceinline__ float gelu_exact(float x) {
    return 0.5f * x * (1.0f + erff(x * 0.70710678118654752440f));
}
__device__ __forceinline__ uint2 conv4h(float4 v) {
    union { __half2 h2[2]; uint2 u; } H;
    H.h2[0] = __halves2half2(__float2half_rn(v.x), __float2half_rn(v.y));
    H.h2[1] = __halves2half2(__float2half_rn(v.z), __float2half_rn(v.w));
    return H.u;
}
__device__ __forceinline__ float4 h4_to_f4(uint2 u) {
    union { uint2 uu; __half2 h2[2]; } U; U.uu = u;
    float2 lo = __half22float2(U.h2[0]);
    float2 hi = __half22float2(U.h2[1]);
    return make_float4(lo.x, lo.y, hi.x, hi.y);
}

// ================= fp16 1-term GEMM, CTA tile 128x256 =================
// C[M,N] = act(scale * A @ B^T + bias + resid)
// OUT: 0 = fp32 C; 2 = fp16
#define KC     64
#define SKB    72
#define A_TILE (128*SKB*2)          // 18432 B
#define B_TILE (256*SKB*2)          // 36864 B
#define STG    (A_TILE + B_TILE)    // 55296 B
#define SM1    (3*STG)              // 165888 B dynamic smem (3-stage cp.async)

template<bool HB, bool HR, int ACT, int OUT>
__global__ __launch_bounds__(256, 1) void tc_ghf(
    const __half* __restrict__ Ah, int lda,
    const __half* __restrict__ Bh, int ldb,
    const float* __restrict__ bias,
    const float* __restrict__ resid,
    float* __restrict__ C, __half* __restrict__ Cho, int ldc,
    int K, float scale,
    long aso, long asi, long bso, long bsi, long cso, long csi, int zinner)
{
    const int z  = blockIdx.z;
    const int zo = z / zinner;
    const int zi = z - zo * zinner;
    const size_t aofs = (size_t)zo * aso + (size_t)zi * asi;
    const size_t bofs = (size_t)zo * bso + (size_t)zi * bsi;
    const size_t cofs = (size_t)zo * cso + (size_t)zi * csi;
    Ah += aofs;
    Bh += bofs;

    extern __shared__ char dsm[];
    const uint32_t sb32 = smem_u32(dsm);

    const int tid  = threadIdx.x;
    const int wid  = tid >> 5;
    const int lane = tid & 31;
    const int wr   = wid & 3;       // row band (32 rows)
    const int wc   = wid >> 2;      // col band (128 cols)
    const int row0 = blockIdx.y * 128;
    const int col0 = blockIdx.x * 256;

    // loader: each 16B chunk covers 8 halves; A has 1024 chunks, B has 2048
    const int lr0 = tid >> 3;            // A: base row, stride 32, 4 iters
    const int lc8 = (tid & 7) << 3;      // col in halves

    const __half* A0 = Ah + (size_t)row0 * lda;
    const __half* B0 = Bh + (size_t)col0 * ldb;

    float acc[2][16][4];
    #pragma unroll
    for (int mt = 0; mt < 2; mt++)
        #pragma unroll
        for (int nt = 0; nt < 16; nt++)
            #pragma unroll
            for (int j = 0; j < 4; j++) acc[mt][nt][j] = 0.0f;

    const int nc = K / KC;

    // ---- stage loader (cp.async) ----
    auto load_stage = [&](int stg, int k0) {
        uint32_t base = sb32 + (uint32_t)stg * STG;
        #pragma unroll
        for (int it = 0; it < 4; it++) {
            int r = lr0 + it * 32;
            cpa16(base + (uint32_t)(r * SKB + lc8) * 2, A0 + (size_t)r * lda + k0 + lc8);
        }
        #pragma unroll
        for (int it = 0; it < 8; it++) {
            int r = lr0 + it * 32;
            cpa16(base + A_TILE + (uint32_t)(r * SKB + lc8) * 2, B0 + (size_t)r * ldb + k0 + lc8);
        }
    };

    load_stage(0, 0);
    CP_COMMIT();
    if (nc > 1) load_stage(1, KC);
    CP_COMMIT();

    const int ro = lane & 15;
    const int co = (lane >> 4) << 3;

    for (int c = 0; c < nc; c++) {
        CP_WAIT1();
        __syncthreads();

        if (c + 2 < nc) load_stage((c + 2) % 3, (c + 2) * KC);
        CP_COMMIT();

        const uint32_t sOff = sb32 + (uint32_t)(c % 3) * STG;
        #pragma unroll
        for (int ks = 0; ks < 4; ks++) {
            const int k0 = ks * 16;
            uint32_t ah[2][4];
            #pragma unroll
            for (int mt = 0; mt < 2; mt++) {
                uint32_t off = (uint32_t)((32*wr + 16*mt + ro) * SKB + k0 + co) * 2;
                ldsm4(ah[mt], sOff + off);
            }
            uint32_t bh[16][2];
            #pragma unroll
            for (int p = 0; p < 8; p++) {
                uint32_t off = (uint32_t)((128*wc + 16*p + ro) * SKB + k0 + co) * 2;
                uint32_t r[4];
                ldsm4(r, sOff + A_TILE + off);
                bh[2*p][0] = r[0];   bh[2*p][1] = r[2];
                bh[2*p+1][0] = r[1]; bh[2*p+1][1] = r[3];
            }
            #pragma unroll
            for (int mt = 0; mt < 2; mt++)
                #pragma unroll
                for (int nt = 0; nt < 16; nt++)
                    mma_hf(acc[mt][nt], ah[mt], bh[nt]);
        }
        __syncthreads();
    }

    // ---- epilogue ----
    float*  Cp  = (OUT == 0) ? C + cofs : nullptr;
    __half* ChH = (OUT == 2) ? Cho + cofs : nullptr;
    const float* R = HR ? resid : nullptr;

    #pragma unroll
    for (int mt = 0; mt < 2; mt++) {
        #pragma unroll
        for (int nt = 0; nt < 16; nt++) {
            const int r0 = row0 + 32*wr + 16*mt + (lane >> 2);
            const int cc = col0 + 128*wc + 8*nt + 2*(lane & 3);
            float2 bv = make_float2(0.f, 0.f);
            if (HB) bv = *(const float2*)&bias[cc];
            #pragma unroll
            for (int hh = 0; hh < 2; hh++) {
                const int r = r0 + hh * 8;
                float v0 = acc[mt][nt][2*hh]     * scale;
                float v1 = acc[mt][nt][2*hh + 1] * scale;
                if (HB) { v0 += bv.x; v1 += bv.y; }
                if (HR) {
                    float2 rv = *(const float2*)&R[(size_t)r * ldc + cc];
                    v0 += rv.x; v1 += rv.y;
                }
                if (ACT == 1) { v0 = gelu_exact(v0); v1 = gelu_exact(v1); }
                if (OUT == 0) {
                    *(float2*)&Cp[(size_t)r * ldc + cc] = make_float2(v0, v1);
                } else {
                    *(__half2*)&ChH[(size_t)r * ldc + cc] =
                        __halves2half2(__float2half_rn(v0), __float2half_rn(v1));
                }
            }
        }
    }
}

// ---------------- converter: fp32 -> fp16 ----------------
__global__ __launch_bounds__(256) void conv_hf_kernel(const float4* __restrict__ src,
                                                      uint2* __restrict__ h, int n4)
{
    int i = blockIdx.x * 256 + threadIdx.x;
    if (i < n4) h[i] = conv4h(src[i]);
}

// ---------------- V transpose: fp16 qkv -> fp16 Vt ----------------
__global__ __launch_bounds__(256) void transpose_v(const __half* __restrict__ qv,
                                                   __half* __restrict__ vt)
{
    __shared__ __half t[32][34];
    const int bh = blockIdx.z, b = bh / Hc, h = bh % Hc;
    const int q0 = blockIdx.x * 32, d0 = blockIdx.y * 32;
    const int tx = threadIdx.x & 31, ty = threadIdx.x >> 5;
    const size_t so = (size_t)b * Lc * D3c + 2 * Dc + h * HDc;
    #pragma unroll
    for (int i = ty; i < 32; i += 8)
        t[i][tx] = qv[so + (size_t)(q0 + i) * D3c + d0 + tx];
    __syncthreads();
    const size_t dofs = (size_t)bh * HDc * Lc;
    #pragma unroll
    for (int i = ty; i < 32; i += 8)
        vt[dofs + (size_t)(d0 + i) * Lc + q0 + tx] = t[tx][i];
}

// ---------------- layernorm: fp32 in; OMODE 0 = fp32 out, 1 = fp16 out ----------------
template<int OMODE>
__global__ __launch_bounds__(256)
void layernorm_kernel(const float* __restrict__ x, const float* __restrict__ g,
                      const float* __restrict__ b,
                      float* __restrict__ outF, __half* __restrict__ outH)
{
    const int row = blockIdx.x;
    const int t   = threadIdx.x;
    const float4 v = ((const float4*)(x + (size_t)row * Dc))[t];

    float s1 = v.x + v.y + v.z + v.w;
    float s2 = v.x*v.x + v.y*v.y + v.z*v.z + v.w*v.w;

    __shared__ float sh1[8], sh2[8];
    #pragma unroll
    for (int o = 16; o > 0; o >>= 1) {
        s1 += __shfl_down_sync(0xffffffffu, s1, o);
        s2 += __shfl_down_sync(0xffffffffu, s2, o);
    }
    if ((t & 31) == 0) { sh1[t >> 5] = s1; sh2[t >> 5] = s2; }
    __syncthreads();
    if (t < 8) {
        s1 = sh1[t]; s2 = sh2[t];
        #pragma unroll
        for (int o = 4; o > 0; o >>= 1) {
            s1 += __shfl_down_sync(0xffu, s1, o);
            s2 += __shfl_down_sync(0xffu, s2, o);
        }
        if (t == 0) { sh1[0] = s1; sh2[0] = s2; }
    }
    __syncthreads();

    const float mean = sh1[0] * (1.0f / Dc);
    const float var  = sh2[0] * (1.0f / Dc) - mean * mean;
    const float rstd = rsqrtf(var + 1e-5f);

    const float4 gv = ((const float4*)g)[t];
    const float4 bv = ((const float4*)b)[t];
    float4 r;
    r.x = (v.x - mean) * rstd * gv.x + bv.x;
    r.y = (v.y - mean) * rstd * gv.y + bv.y;
    r.z = (v.z - mean) * rstd * gv.z + bv.z;
    r.w = (v.w - mean) * rstd * gv.w + bv.w;
    if (OMODE == 1) {
        ((uint2*)(outH + (size_t)row * Dc))[t] = conv4h(r);
    } else {
        ((float4*)(outF + (size_t)row * Dc))[t] = r;
    }
}

// ---------------- softmax: fp16 logits in, fp16 probs out (in place) ----------------
__global__ __launch_bounds__(256)
void softmax_kernel(__half* __restrict__ pp)
{
    const size_t row = blockIdx.x;
    uint2* p = (uint2*)(pp + row * (size_t)Lc);
    const int t = threadIdx.x;

    float4 a = h4_to_f4(p[t]);
    float4 c = h4_to_f4(p[t + 256]);

    float mx = fmaxf(fmaxf(fmaxf(a.x, a.y), fmaxf(a.z, a.w)),
                     fmaxf(fmaxf(c.x, c.y), fmaxf(c.z, c.w)));

    __shared__ float sh[8];
    #pragma unroll
    for (int o = 16; o > 0; o >>= 1) mx = fmaxf(mx, __shfl_down_sync(0xffffffffu, mx, o));
    if ((t & 31) == 0) sh[t >> 5] = mx;
    __syncthreads();
    if (t < 8) {
        mx = sh[t];
        #pragma unroll
        for (int o = 4; o > 0; o >>= 1) mx = fmaxf(mx, __shfl_down_sync(0xffu, mx, o));
        if (t == 0) sh[0] = mx;
    }
    __syncthreads();
    mx = sh[0];
    __syncthreads();

    a.x = expf(a.x - mx); a.y = expf(a.y - mx); a.z = expf(a.z - mx); a.w = expf(a.w - mx);
    c.x = expf(c.x - mx); c.y = expf(c.y - mx); c.z = expf(c.z - mx); c.w = expf(c.w - mx);

    float sm = a.x + a.y + a.z + a.w + c.x + c.y + c.z + c.w;
    #pragma unroll
    for (int o = 16; o > 0; o >>= 1) sm += __shfl_down_sync(0xffffffffu, sm, o);
    if ((t & 31) == 0) sh[t >> 5] = sm;
    __syncthreads();
    if (t < 8) {
        sm = sh[t];
        #pragma unroll
        for (int o = 4; o > 0; o >>= 1) sm += __shfl_down_sync(0xffu, sm, o);
        if (t == 0) sh[0] = sm;
    }
    __syncthreads();
    const float inv = 1.0f / sh[0];

    a.x *= inv; a.y *= inv; a.z *= inv; a.w *= inv;
    c.x *= inv; c.y *= inv; c.z *= inv; c.w *= inv;

    p[t]       = conv4h(a);
    p[t + 256] = conv4h(c);
}

// ---------------- host side ----------------
static void do_conv_hf(const float* src, __half* h, size_t n) {
    int n4 = (int)(n / 4);
    conv_hf_kernel<<<(n4 + 255) / 256, 256>>>((const float4*)src, (uint2*)h, n4);
}

extern "C" void kernel_launch(void* const* d_in, const int* in_sizes, int n_in,
                              void* d_out, int out_size)
{
    const float* x    = (const float*)d_in[0];
    const float* w3d  = (const float*)d_in[1];
    const float* b3d  = (const float*)d_in[2];
    const float* ln1g = (const float*)d_in[3];
    const float* ln1b = (const float*)d_in[4];
    const float* wqkv = (const float*)d_in[5];
    const float* bqkv = (const float*)d_in[6];
    const float* wprj = (const float*)d_in[7];
    const float* bprj = (const float*)d_in[8];
    const float* ln2g = (const float*)d_in[9];
    const float* ln2b = (const float*)d_in[10];
    const float* w1   = (const float*)d_in[11];
    const float* b1   = (const float*)d_in[12];
    const float* w2   = (const float*)d_in[13];
    const float* b2   = (const float*)d_in[14];
    const float* lnfg = (const float*)d_in[15];
    const float* lnfb = (const float*)d_in[16];
    float* out = (float*)d_out;

    float *h;
    __half *xp,*w3,*hn,*wq,*wp,*w1p,*w2p,*qv,*vt,*pp,*op,*fp;
    cudaGetSymbolAddress((void**)&h,   g_h);
    cudaGetSymbolAddress((void**)&xp,  g_x);
    cudaGetSymbolAddress((void**)&w3,  g_w3);
    cudaGetSymbolAddress((void**)&hn,  g_hn);
    cudaGetSymbolAddress((void**)&wq,  g_wq);
    cudaGetSymbolAddress((void**)&wp,  g_wp);
    cudaGetSymbolAddress((void**)&w1p, g_w1);
    cudaGetSymbolAddress((void**)&w2p, g_w2);
    cudaGetSymbolAddress((void**)&qv,  g_qv);
    cudaGetSymbolAddress((void**)&vt,  g_vt);
    cudaGetSymbolAddress((void**)&pp,  g_p);
    cudaGetSymbolAddress((void**)&op,  g_o);
    cudaGetSymbolAddress((void**)&fp,  g_f);

    cudaFuncSetAttribute(tc_ghf<true,false,0,0>,  cudaFuncAttributeMaxDynamicSharedMemorySize, SM1);
    cudaFuncSetAttribute(tc_ghf<true,false,0,2>,  cudaFuncAttributeMaxDynamicSharedMemorySize, SM1);
    cudaFuncSetAttribute(tc_ghf<false,false,0,2>, cudaFuncAttributeMaxDynamicSharedMemorySize, SM1);
    cudaFuncSetAttribute(tc_ghf<true,true,0,0>,   cudaFuncAttributeMaxDynamicSharedMemorySize, SM1);
    cudaFuncSetAttribute(tc_ghf<true,false,1,2>,  cudaFuncAttributeMaxDynamicSharedMemorySize, SM1);

    const dim3 blk(256);

    // one-time conversions
    do_conv_hf(x,   xp, (size_t)Mc * D3c);
    do_conv_hf(w3d, w3, (size_t)Dc * D3c);

    // ---- embed: h = x @ w3d^T + b3d ----
    tc_ghf<true,false,0,0><<<dim3(Dc/256, Mc/128, 1), blk, SM1>>>(
        xp, D3c, w3, D3c, b3d, nullptr,
        h, nullptr, Dc, D3c, 1.0f, 0,0,0,0,0,0, 1);

    for (int i = 0; i < NLc; i++) {
        do_conv_hf(wqkv + (size_t)i*D3c*Dc, wq, (size_t)D3c*Dc);

        layernorm_kernel<1><<<Mc, blk>>>(h, ln1g + (size_t)i*Dc, ln1b + (size_t)i*Dc,
                                         nullptr, hn);

        // qkv = hn @ wqkv^T + bqkv -> fp16
        tc_ghf<true,false,0,2><<<dim3(D3c/256, Mc/128, 1), blk, SM1>>>(
            hn, Dc, wq, Dc, bqkv + (size_t)i*D3c, nullptr,
            nullptr, qv, D3c, Dc, 1.0f, 0,0,0,0,0,0, 1);

        transpose_v<<<dim3(Lc/32, HDc/32, Bc*Hc), blk>>>(qv, vt);

        // logits = scale * Q @ K^T -> fp16 (into g_p)
        tc_ghf<false,false,0,2><<<dim3(Lc/256, Lc/128, Bc*Hc), blk, SM1>>>(
            qv, D3c,
            qv + Dc, D3c,
            nullptr, nullptr,
            nullptr, pp, Lc, HDc, 0.0625f,
            (long)Lc*D3c, (long)HDc,
            (long)Lc*D3c, (long)HDc,
            (long)Hc*Lc*Lc, (long)Lc*Lc,
            Hc);

        softmax_kernel<<<Bc*Hc*Lc, blk>>>(pp);   // in place

        // o = P @ Vt^T -> fp16
        tc_ghf<false,false,0,2><<<dim3(HDc/256, Lc/128, Bc*Hc), blk, SM1>>>(
            pp, Lc,
            vt, Lc,
            nullptr, nullptr,
            nullptr, op, Dc, Lc, 1.0f,
            (long)Hc*Lc*Lc, (long)Lc*Lc,
            (long)Hc*HDc*Lc, (long)HDc*Lc,
            (long)Lc*Dc, (long)HDc,
            Hc);

        do_conv_hf(wprj + (size_t)i*Dc*Dc, wp, (size_t)Dc*Dc);

        // h = h + o @ wproj^T + bproj
        tc_ghf<true,true,0,0><<<dim3(Dc/256, Mc/128, 1), blk, SM1>>>(
            op, Dc, wp, Dc, bprj + (size_t)i*Dc, h,
            h, nullptr, Dc, Dc, 1.0f, 0,0,0,0,0,0, 1);

        layernorm_kernel<1><<<Mc, blk>>>(h, ln2g + (size_t)i*Dc, ln2b + (size_t)i*Dc,
                                         nullptr, hn);

        do_conv_hf(w1 + (size_t)i*FFc*Dc, w1p, (size_t)FFc*Dc);

        // f = gelu(hn @ w1^T + b1) -> fp16
        tc_ghf<true,false,1,2><<<dim3(FFc/256, Mc/128, 1), blk, SM1>>>(
            hn, Dc, w1p, Dc, b1 + (size_t)i*FFc, nullptr,
            nullptr, fp, FFc, Dc, 1.0f, 0,0,0,0,0,0, 1);

        do_conv_hf(w2 + (size_t)i*Dc*FFc, w2p, (size_t)Dc*FFc);

        // h = h + f @ w2^T + b2
        tc_ghf<true,true,0,0><<<dim3(Dc/256, Mc/128, 1), blk, SM1>>>(
            fp, FFc, w2p, FFc, b2 + (size_t)i*Dc, h,
            h, nullptr, Dc, FFc, 1.0f, 0,0,0,0,0,0, 1);
    }

    layernorm_kernel<0><<<Mc, blk>>>(h, lnfg, lnfb, out, nullptr);
}

// round 12
// speedup vs baseline: 3.0097x; 1.0104x over previous
#include <cuda_runtime.h>
#include <cuda_fp16.h>
#include <math.h>
#include <stdint.h>

// ---------------- problem constants ----------------
#define Bc   4
#define Lc   2048
#define Dc   1024
#define Hc   4
#define HDc  256
#define NLc  2
#define FFc  4096
#define Mc   (Bc*Lc)     // 8192 tokens
#define D3c  (3*Dc)      // 3072

// ---------------- device scratch (static; no allocations) ----------------
__device__ __align__(16) __half g_h  [(size_t)Mc*Dc];        // residual fp16
__device__ __align__(16) __half g_x  [(size_t)Mc*D3c];
__device__ __align__(16) __half g_w3 [(size_t)Dc*D3c];
__device__ __align__(16) __half g_hn [(size_t)Mc*Dc];
__device__ __align__(16) __half g_wq [(size_t)D3c*Dc];
__device__ __align__(16) __half g_wp [(size_t)Dc*Dc];
__device__ __align__(16) __half g_w1 [(size_t)FFc*Dc];
__device__ __align__(16) __half g_w2 [(size_t)Dc*FFc];
__device__ __align__(16) __half g_qv [(size_t)Mc*D3c];
__device__ __align__(16) __half g_vt [(size_t)Bc*Hc*HDc*Lc];
__device__ __align__(16) __half g_p  [(size_t)Bc*Hc*Lc*Lc];  // logits -> probs in place
__device__ __align__(16) __half g_o  [(size_t)Mc*Dc];
__device__ __align__(16) __half g_f  [(size_t)Mc*FFc];

// ---------------- helpers ----------------
__device__ __forceinline__ uint32_t smem_u32(const void* p) {
    uint32_t a;
    asm("{ .reg .u64 t; cvta.to.shared.u64 t, %1; cvt.u32.u64 %0, t; }" : "=r"(a) : "l"(p));
    return a;
}
__device__ __forceinline__ void ldsm4(uint32_t* r, uint32_t addr) {
    asm volatile("ldmatrix.sync.aligned.m8n8.x4.shared.b16 {%0,%1,%2,%3}, [%4];"
        : "=r"(r[0]), "=r"(r[1]), "=r"(r[2]), "=r"(r[3]) : "r"(addr));
}
__device__ __forceinline__ void mma_hf(float* d, const uint32_t* a, const uint32_t* b) {
    asm volatile(
        "mma.sync.aligned.m16n8k16.row.col.f32.f16.f16.f32 "
        "{%0,%1,%2,%3}, {%4,%5,%6,%7}, {%8,%9}, {%0,%1,%2,%3};"
        : "+f"(d[0]), "+f"(d[1]), "+f"(d[2]), "+f"(d[3])
        : "r"(a[0]), "r"(a[1]), "r"(a[2]), "r"(a[3]), "r"(b[0]), "r"(b[1]));
}
__device__ __forceinline__ void cpa16(uint32_t dst, const void* src) {
    asm volatile("cp.async.cg.shared.global [%0], [%1], 16;" :: "r"(dst), "l"(src));
}
#define CP_COMMIT() asm volatile("cp.async.commit_group;" ::: "memory")
#define CP_WAIT1()  asm volatile("cp.async.wait_group 1;"  ::: "memory")

__device__ __forceinline__ float gelu_exact(float x) {
    return 0.5f * x * (1.0f + erff(x * 0.70710678118654752440f));
}
__device__ __forceinline__ uint2 conv4h(float4 v) {
    union { __half2 h2[2]; uint2 u; } H;
    H.h2[0] = __halves2half2(__float2half_rn(v.x), __float2half_rn(v.y));
    H.h2[1] = __halves2half2(__float2half_rn(v.z), __float2half_rn(v.w));
    return H.u;
}
__device__ __forceinline__ float4 h4_to_f4(uint2 u) {
    union { uint2 uu; __half2 h2[2]; } U; U.uu = u;
    float2 lo = __half22float2(U.h2[0]);
    float2 hi = __half22float2(U.h2[1]);
    return make_float4(lo.x, lo.y, hi.x, hi.y);
}

// ================= fp16 1-term GEMM, CTA tile 128x256, fp16 out =================
// C[M,N] = act(scale * A @ B^T + bias + resid)
#define KC     64
#define SKB    72
#define A_TILE (128*SKB*2)          // 18432 B
#define B_TILE (256*SKB*2)          // 36864 B
#define STG    (A_TILE + B_TILE)    // 55296 B
#define SM1    (3*STG)              // 165888 B dynamic smem (3-stage cp.async)

template<bool HB, bool HR, int ACT>
__global__ __launch_bounds__(256, 1) void tc_ghf(
    const __half* __restrict__ Ah, int lda,
    const __half* __restrict__ Bh, int ldb,
    const float* __restrict__ bias,
    const __half* __restrict__ resid,
    __half* __restrict__ Cho, int ldc,
    int K, float scale,
    long aso, long asi, long bso, long bsi, long cso, long csi, int zinner)
{
    const int z  = blockIdx.z;
    const int zo = z / zinner;
    const int zi = z - zo * zinner;
    const size_t aofs = (size_t)zo * aso + (size_t)zi * asi;
    const size_t bofs = (size_t)zo * bso + (size_t)zi * bsi;
    const size_t cofs = (size_t)zo * cso + (size_t)zi * csi;
    Ah += aofs;
    Bh += bofs;

    extern __shared__ char dsm[];
    const uint32_t sb32 = smem_u32(dsm);

    const int tid  = threadIdx.x;
    const int wid  = tid >> 5;
    const int lane = tid & 31;
    const int wr   = wid & 3;       // row band (32 rows)
    const int wc   = wid >> 2;      // col band (128 cols)
    const int row0 = blockIdx.y * 128;
    const int col0 = blockIdx.x * 256;

    const int lr0 = tid >> 3;            // loader base row (stride 32)
    const int lc8 = (tid & 7) << 3;      // col in halves

    const __half* A0 = Ah + (size_t)row0 * lda;
    const __half* B0 = Bh + (size_t)col0 * ldb;

    float acc[2][16][4];
    #pragma unroll
    for (int mt = 0; mt < 2; mt++)
        #pragma unroll
        for (int nt = 0; nt < 16; nt++)
            #pragma unroll
            for (int j = 0; j < 4; j++) acc[mt][nt][j] = 0.0f;

    const int nc = K / KC;

    auto load_stage = [&](int stg, int k0) {
        uint32_t base = sb32 + (uint32_t)stg * STG;
        #pragma unroll
        for (int it = 0; it < 4; it++) {
            int r = lr0 + it * 32;
            cpa16(base + (uint32_t)(r * SKB + lc8) * 2, A0 + (size_t)r * lda + k0 + lc8);
        }
        #pragma unroll
        for (int it = 0; it < 8; it++) {
            int r = lr0 + it * 32;
            cpa16(base + A_TILE + (uint32_t)(r * SKB + lc8) * 2, B0 + (size_t)r * ldb + k0 + lc8);
        }
    };

    load_stage(0, 0);
    CP_COMMIT();
    if (nc > 1) load_stage(1, KC);
    CP_COMMIT();

    const int ro = lane & 15;
    const int co = (lane >> 4) << 3;

    for (int c = 0; c < nc; c++) {
        CP_WAIT1();
        __syncthreads();

        if (c + 2 < nc) load_stage((c + 2) % 3, (c + 2) * KC);
        CP_COMMIT();

        const uint32_t sOff = sb32 + (uint32_t)(c % 3) * STG;
        #pragma unroll
        for (int ks = 0; ks < 4; ks++) {
            const int k0 = ks * 16;
            uint32_t ah[2][4];
            #pragma unroll
            for (int mt = 0; mt < 2; mt++) {
                uint32_t off = (uint32_t)((32*wr + 16*mt + ro) * SKB + k0 + co) * 2;
                ldsm4(ah[mt], sOff + off);
            }
            uint32_t bh[16][2];
            #pragma unroll
            for (int p = 0; p < 8; p++) {
                uint32_t off = (uint32_t)((128*wc + 16*p + ro) * SKB + k0 + co) * 2;
                uint32_t r[4];
                ldsm4(r, sOff + A_TILE + off);
                bh[2*p][0] = r[0];   bh[2*p][1] = r[2];
                bh[2*p+1][0] = r[1]; bh[2*p+1][1] = r[3];
            }
            #pragma unroll
            for (int mt = 0; mt < 2; mt++)
                #pragma unroll
                for (int nt = 0; nt < 16; nt++)
                    mma_hf(acc[mt][nt], ah[mt], bh[nt]);
        }
        __syncthreads();
    }

    // ---- epilogue ----
    __half* Ch = Cho + cofs;
    const __half* R = HR ? resid + cofs : nullptr;

    #pragma unroll
    for (int mt = 0; mt < 2; mt++) {
        #pragma unroll
        for (int nt = 0; nt < 16; nt++) {
            const int r0 = row0 + 32*wr + 16*mt + (lane >> 2);
            const int cc = col0 + 128*wc + 8*nt + 2*(lane & 3);
            float2 bv = make_float2(0.f, 0.f);
            if (HB) bv = *(const float2*)&bias[cc];
            #pragma unroll
            for (int hh = 0; hh < 2; hh++) {
                const int r = r0 + hh * 8;
                float v0 = acc[mt][nt][2*hh]     * scale;
                float v1 = acc[mt][nt][2*hh + 1] * scale;
                if (HB) { v0 += bv.x; v1 += bv.y; }
                if (HR) {
                    float2 rv = __half22float2(*(const __half2*)&R[(size_t)r * ldc + cc]);
                    v0 += rv.x; v1 += rv.y;
                }
                if (ACT == 1) { v0 = gelu_exact(v0); v1 = gelu_exact(v1); }
                *(__half2*)&Ch[(size_t)r * ldc + cc] =
                    __halves2half2(__float2half_rn(v0), __float2half_rn(v1));
            }
        }
    }
}

// ---------------- converter: fp32 -> fp16 ----------------
__global__ __launch_bounds__(256) void conv_hf_kernel(const float4* __restrict__ src,
                                                      uint2* __restrict__ h, int n4)
{
    int i = blockIdx.x * 256 + threadIdx.x;
    if (i < n4) h[i] = conv4h(src[i]);
}

// ---------------- V transpose: fp16 qkv -> fp16 Vt ----------------
__global__ __launch_bounds__(256) void transpose_v(const __half* __restrict__ qv,
                                                   __half* __restrict__ vt)
{
    __shared__ __half t[32][34];
    const int bh = blockIdx.z, b = bh / Hc, h = bh % Hc;
    const int q0 = blockIdx.x * 32, d0 = blockIdx.y * 32;
    const int tx = threadIdx.x & 31, ty = threadIdx.x >> 5;
    const size_t so = (size_t)b * Lc * D3c + 2 * Dc + h * HDc;
    #pragma unroll
    for (int i = ty; i < 32; i += 8)
        t[i][tx] = qv[so + (size_t)(q0 + i) * D3c + d0 + tx];
    __syncthreads();
    const size_t dofs = (size_t)bh * HDc * Lc;
    #pragma unroll
    for (int i = ty; i < 32; i += 8)
        vt[dofs + (size_t)(d0 + i) * Lc + q0 + tx] = t[tx][i];
}

// ---------------- layernorm: fp16 in; OMODE 0 = fp32 out, 1 = fp16 out ----------------
template<int OMODE>
__global__ __launch_bounds__(256)
void layernorm_kernel(const __half* __restrict__ x, const float* __restrict__ g,
                      const float* __restrict__ b,
                      float* __restrict__ outF, __half* __restrict__ outH)
{
    const int row = blockIdx.x;
    const int t   = threadIdx.x;
    const float4 v = h4_to_f4(((const uint2*)(x + (size_t)row * Dc))[t]);

    float s1 = v.x + v.y + v.z + v.w;
    float s2 = v.x*v.x + v.y*v.y + v.z*v.z + v.w*v.w;

    __shared__ float sh1[8], sh2[8];
    #pragma unroll
    for (int o = 16; o > 0; o >>= 1) {
        s1 += __shfl_down_sync(0xffffffffu, s1, o);
        s2 += __shfl_down_sync(0xffffffffu, s2, o);
    }
    if ((t & 31) == 0) { sh1[t >> 5] = s1; sh2[t >> 5] = s2; }
    __syncthreads();
    if (t < 8) {
        s1 = sh1[t]; s2 = sh2[t];
        #pragma unroll
        for (int o = 4; o > 0; o >>= 1) {
            s1 += __shfl_down_sync(0xffu, s1, o);
            s2 += __shfl_down_sync(0xffu, s2, o);
        }
        if (t == 0) { sh1[0] = s1; sh2[0] = s2; }
    }
    __syncthreads();

    const float mean = sh1[0] * (1.0f / Dc);
    const float var  = sh2[0] * (1.0f / Dc) - mean * mean;
    const float rstd = rsqrtf(var + 1e-5f);

    const float4 gv = ((const float4*)g)[t];
    const float4 bv = ((const float4*)b)[t];
    float4 r;
    r.x = (v.x - mean) * rstd * gv.x + bv.x;
    r.y = (v.y - mean) * rstd * gv.y + bv.y;
    r.z = (v.z - mean) * rstd * gv.z + bv.z;
    r.w = (v.w - mean) * rstd * gv.w + bv.w;
    if (OMODE == 1) {
        ((uint2*)(outH + (size_t)row * Dc))[t] = conv4h(r);
    } else {
        ((float4*)(outF + (size_t)row * Dc))[t] = r;
    }
}

// ---------------- softmax: fp16 logits in, fp16 probs out (in place) ----------------
__global__ __launch_bounds__(256)
void softmax_kernel(__half* __restrict__ pp)
{
    const size_t row = blockIdx.x;
    uint2* p = (uint2*)(pp + row * (size_t)Lc);
    const int t = threadIdx.x;

    float4 a = h4_to_f4(p[t]);
    float4 c = h4_to_f4(p[t + 256]);

    float mx = fmaxf(fmaxf(fmaxf(a.x, a.y), fmaxf(a.z, a.w)),
                     fmaxf(fmaxf(c.x, c.y), fmaxf(c.z, c.w)));

    __shared__ float sh[8];
    #pragma unroll
    for (int o = 16; o > 0; o >>= 1) mx = fmaxf(mx, __shfl_down_sync(0xffffffffu, mx, o));
    if ((t & 31) == 0) sh[t >> 5] = mx;
    __syncthreads();
    if (t < 8) {
        mx = sh[t];
        #pragma unroll
        for (int o = 4; o > 0; o >>= 1) mx = fmaxf(mx, __shfl_down_sync(0xffu, mx, o));
        if (t == 0) sh[0] = mx;
    }
    __syncthreads();
    mx = sh[0];
    __syncthreads();

    a.x = __expf(a.x - mx); a.y = __expf(a.y - mx); a.z = __expf(a.z - mx); a.w = __expf(a.w - mx);
    c.x = __expf(c.x - mx); c.y = __expf(c.y - mx); c.z = __expf(c.z - mx); c.w = __expf(c.w - mx);

    float sm = a.x + a.y + a.z + a.w + c.x + c.y + c.z + c.w;
    #pragma unroll
    for (int o = 16; o > 0; o >>= 1) sm += __shfl_down_sync(0xffffffffu, sm, o);
    if ((t & 31) == 0) sh[t >> 5] = sm;
    __syncthreads();
    if (t < 8) {
        sm = sh[t];
        #pragma unroll
        for (int o = 4; o > 0; o >>= 1) sm += __shfl_down_sync(0xffu, sm, o);
        if (t == 0) sh[0] = sm;
    }
    __syncthreads();
    const float inv = 1.0f / sh[0];

    a.x *= inv; a.y *= inv; a.z *= inv; a.w *= inv;
    c.x *= inv; c.y *= inv; c.z *= inv; c.w *= inv;

    p[t]       = conv4h(a);
    p[t + 256] = conv4h(c);
}

// ---------------- host side ----------------
static void do_conv_hf(const float* src, __half* h, size_t n) {
    int n4 = (int)(n / 4);
    conv_hf_kernel<<<(n4 + 255) / 256, 256>>>((const float4*)src, (uint2*)h, n4);
}

extern "C" void kernel_launch(void* const* d_in, const int* in_sizes, int n_in,
                              void* d_out, int out_size)
{
    const float* x    = (const float*)d_in[0];
    const float* w3d  = (const float*)d_in[1];
    const float* b3d  = (const float*)d_in[2];
    const float* ln1g = (const float*)d_in[3];
    const float* ln1b = (const float*)d_in[4];
    const float* wqkv = (const float*)d_in[5];
    const float* bqkv = (const float*)d_in[6];
    const float* wprj = (const float*)d_in[7];
    const float* bprj = (const float*)d_in[8];
    const float* ln2g = (const float*)d_in[9];
    const float* ln2b = (const float*)d_in[10];
    const float* w1   = (const float*)d_in[11];
    const float* b1   = (const float*)d_in[12];
    const float* w2   = (const float*)d_in[13];
    const float* b2   = (const float*)d_in[14];
    const float* lnfg = (const float*)d_in[15];
    const float* lnfb = (const float*)d_in[16];
    float* out = (float*)d_out;

    __half *h,*xp,*w3,*hn,*wq,*wp,*w1p,*w2p,*qv,*vt,*pp,*op,*fp;
    cudaGetSymbolAddress((void**)&h,   g_h);
    cudaGetSymbolAddress((void**)&xp,  g_x);
    cudaGetSymbolAddress((void**)&w3,  g_w3);
    cudaGetSymbolAddress((void**)&hn,  g_hn);
    cudaGetSymbolAddress((void**)&wq,  g_wq);
    cudaGetSymbolAddress((void**)&wp,  g_wp);
    cudaGetSymbolAddress((void**)&w1p, g_w1);
    cudaGetSymbolAddress((void**)&w2p, g_w2);
    cudaGetSymbolAddress((void**)&qv,  g_qv);
    cudaGetSymbolAddress((void**)&vt,  g_vt);
    cudaGetSymbolAddress((void**)&pp,  g_p);
    cudaGetSymbolAddress((void**)&op,  g_o);
    cudaGetSymbolAddress((void**)&fp,  g_f);

    cudaFuncSetAttribute(tc_ghf<true,false,0>,  cudaFuncAttributeMaxDynamicSharedMemorySize, SM1);
    cudaFuncSetAttribute(tc_ghf<false,false,0>, cudaFuncAttributeMaxDynamicSharedMemorySize, SM1);
    cudaFuncSetAttribute(tc_ghf<true,true,0>,   cudaFuncAttributeMaxDynamicSharedMemorySize, SM1);
    cudaFuncSetAttribute(tc_ghf<true,false,1>,  cudaFuncAttributeMaxDynamicSharedMemorySize, SM1);

    const dim3 blk(256);

    // one-time conversions
    do_conv_hf(x,   xp, (size_t)Mc * D3c);
    do_conv_hf(w3d, w3, (size_t)Dc * D3c);

    // ---- embed: h = x @ w3d^T + b3d -> fp16 ----
    tc_ghf<true,false,0><<<dim3(Dc/256, Mc/128, 1), blk, SM1>>>(
        xp, D3c, w3, D3c, b3d, nullptr,
        h, Dc, D3c, 1.0f, 0,0,0,0,0,0, 1);

    for (int i = 0; i < NLc; i++) {
        do_conv_hf(wqkv + (size_t)i*D3c*Dc, wq, (size_t)D3c*Dc);

        layernorm_kernel<1><<<Mc, blk>>>(h, ln1g + (size_t)i*Dc, ln1b + (size_t)i*Dc,
                                         nullptr, hn);

        // qkv = hn @ wqkv^T + bqkv -> fp16
        tc_ghf<true,false,0><<<dim3(D3c/256, Mc/128, 1), blk, SM1>>>(
            hn, Dc, wq, Dc, bqkv + (size_t)i*D3c, nullptr,
            qv, D3c, Dc, 1.0f, 0,0,0,0,0,0, 1);

        transpose_v<<<dim3(Lc/32, HDc/32, Bc*Hc), blk>>>(qv, vt);

        // logits = scale * Q @ K^T -> fp16 (into g_p)
        tc_ghf<false,false,0><<<dim3(Lc/256, Lc/128, Bc*Hc), blk, SM1>>>(
            qv, D3c,
            qv + Dc, D3c,
            nullptr, nullptr,
            pp, Lc, HDc, 0.0625f,
            (long)Lc*D3c, (long)HDc,
            (long)Lc*D3c, (long)HDc,
            (long)Hc*Lc*Lc, (long)Lc*Lc,
            Hc);

        softmax_kernel<<<Bc*Hc*Lc, blk>>>(pp);   // in place

        // o = P @ Vt^T -> fp16
        tc_ghf<false,false,0><<<dim3(HDc/256, Lc/128, Bc*Hc), blk, SM1>>>(
            pp, Lc,
            vt, Lc,
            nullptr, nullptr,
            op, Dc, Lc, 1.0f,
            (long)Hc*Lc*Lc, (long)Lc*Lc,
            (long)Hc*HDc*Lc, (long)HDc*Lc,
            (long)Lc*Dc, (long)HDc,
            Hc);

        do_conv_hf(wprj + (size_t)i*Dc*Dc, wp, (size_t)Dc*Dc);

        // h = h + o @ wproj^T + bproj (in place on fp16 h)
        tc_ghf<true,true,0><<<dim3(Dc/256, Mc/128, 1), blk, SM1>>>(
            op, Dc, wp, Dc, bprj + (size_t)i*Dc, h,
            h, Dc, Dc, 1.0f, 0,0,0,0,0,0, 1);

        layernorm_kernel<1><<<Mc, blk>>>(h, ln2g + (size_t)i*Dc, ln2b + (size_t)i*Dc,
                                         nullptr, hn);

        do_conv_hf(w1 + (size_t)i*FFc*Dc, w1p, (size_t)FFc*Dc);

        // f = gelu(hn @ w1^T + b1) -> fp16
        tc_ghf<true,false,1><<<dim3(FFc/256, Mc/128, 1), blk, SM1>>>(
            hn, Dc, w1p, Dc, b1 + (size_t)i*FFc, nullptr,
            fp, FFc, Dc, 1.0f, 0,0,0,0,0,0, 1);

        do_conv_hf(w2 + (size_t)i*Dc*FFc, w2p, (size_t)Dc*FFc);

        // h = h + f @ w2^T + b2 (in place on fp16 h)
        tc_ghf<true,true,0><<<dim3(Dc/256, Mc/128, 1), blk, SM1>>>(
            fp, FFc, w2p, FFc, b2 + (size_t)i*Dc, h,
            h, Dc, FFc, 1.0f, 0,0,0,0,0,0, 1);
    }

    layernorm_kernel<0><<<Mc, blk>>>(h, lnfg, lnfb, out, nullptr);
}

// round 13
// speedup vs baseline: 3.0567x; 1.0156x over previous
#include <cuda_runtime.h>
#include <cuda_fp16.h>
#include <math.h>
#include <stdint.h>

// ---------------- problem constants ----------------
#define Bc   4
#define Lc   2048
#define Dc   1024
#define Hc   4
#define HDc  256
#define NLc  2
#define FFc  4096
#define Mc   (Bc*Lc)     // 8192 tokens
#define D3c  (3*Dc)      // 3072

// ---------------- device scratch (static; no allocations) ----------------
__device__ __align__(16) __half g_h  [(size_t)Mc*Dc];        // residual fp16
__device__ __align__(16) __half g_x  [(size_t)Mc*D3c];
__device__ __align__(16) __half g_w3 [(size_t)Dc*D3c];
__device__ __align__(16) __half g_hn [(size_t)Mc*Dc];
__device__ __align__(16) __half g_wq [(size_t)NLc*D3c*Dc];
__device__ __align__(16) __half g_wp [(size_t)NLc*Dc*Dc];
__device__ __align__(16) __half g_w1 [(size_t)NLc*FFc*Dc];
__device__ __align__(16) __half g_w2 [(size_t)NLc*Dc*FFc];
__device__ __align__(16) __half g_qv [(size_t)Mc*D3c];
__device__ __align__(16) __half g_vt [(size_t)Bc*Hc*HDc*Lc];
__device__ __align__(16) __half g_p  [(size_t)Bc*Hc*Lc*Lc];  // logits -> probs in place
__device__ __align__(16) __half g_o  [(size_t)Mc*Dc];
__device__ __align__(16) __half g_f  [(size_t)Mc*FFc];

// ---------------- helpers ----------------
__device__ __forceinline__ uint32_t smem_u32(const void* p) {
    uint32_t a;
    asm("{ .reg .u64 t; cvta.to.shared.u64 t, %1; cvt.u32.u64 %0, t; }" : "=r"(a) : "l"(p));
    return a;
}
__device__ __forceinline__ void ldsm4(uint32_t* r, uint32_t addr) {
    asm volatile("ldmatrix.sync.aligned.m8n8.x4.shared.b16 {%0,%1,%2,%3}, [%4];"
        : "=r"(r[0]), "=r"(r[1]), "=r"(r[2]), "=r"(r[3]) : "r"(addr));
}
__device__ __forceinline__ void mma_hf(float* d, const uint32_t* a, const uint32_t* b) {
    asm volatile(
        "mma.sync.aligned.m16n8k16.row.col.f32.f16.f16.f32 "
        "{%0,%1,%2,%3}, {%4,%5,%6,%7}, {%8,%9}, {%0,%1,%2,%3};"
        : "+f"(d[0]), "+f"(d[1]), "+f"(d[2]), "+f"(d[3])
        : "r"(a[0]), "r"(a[1]), "r"(a[2]), "r"(a[3]), "r"(b[0]), "r"(b[1]));
}
__device__ __forceinline__ void cpa16(uint32_t dst, const void* src) {
    asm volatile("cp.async.cg.shared.global [%0], [%1], 16;" :: "r"(dst), "l"(src));
}
#define CP_COMMIT() asm volatile("cp.async.commit_group;" ::: "memory")
#define CP_WAIT1()  asm volatile("cp.async.wait_group 1;"  ::: "memory")

__device__ __forceinline__ float gelu_exact(float x) {
    return 0.5f * x * (1.0f + erff(x * 0.70710678118654752440f));
}
__device__ __forceinline__ uint2 conv4h(float4 v) {
    union { __half2 h2[2]; uint2 u; } H;
    H.h2[0] = __halves2half2(__float2half_rn(v.x), __float2half_rn(v.y));
    H.h2[1] = __halves2half2(__float2half_rn(v.z), __float2half_rn(v.w));
    return H.u;
}
__device__ __forceinline__ float4 h4_to_f4(uint2 u) {
    union { uint2 uu; __half2 h2[2]; } U; U.uu = u;
    float2 lo = __half22float2(U.h2[0]);
    float2 hi = __half22float2(U.h2[1]);
    return make_float4(lo.x, lo.y, hi.x, hi.y);
}

// ================= fp16 1-term GEMM, CTA tile 128x256, fp16 out =================
#define KC     64
#define SKB    72
#define A_TILE (128*SKB*2)          // 18432 B
#define B_TILE (256*SKB*2)          // 36864 B
#define STG    (A_TILE + B_TILE)    // 55296 B
#define SM1    (3*STG)              // 165888 B dynamic smem

template<bool HB, bool HR, int ACT>
__global__ __launch_bounds__(256, 1) void tc_ghf(
    const __half* __restrict__ Ah, int lda,
    const __half* __restrict__ Bh, int ldb,
    const float* __restrict__ bias,
    const __half* __restrict__ resid,
    __half* __restrict__ Cho, int ldc,
    int K, float scale,
    long aso, long asi, long bso, long bsi, long cso, long csi, int zinner)
{
    const int z  = blockIdx.z;
    const int zo = z / zinner;
    const int zi = z - zo * zinner;
    const size_t aofs = (size_t)zo * aso + (size_t)zi * asi;
    const size_t bofs = (size_t)zo * bso + (size_t)zi * bsi;
    const size_t cofs = (size_t)zo * cso + (size_t)zi * csi;
    Ah += aofs;
    Bh += bofs;

    extern __shared__ char dsm[];
    const uint32_t sb32 = smem_u32(dsm);

    const int tid  = threadIdx.x;
    const int wid  = tid >> 5;
    const int lane = tid & 31;
    const int wr   = wid & 3;
    const int wc   = wid >> 2;
    const int row0 = blockIdx.y * 128;
    const int col0 = blockIdx.x * 256;

    const int lr0 = tid >> 3;
    const int lc8 = (tid & 7) << 3;

    const __half* A0 = Ah + (size_t)row0 * lda;
    const __half* B0 = Bh + (size_t)col0 * ldb;

    float acc[2][16][4];
    #pragma unroll
    for (int mt = 0; mt < 2; mt++)
        #pragma unroll
        for (int nt = 0; nt < 16; nt++)
            #pragma unroll
            for (int j = 0; j < 4; j++) acc[mt][nt][j] = 0.0f;

    const int nc = K / KC;

    auto load_stage = [&](int stg, int k0) {
        uint32_t base = sb32 + (uint32_t)stg * STG;
        #pragma unroll
        for (int it = 0; it < 4; it++) {
            int r = lr0 + it * 32;
            cpa16(base + (uint32_t)(r * SKB + lc8) * 2, A0 + (size_t)r * lda + k0 + lc8);
        }
        #pragma unroll
        for (int it = 0; it < 8; it++) {
            int r = lr0 + it * 32;
            cpa16(base + A_TILE + (uint32_t)(r * SKB + lc8) * 2, B0 + (size_t)r * ldb + k0 + lc8);
        }
    };

    load_stage(0, 0);
    CP_COMMIT();
    if (nc > 1) load_stage(1, KC);
    CP_COMMIT();

    const int ro = lane & 15;
    const int co = (lane >> 4) << 3;

    for (int c = 0; c < nc; c++) {
        CP_WAIT1();
        __syncthreads();

        if (c + 2 < nc) load_stage((c + 2) % 3, (c + 2) * KC);
        CP_COMMIT();

        const uint32_t sOff = sb32 + (uint32_t)(c % 3) * STG;
        #pragma unroll
        for (int ks = 0; ks < 4; ks++) {
            const int k0 = ks * 16;
            uint32_t ah[2][4];
            #pragma unroll
            for (int mt = 0; mt < 2; mt++) {
                uint32_t off = (uint32_t)((32*wr + 16*mt + ro) * SKB + k0 + co) * 2;
                ldsm4(ah[mt], sOff + off);
            }
            uint32_t bh[16][2];
            #pragma unroll
            for (int p = 0; p < 8; p++) {
                uint32_t off = (uint32_t)((128*wc + 16*p + ro) * SKB + k0 + co) * 2;
                uint32_t r[4];
                ldsm4(r, sOff + A_TILE + off);
                bh[2*p][0] = r[0];   bh[2*p][1] = r[2];
                bh[2*p+1][0] = r[1]; bh[2*p+1][1] = r[3];
            }
            #pragma unroll
            for (int mt = 0; mt < 2; mt++)
                #pragma unroll
                for (int nt = 0; nt < 16; nt++)
                    mma_hf(acc[mt][nt], ah[mt], bh[nt]);
        }
        __syncthreads();
    }

    // ---- epilogue ----
    __half* Ch = Cho + cofs;
    const __half* R = HR ? resid + cofs : nullptr;

    #pragma unroll
    for (int mt = 0; mt < 2; mt++) {
        #pragma unroll
        for (int nt = 0; nt < 16; nt++) {
            const int r0 = row0 + 32*wr + 16*mt + (lane >> 2);
            const int cc = col0 + 128*wc + 8*nt + 2*(lane & 3);
            float2 bv = make_float2(0.f, 0.f);
            if (HB) bv = *(const float2*)&bias[cc];
            #pragma unroll
            for (int hh = 0; hh < 2; hh++) {
                const int r = r0 + hh * 8;
                float v0 = acc[mt][nt][2*hh]     * scale;
                float v1 = acc[mt][nt][2*hh + 1] * scale;
                if (HB) { v0 += bv.x; v1 += bv.y; }
                if (HR) {
                    float2 rv = __half22float2(*(const __half2*)&R[(size_t)r * ldc + cc]);
                    v0 += rv.x; v1 += rv.y;
                }
                if (ACT == 1) { v0 = gelu_exact(v0); v1 = gelu_exact(v1); }
                *(__half2*)&Ch[(size_t)r * ldc + cc] =
                    __halves2half2(__float2half_rn(v0), __float2half_rn(v1));
            }
        }
    }
}

// ---------------- converter: fp32 -> fp16 ----------------
__global__ __launch_bounds__(256) void conv_hf_kernel(const float4* __restrict__ src,
                                                      uint2* __restrict__ h, int n4)
{
    int i = blockIdx.x * 256 + threadIdx.x;
    if (i < n4) h[i] = conv4h(src[i]);
}

// ---------------- V transpose: fp16 qkv -> fp16 Vt ----------------
__global__ __launch_bounds__(256) void transpose_v(const __half* __restrict__ qv,
                                                   __half* __restrict__ vt)
{
    __shared__ __half t[32][34];
    const int bh = blockIdx.z, b = bh / Hc, h = bh % Hc;
    const int q0 = blockIdx.x * 32, d0 = blockIdx.y * 32;
    const int tx = threadIdx.x & 31, ty = threadIdx.x >> 5;
    const size_t so = (size_t)b * Lc * D3c + 2 * Dc + h * HDc;
    #pragma unroll
    for (int i = ty; i < 32; i += 8)
        t[i][tx] = qv[so + (size_t)(q0 + i) * D3c + d0 + tx];
    __syncthreads();
    const size_t dofs = (size_t)bh * HDc * Lc;
    #pragma unroll
    for (int i = ty; i < 32; i += 8)
        vt[dofs + (size_t)(d0 + i) * Lc + q0 + tx] = t[tx][i];
}

// ---------------- layernorm: fp16 in; OMODE 0 = fp32 out, 1 = fp16 out ----------------
template<int OMODE>
__global__ __launch_bounds__(256)
void layernorm_kernel(const __half* __restrict__ x, const float* __restrict__ g,
                      const float* __restrict__ b,
                      float* __restrict__ outF, __half* __restrict__ outH)
{
    const int row = blockIdx.x;
    const int t   = threadIdx.x;
    const float4 v = h4_to_f4(((const uint2*)(x + (size_t)row * Dc))[t]);

    float s1 = v.x + v.y + v.z + v.w;
    float s2 = v.x*v.x + v.y*v.y + v.z*v.z + v.w*v.w;

    __shared__ float sh1[8], sh2[8];
    #pragma unroll
    for (int o = 16; o > 0; o >>= 1) {
        s1 += __shfl_down_sync(0xffffffffu, s1, o);
        s2 += __shfl_down_sync(0xffffffffu, s2, o);
    }
    if ((t & 31) == 0) { sh1[t >> 5] = s1; sh2[t >> 5] = s2; }
    __syncthreads();
    if (t < 8) {
        s1 = sh1[t]; s2 = sh2[t];
        #pragma unroll
        for (int o = 4; o > 0; o >>= 1) {
            s1 += __shfl_down_sync(0xffu, s1, o);
            s2 += __shfl_down_sync(0xffu, s2, o);
        }
        if (t == 0) { sh1[0] = s1; sh2[0] = s2; }
    }
    __syncthreads();

    const float mean = sh1[0] * (1.0f / Dc);
    const float var  = sh2[0] * (1.0f / Dc) - mean * mean;
    const float rstd = rsqrtf(var + 1e-5f);

    const float4 gv = ((const float4*)g)[t];
    const float4 bv = ((const float4*)b)[t];
    float4 r;
    r.x = (v.x - mean) * rstd * gv.x + bv.x;
    r.y = (v.y - mean) * rstd * gv.y + bv.y;
    r.z = (v.z - mean) * rstd * gv.z + bv.z;
    r.w = (v.w - mean) * rstd * gv.w + bv.w;
    if (OMODE == 1) {
        ((uint2*)(outH + (size_t)row * Dc))[t] = conv4h(r);
    } else {
        ((float4*)(outF + (size_t)row * Dc))[t] = r;
    }
}

// ---------------- softmax: fp16 logits in, fp16 probs out (in place) ----------------
__global__ __launch_bounds__(256)
void softmax_kernel(__half* __restrict__ pp)
{
    const size_t row = blockIdx.x;
    uint2* p = (uint2*)(pp + row * (size_t)Lc);
    const int t = threadIdx.x;

    float4 a = h4_to_f4(p[t]);
    float4 c = h4_to_f4(p[t + 256]);

    float mx = fmaxf(fmaxf(fmaxf(a.x, a.y), fmaxf(a.z, a.w)),
                     fmaxf(fmaxf(c.x, c.y), fmaxf(c.z, c.w)));

    __shared__ float sh[8];
    #pragma unroll
    for (int o = 16; o > 0; o >>= 1) mx = fmaxf(mx, __shfl_down_sync(0xffffffffu, mx, o));
    if ((t & 31) == 0) sh[t >> 5] = mx;
    __syncthreads();
    if (t < 8) {
        mx = sh[t];
        #pragma unroll
        for (int o = 4; o > 0; o >>= 1) mx = fmaxf(mx, __shfl_down_sync(0xffu, mx, o));
        if (t == 0) sh[0] = mx;
    }
    __syncthreads();
    mx = sh[0];
    __syncthreads();

    a.x = __expf(a.x - mx); a.y = __expf(a.y - mx); a.z = __expf(a.z - mx); a.w = __expf(a.w - mx);
    c.x = __expf(c.x - mx); c.y = __expf(c.y - mx); c.z = __expf(c.z - mx); c.w = __expf(c.w - mx);

    float sm = a.x + a.y + a.z + a.w + c.x + c.y + c.z + c.w;
    #pragma unroll
    for (int o = 16; o > 0; o >>= 1) sm += __shfl_down_sync(0xffffffffu, sm, o);
    if ((t & 31) == 0) sh[t >> 5] = sm;
    __syncthreads();
    if (t < 8) {
        sm = sh[t];
        #pragma unroll
        for (int o = 4; o > 0; o >>= 1) sm += __shfl_down_sync(0xffu, sm, o);
        if (t == 0) sh[0] = sm;
    }
    __syncthreads();
    const float inv = 1.0f / sh[0];

    a.x *= inv; a.y *= inv; a.z *= inv; a.w *= inv;
    c.x *= inv; c.y *= inv; c.z *= inv; c.w *= inv;

    p[t]       = conv4h(a);
    p[t + 256] = conv4h(c);
}

// ---------------- host side ----------------
static void conv_on(cudaStream_t s, const float* src, __half* h, size_t n) {
    int n4 = (int)(n / 4);
    conv_hf_kernel<<<(n4 + 255) / 256, 256, 0, s>>>((const float4*)src, (uint2*)h, n4);
}

extern "C" void kernel_launch(void* const* d_in, const int* in_sizes, int n_in,
                              void* d_out, int out_size)
{
    const float* x    = (const float*)d_in[0];
    const float* w3d  = (const float*)d_in[1];
    const float* b3d  = (const float*)d_in[2];
    const float* ln1g = (const float*)d_in[3];
    const float* ln1b = (const float*)d_in[4];
    const float* wqkv = (const float*)d_in[5];
    const float* bqkv = (const float*)d_in[6];
    const float* wprj = (const float*)d_in[7];
    const float* bprj = (const float*)d_in[8];
    const float* ln2g = (const float*)d_in[9];
    const float* ln2b = (const float*)d_in[10];
    const float* w1   = (const float*)d_in[11];
    const float* b1   = (const float*)d_in[12];
    const float* w2   = (const float*)d_in[13];
    const float* b2   = (const float*)d_in[14];
    const float* lnfg = (const float*)d_in[15];
    const float* lnfb = (const float*)d_in[16];
    float* out = (float*)d_out;

    __half *h,*xp,*w3,*hn,*wq,*wp,*w1p,*w2p,*qv,*vt,*pp,*op,*fp;
    cudaGetSymbolAddress((void**)&h,   g_h);
    cudaGetSymbolAddress((void**)&xp,  g_x);
    cudaGetSymbolAddress((void**)&w3,  g_w3);
    cudaGetSymbolAddress((void**)&hn,  g_hn);
    cudaGetSymbolAddress((void**)&wq,  g_wq);
    cudaGetSymbolAddress((void**)&wp,  g_wp);
    cudaGetSymbolAddress((void**)&w1p, g_w1);
    cudaGetSymbolAddress((void**)&w2p, g_w2);
    cudaGetSymbolAddress((void**)&qv,  g_qv);
    cudaGetSymbolAddress((void**)&vt,  g_vt);
    cudaGetSymbolAddress((void**)&pp,  g_p);
    cudaGetSymbolAddress((void**)&op,  g_o);
    cudaGetSymbolAddress((void**)&fp,  g_f);

    // one-time stream/event setup (created on the uncaptured correctness call)
    static cudaStream_t s2 = nullptr;
    static cudaEvent_t eFork = nullptr, eConv = nullptr, eQkv = nullptr, eVt = nullptr;
    static bool smem_set = false;
    if (!s2) {
        cudaStreamCreateWithFlags(&s2, cudaStreamNonBlocking);
        cudaEventCreateWithFlags(&eFork, cudaEventDisableTiming);
        cudaEventCreateWithFlags(&eConv, cudaEventDisableTiming);
        cudaEventCreateWithFlags(&eQkv,  cudaEventDisableTiming);
        cudaEventCreateWithFlags(&eVt,   cudaEventDisableTiming);
    }
    if (!smem_set) {
        cudaFuncSetAttribute(tc_ghf<true,false,0>,  cudaFuncAttributeMaxDynamicSharedMemorySize, SM1);
        cudaFuncSetAttribute(tc_ghf<false,false,0>, cudaFuncAttributeMaxDynamicSharedMemorySize, SM1);
        cudaFuncSetAttribute(tc_ghf<true,true,0>,   cudaFuncAttributeMaxDynamicSharedMemorySize, SM1);
        cudaFuncSetAttribute(tc_ghf<true,false,1>,  cudaFuncAttributeMaxDynamicSharedMemorySize, SM1);
        smem_set = true;
    }

    const dim3 blk(256);
    const size_t WQ = (size_t)D3c*Dc, WP = (size_t)Dc*Dc, W1 = (size_t)FFc*Dc, W2 = (size_t)Dc*FFc;

    // ---- fork: all weight conversions on s2, overlapped with embed ----
    cudaEventRecord(eFork, 0);
    cudaStreamWaitEvent(s2, eFork, 0);
    for (int i = 0; i < NLc; i++) {
        conv_on(s2, wqkv + (size_t)i*WQ, wq  + (size_t)i*WQ, WQ);
        conv_on(s2, wprj + (size_t)i*WP, wp  + (size_t)i*WP, WP);
        conv_on(s2, w1   + (size_t)i*W1, w1p + (size_t)i*W1, W1);
        conv_on(s2, w2   + (size_t)i*W2, w2p + (size_t)i*W2, W2);
    }
    cudaEventRecord(eConv, s2);

    // ---- main stream: inputs for embed ----
    conv_on(0, x,   xp, (size_t)Mc * D3c);
    conv_on(0, w3d, w3, (size_t)Dc * D3c);

    // embed: h = x @ w3d^T + b3d -> fp16
    tc_ghf<true,false,0><<<dim3(Dc/256, Mc/128, 1), blk, SM1>>>(
        xp, D3c, w3, D3c, b3d, nullptr,
        h, Dc, D3c, 1.0f, 0,0,0,0,0,0, 1);

    cudaStreamWaitEvent(0, eConv, 0);   // weights ready

    for (int i = 0; i < NLc; i++) {
        const __half* wqi = wq  + (size_t)i*WQ;
        const __half* wpi = wp  + (size_t)i*WP;
        const __half* w1i = w1p + (size_t)i*W1;
        const __half* w2i = w2p + (size_t)i*W2;

        layernorm_kernel<1><<<Mc, blk>>>(h, ln1g + (size_t)i*Dc, ln1b + (size_t)i*Dc,
                                         nullptr, hn);

        // qkv = hn @ wqkv^T + bqkv -> fp16
        tc_ghf<true,false,0><<<dim3(D3c/256, Mc/128, 1), blk, SM1>>>(
            hn, Dc, wqi, Dc, bqkv + (size_t)i*D3c, nullptr,
            qv, D3c, Dc, 1.0f, 0,0,0,0,0,0, 1);

        // transpose V on s2, overlapped with QK + softmax
        cudaEventRecord(eQkv, 0);
        cudaStreamWaitEvent(s2, eQkv, 0);
        transpose_v<<<dim3(Lc/32, HDc/32, Bc*Hc), blk, 0, s2>>>(qv, vt);
        cudaEventRecord(eVt, s2);

        // logits = scale * Q @ K^T -> fp16 (into g_p)
        tc_ghf<false,false,0><<<dim3(Lc/256, Lc/128, Bc*Hc), blk, SM1>>>(
            qv, D3c,
            qv + Dc, D3c,
            nullptr, nullptr,
            pp, Lc, HDc, 0.0625f,
            (long)Lc*D3c, (long)HDc,
            (long)Lc*D3c, (long)HDc,
            (long)Hc*Lc*Lc, (long)Lc*Lc,
            Hc);

        softmax_kernel<<<Bc*Hc*Lc, blk>>>(pp);   // in place

        cudaStreamWaitEvent(0, eVt, 0);           // Vt ready

        // o = P @ Vt^T -> fp16
        tc_ghf<false,false,0><<<dim3(HDc/256, Lc/128, Bc*Hc), blk, SM1>>>(
            pp, Lc,
            vt, Lc,
            nullptr, nullptr,
            op, Dc, Lc, 1.0f,
            (long)Hc*Lc*Lc, (long)Lc*Lc,
            (long)Hc*HDc*Lc, (long)HDc*Lc,
            (long)Lc*Dc, (long)HDc,
            Hc);

        // h = h + o @ wproj^T + bproj (in place on fp16 h)
        tc_ghf<true,true,0><<<dim3(Dc/256, Mc/128, 1), blk, SM1>>>(
            op, Dc, wpi, Dc, bprj + (size_t)i*Dc, h,
            h, Dc, Dc, 1.0f, 0,0,0,0,0,0, 1);

        layernorm_kernel<1><<<Mc, blk>>>(h, ln2g + (size_t)i*Dc, ln2b + (size_t)i*Dc,
                                         nullptr, hn);

        // f = gelu(hn @ w1^T + b1) -> fp16
        tc_ghf<true,false,1><<<dim3(FFc/256, Mc/128, 1), blk, SM1>>>(
            hn, Dc, w1i, Dc, b1 + (size_t)i*FFc, nullptr,
            fp, FFc, Dc, 1.0f, 0,0,0,0,0,0, 1);

        // h = h + f @ w2^T + b2 (in place on fp16 h)
        tc_ghf<true,true,0><<<dim3(Dc/256, Mc/128, 1), blk, SM1>>>(
            fp, FFc, w2i, FFc, b2 + (size_t)i*Dc, h,
            h, Dc, FFc, 1.0f, 0,0,0,0,0,0, 1);
    }

    layernorm_kernel<0><<<Mc, blk>>>(h, lnfg, lnfb, out, nullptr);
}